// round 9
// baseline (speedup 1.0000x reference)
#include <cuda_runtime.h>
#include <cuda_fp16.h>
#include <math.h>

#define T_  2048
#define B_  2
#define E_  512
#define H_  8
#define D_  64
#define E3_ 1536

// scale * log2(e): softmax in base-2 domain
#define SCL 0.1803368801111204f

// ---- scratch (__device__ globals: allocation-guard-legal) ----
__device__ __half g_q[B_*H_*T_*D_];           // [B,H,T,D] fp16
__device__ __half g_k[B_*H_*T_*D_];           // [B,H,T,D] fp16, d uint-pair-permuted
__device__ __half g_v[B_*H_*D_*T_];           // [B,H,D,T] fp16 (transposed for PV)
__device__ __half g_r[H_*T_*D_];              // [H,R,D]   fp16
__device__ __half g_BDs[(size_t)B_*H_*T_*T_]; // BD, PRE-SHIFTED + scaled, fp16
__device__ __half g_ctx[T_*B_*E_];            // [T,B,E]   fp16
// fp16 copies of harness inputs (raw cp.async GEMM operands)
__device__ __half g_ci[T_*B_*E_];
__device__ __half g_cpos[T_*E_];
__device__ __half g_cwin[E3_*E_];
__device__ __half g_cwout[E_*E_];
__device__ __half g_cwpos[E_*E_];

__device__ __forceinline__ float ex2f(float x) {
    float y;
    asm("ex2.approx.ftz.f32 %0, %1;" : "=f"(y) : "f"(x));
    return y;
}
__device__ __forceinline__ void cpa16(void* d, const void* s) {
    unsigned a = (unsigned)__cvta_generic_to_shared(d);
    asm volatile("cp.async.cg.shared.global [%0], [%1], 16;" :: "r"(a), "l"(s));
}

// fp16 mma, fp32 accum
#define MMA16(d, a, b) \
  asm volatile("mma.sync.aligned.m16n8k16.row.col.f32.f16.f16.f32 " \
      "{%0,%1,%2,%3},{%4,%5,%6,%7},{%8,%9},{%0,%1,%2,%3};" \
      : "+f"((d)[0]), "+f"((d)[1]), "+f"((d)[2]), "+f"((d)[3]) \
      : "r"((a)[0]), "r"((a)[1]), "r"((a)[2]), "r"((a)[3]), \
        "r"((b)[0]), "r"((b)[1]))

// ============================================================
// One-shot fp32 -> fp16 conversion of all inputs (merged)
// ============================================================
#define N4_CI   (T_*B_*E_/4)
#define N4_CPOS (T_*E_/4)
#define N4_CWIN (E3_*E_/4)
#define N4_CW   (E_*E_/4)
#define N4_TOT  (N4_CI + N4_CPOS + N4_CWIN + 2*N4_CW)

__global__ __launch_bounds__(256) void k_cvt_all(const float* __restrict__ s0,
                                                 const float* __restrict__ s1,
                                                 const float* __restrict__ s2,
                                                 const float* __restrict__ s3,
                                                 const float* __restrict__ s4) {
    int i = blockIdx.x * 256 + threadIdx.x;
    if (i >= N4_TOT) return;
    const float* src; __half* dst; int off = i;
    if (i < N4_CI)                               { src = s0; dst = g_ci; }
    else if ((off -= N4_CI)   < N4_CPOS)         { src = s1; dst = g_cpos; }
    else if ((off -= N4_CPOS) < N4_CWIN)         { src = s2; dst = g_cwin; }
    else if ((off -= N4_CWIN) < N4_CW)           { src = s3; dst = g_cwout; }
    else { off -= N4_CW;                           src = s4; dst = g_cwpos; }
    float4 v = ((const float4*)src)[off];
    __half2 h0 = __floats2half2_rn(v.x, v.y);
    __half2 h1 = __floats2half2_rn(v.z, v.w);
    uint2 u = { *(unsigned*)&h0, *(unsigned*)&h1 };
    ((uint2*)dst)[off] = u;
}

// ============================================================
// fp16 double-buffered cp.async NT mainloop: C[128,128] = A·Bt^T.
// ============================================================
template<int KTOT>
__device__ __forceinline__ void gemm_nt_hp(const __half* __restrict__ A, int lda,
                                           const __half* __restrict__ Bt, int ldb,
                                           int m0, int n0, float acc[4][4][4],
                                           unsigned* sm) {
    const int tid = threadIdx.x;
    const int lane = tid & 31, warp = tid >> 5;
    const int wm = (warp >> 2) * 64, wn = (warp & 3) * 32;

#define HSTAGE(buf_, k0_) do {                                                \
    unsigned* As_ = sm + (buf_) * 5120;                                       \
    unsigned* Bs_ = As_ + 2560;                                               \
    _Pragma("unroll")                                                         \
    for (int i_ = 0; i_ < 2; i_++) {                                          \
        int idx_ = tid + i_ * 256;                                            \
        int row_ = idx_ >> 2, c8_ = (idx_ & 3) * 8;                           \
        cpa16(As_ + row_*20 + (idx_ & 3)*4, A  + (size_t)(m0 + row_) * lda + (k0_) + c8_); \
        cpa16(Bs_ + row_*20 + (idx_ & 3)*4, Bt + (size_t)(n0 + row_) * ldb + (k0_) + c8_); \
    }                                                                         \
    asm volatile("cp.async.commit_group;" ::: "memory");                      \
} while (0)

    HSTAGE(0, 0);
    #pragma unroll 1
    for (int k0 = 0; k0 < KTOT; k0 += 32) {
        const int buf = (k0 >> 5) & 1;
        const bool more = (k0 + 32 < KTOT);
        if (more) HSTAGE(buf ^ 1, k0 + 32);
        if (more) asm volatile("cp.async.wait_group 1;" ::: "memory");
        else      asm volatile("cp.async.wait_group 0;" ::: "memory");
        __syncthreads();

        const unsigned* As = sm + buf * 5120;
        const unsigned* Bs = As + 2560;
        #pragma unroll
        for (int ks = 0; ks < 2; ks++) {
            const int r = lane >> 2, c = ks * 8 + (lane & 3);
            unsigned af[4][4], bf[4][2];
            #pragma unroll
            for (int mi = 0; mi < 4; mi++) {
                int rr = wm + mi * 16 + r;
                af[mi][0] = As[rr*20 + c];     af[mi][1] = As[(rr+8)*20 + c];
                af[mi][2] = As[rr*20 + c + 4]; af[mi][3] = As[(rr+8)*20 + c + 4];
            }
            #pragma unroll
            for (int ni = 0; ni < 4; ni++) {
                int rb = wn + ni * 8 + r;
                bf[ni][0] = Bs[rb*20 + c]; bf[ni][1] = Bs[rb*20 + c + 4];
            }
            #pragma unroll
            for (int mi = 0; mi < 4; mi++)
                #pragma unroll
                for (int ni = 0; ni < 4; ni++)
                    MMA16(acc[mi][ni], af[mi], bf[ni]);
        }
        __syncthreads();
    }
#undef HSTAGE
}

#define EPI_ROW(m0, wm, mi, rg) ((m0) + (wm) + (mi)*16 + (lane >> 2) + (((rg) & 2) << 2))
#define EPI_COL(n0, wn, ni, rg) ((n0) + (wn) + (ni)*8 + ((lane & 3) << 1) + ((rg) & 1))

// ============================================================
// MERGED projections: blocks [0,384) = QKV, [384,448) = pos.
// qkv -> q/k [B,H,T,D], v [B,H,D,T]; pos -> g_r[H,R,D]
// ============================================================
__global__ __launch_bounds__(256) void k_proj(const float* __restrict__ bias_in,
                                              const float* __restrict__ bias_pos) {
    extern __shared__ unsigned dsm[];
    const int bid = blockIdx.x;
    const int lane = threadIdx.x & 31, warp = threadIdx.x >> 5;
    const int wm = (warp >> 2) * 64, wn = (warp & 3) * 32;
    float acc[4][4][4] = {};

    if (bid < 384) {
        const int m0 = (bid / 12) * 128, n0 = (bid % 12) * 128;
        gemm_nt_hp<E_>(g_ci, E_, g_cwin, E_, m0, n0, acc, dsm);
        #pragma unroll
        for (int mi = 0; mi < 4; mi++)
            #pragma unroll
            for (int ni = 0; ni < 4; ni++)
                #pragma unroll
                for (int rg = 0; rg < 4; rg++) {
                    int row = EPI_ROW(m0, wm, mi, rg);
                    int col = EPI_COL(n0, wn, ni, rg);
                    float v = acc[mi][ni][rg] + bias_in[col];
                    int t = row / B_, b = row % B_;
                    int sec = col >> 9, h = (col >> 6) & 7, d = col & 63;
                    if (sec == 0) {
                        g_q[(((size_t)(b * H_ + h) * T_) + t) * D_ + d] = __float2half_rn(v);
                    } else if (sec == 1) {
                        int u = d >> 1;
                        int up = (u & 24) | ((u & 3) << 1) | ((u >> 2) & 1);
                        g_k[(((size_t)(b * H_ + h) * T_) + t) * D_ + (up << 1 | (d & 1))] =
                            __float2half_rn(v);
                    } else {
                        g_v[(((size_t)(b * H_ + h) * D_) + d) * T_ + t] = __float2half_rn(v);
                    }
                }
    } else {
        const int rem = bid - 384;
        const int m0 = (rem / 4) * 128, n0 = (rem % 4) * 128;
        gemm_nt_hp<E_>(g_cpos, E_, g_cwpos, E_, m0, n0, acc, dsm);
        #pragma unroll
        for (int mi = 0; mi < 4; mi++)
            #pragma unroll
            for (int ni = 0; ni < 4; ni++)
                #pragma unroll
                for (int rg = 0; rg < 4; rg++) {
                    int rr = EPI_ROW(m0, wm, mi, rg);
                    int col = EPI_COL(n0, wn, ni, rg);
                    int h = col >> 6, d = col & 63;
                    g_r[((size_t)h * T_ + rr) * D_ + d] =
                        __float2half_rn(acc[mi][ni][rg] + bias_pos[col]);
                }
    }
}

// ============================================================
// BD: raw[t,c] = q[t]·r[c] + br[c], written PRE-SHIFTED + scaled fp16.
// br[c] = rrb_h·r[h,c] computed in-block (smem) — no separate kernel.
// ============================================================
__global__ __launch_bounds__(256) void k_bd(const float* __restrict__ rrb) {
    extern __shared__ unsigned dsm[];
    const int bh = blockIdx.z, h = bh & 7;
    float acc[4][4][4] = {};
    const int m0 = blockIdx.y * 128, n0 = blockIdx.x * 128;
    gemm_nt_hp<D_>(g_q + (size_t)bh * T_ * D_, D_,
                   g_r + (size_t)h  * T_ * D_, D_, m0, n0, acc, dsm);

    const int tid = threadIdx.x, lane = tid & 31, warp = tid >> 5;
    const int wm = (warp >> 2) * 64, wn = (warp & 3) * 32;
    __half* Hs = (__half*)dsm;                  // [128][136] halfs (34816 B)
    float* brs = (float*)(dsm + 8704);          // 128 floats after Hs

    // cooperative br slice: brs[i] = rrb_h · r[h, n0+i]
    if (tid < 128) {
        const __half2* rr = (const __half2*)(g_r + ((size_t)h * T_ + n0 + tid) * D_);
        const float* bb = rrb + h * D_;
        float s = 0.f;
        #pragma unroll
        for (int i = 0; i < 32; i++) {
            float2 a = __half22float2(rr[i]);
            s += a.x * bb[2*i] + a.y * bb[2*i + 1];
        }
        brs[tid] = s;
    }
    __syncthreads();

    #pragma unroll
    for (int mi = 0; mi < 4; mi++)
        #pragma unroll
        for (int ni = 0; ni < 4; ni++)
            #pragma unroll
            for (int rg = 0; rg < 4; rg++) {
                int lt = wm + mi*16 + (lane >> 2) + (((rg) & 2) << 2);
                int lc = wn + ni*8 + ((lane & 3) << 1) + ((rg) & 1);
                float v = (acc[mi][ni][rg] + brs[lc]) * SCL;
                Hs[lt * 136 + lc] = __float2half_rn(v);
            }
    __syncthreads();

    __half* out = g_BDs + (size_t)bh * T_ * T_;
    for (int i = 0; i < 16; i++) {
        int lt = warp * 16 + i;
        int t = m0 + lt;
        int cut = (T_ - 1) - t - n0;
        cut = min(max(cut, 0), 128);
        const __half* src = Hs + lt * 136;

        // segment A: cl in [cut,128) -> row t
        {
            int len = 128 - cut;
            if (len > 0) {
                size_t dst = (size_t)t * T_ + (n0 + cut + t - (T_ - 1));
                int so = cut;
                int k0 = (int)(dst & 1);
                if (k0 && lane == 0) out[dst] = src[so];
                for (int k = k0 + 2 * lane; k + 1 < len; k += 64) {
                    __half2 v = { src[so + k], src[so + k + 1] };
                    *(__half2*)(out + dst + k) = v;
                }
                if (((len - k0) & 1) && lane == 0) out[dst + len - 1] = src[so + len - 1];
            }
        }
        // segment B: cl in [0,cut) -> row t-1
        if (t >= 1 && cut > 0) {
            int len = cut;
            size_t dst = (size_t)(t - 1) * T_ + (n0 + t + 1);
            int k0 = (int)(dst & 1);
            if (k0 && lane == 0) out[dst] = src[0];
            for (int k = k0 + 2 * lane; k + 1 < len; k += 64) {
                __half2 v = { src[k], src[k + 1] };
                *(__half2*)(out + dst + k) = v;
            }
            if (((len - k0) & 1) && lane == 0) out[dst + len - 1] = src[len - 1];
        }
    }
}

// ============================================================
// Flash attention: t-tile 128, s-tile 64, 2 CTAs/SM, all-fp16 MMA,
// P in registers, 3-STAGE KV pipeline.
// Commit order: KV(it), BD(it), KV(it+1) -> top wait_group 2 (KV),
// post-AC wait_group 1 (BD).
// ============================================================
__global__ __launch_bounds__(256, 2) void k_flash(const float* __restrict__ rwb) {
    extern __shared__ unsigned smem[];
    const int KW = 64 * 40;                 // K tile words (fp16, pitch 40)
    const int VW = 64 * 36;                 // V tile words (fp16 transposed, pitch 36)
    const int BUFW = KW + VW;               // 4864 words per stage
    unsigned* Ps = smem + 3 * BUFW;         // BD: [128][36] words

    const int bh = blockIdx.y, h = bh & 7, b = bh >> 3;
    const int t0 = blockIdx.x * 128;
    const __half* Q  = g_q + (size_t)bh * T_ * D_;
    const __half* K  = g_k + (size_t)bh * T_ * D_;
    const __half* V  = g_v + (size_t)bh * D_ * T_;   // [d][t]
    const __half* BD = g_BDs + (size_t)bh * T_ * T_;

    const int tid = threadIdx.x, lane = tid & 31, warp = tid >> 5;
    const int r = lane >> 2, cc = lane & 3;
    const int row0 = warp * 16;
    const int trow0 = t0 + row0 + r, trow1 = trow0 + 8;

#define PREFETCH_KV(buf, s0_) do {                                            \
    unsigned* Kb_ = smem + (buf) * BUFW;                                      \
    unsigned* Vb_ = Kb_ + KW;                                                 \
    _Pragma("unroll")                                                         \
    for (int i_ = 0; i_ < 2; i_++) {      /* K: 64 s-rows x 8 chunks */       \
        int idx_ = tid + i_ * 256;                                            \
        int row_ = idx_ >> 3, ch_ = idx_ & 7;                                 \
        cpa16(Kb_ + row_*40 + ch_*4, K + (size_t)((s0_) + row_) * D_ + ch_*8);\
    }                                                                         \
    _Pragma("unroll")                                                         \
    for (int i_ = 0; i_ < 2; i_++) {      /* V: 64 d-rows x 8 chunks */       \
        int idx_ = tid + i_ * 256;                                            \
        int row_ = idx_ >> 3, ch_ = idx_ & 7;                                 \
        cpa16(Vb_ + row_*36 + ch_*4, V + (size_t)row_ * T_ + (s0_) + ch_*8);  \
    }                                                                         \
    asm volatile("cp.async.commit_group;" ::: "memory");                      \
} while (0)

#define PREFETCH_BD(s0_) do {                                                 \
    _Pragma("unroll")                                                         \
    for (int i_ = 0; i_ < 4; i_++) {                                          \
        int idx_ = lane + i_ * 32;                                            \
        int row_ = idx_ >> 3, c16_ = idx_ & 7;                                \
        cpa16(Ps + (row0 + row_) * 36 + c16_ * 4,                             \
              BD + (size_t)(t0 + row0 + row_) * T_ + (s0_) + c16_ * 8);       \
    }                                                                         \
    asm volatile("cp.async.commit_group;" ::: "memory");                      \
} while (0)

    // q fragments (fp16 m16n8k16 A layout), prescaled + rwb
    unsigned aq[4][4];
    const float* rwbh = rwb + h * D_;
    #pragma unroll
    for (int kc = 0; kc < 4; kc++) {
        int c0 = kc * 16 + 2 * cc;
        #pragma unroll
        for (int half8 = 0; half8 < 2; half8++) {
            int c = c0 + half8 * 8;
            float2 q0 = __half22float2(*(const __half2*)(Q + (size_t)trow0 * D_ + c));
            float2 q1 = __half22float2(*(const __half2*)(Q + (size_t)trow1 * D_ + c));
            __half2 a0 = __floats2half2_rn((q0.x + rwbh[c]) * SCL, (q0.y + rwbh[c+1]) * SCL);
            __half2 a1 = __floats2half2_rn((q1.x + rwbh[c]) * SCL, (q1.y + rwbh[c+1]) * SCL);
            aq[kc][half8 * 2]     = *(unsigned*)&a0;
            aq[kc][half8 * 2 + 1] = *(unsigned*)&a1;
        }
    }

    // pre-loop: commit order KV(0), BD(0), KV(1)
    PREFETCH_KV(0, 0);
    PREFETCH_BD(0);
    PREFETCH_KV(1, 64);

    float oacc[8][4] = {};
    float m0r = -1e30f, m1r = -1e30f, l0 = 0.f, l1 = 0.f;

    #pragma unroll 1
    for (int it = 0; it < T_ / 64; it++) {
        const int s0 = it * 64;
        const int cur = it % 3;
        // outstanding: KV(it), BD(it), KV(it+1) -> release KV(it)
        asm volatile("cp.async.wait_group 2;" ::: "memory");
        __syncthreads();

        const unsigned* Kb = smem + cur * BUFW;
        const unsigned* Vb = Kb + KW;

        // ---- AC = qw · K^T (fp16) ----
        float pacc[8][4];
        #pragma unroll
        for (int nt = 0; nt < 8; nt++)
            #pragma unroll
            for (int j = 0; j < 4; j++) pacc[nt][j] = 0.f;
        #pragma unroll
        for (int kc = 0; kc < 4; kc++) {
            #pragma unroll
            for (int nt = 0; nt < 8; nt++) {
                int srow = nt * 8 + r;
                uint2 kb2 = *(const uint2*)(Kb + srow * 40 + kc * 8 + 2 * cc);
                unsigned bf[2] = { kb2.x, kb2.y };
                MMA16(pacc[nt], aq[kc], bf);
            }
        }

        // release BD(it) (leaves KV(it+1) pending)
        asm volatile("cp.async.wait_group 1;" ::: "memory");
        __syncwarp();

        // ---- add BD (mask s==t+1), row max ----
        const __half2* bd0 = (const __half2*)(Ps + (row0 + r) * 36);
        const __half2* bd1 = (const __half2*)(Ps + (row0 + r + 8) * 36);
        float pm0 = -1e30f, pm1 = -1e30f;
        #pragma unroll
        for (int nt = 0; nt < 8; nt++) {
            int sb = s0 + nt * 8 + 2 * cc;
            float2 f0 = __half22float2(bd0[4 * nt + cc]);
            float2 f1 = __half22float2(bd1[4 * nt + cc]);
            pacc[nt][0] += (sb     == trow0 + 1) ? 0.f : f0.x;
            pacc[nt][1] += (sb + 1 == trow0 + 1) ? 0.f : f0.y;
            pacc[nt][2] += (sb     == trow1 + 1) ? 0.f : f1.x;
            pacc[nt][3] += (sb + 1 == trow1 + 1) ? 0.f : f1.y;
            pm0 = fmaxf(pm0, fmaxf(pacc[nt][0], pacc[nt][1]));
            pm1 = fmaxf(pm1, fmaxf(pacc[nt][2], pacc[nt][3]));
        }
        pm0 = fmaxf(pm0, __shfl_xor_sync(0xffffffffu, pm0, 1));
        pm0 = fmaxf(pm0, __shfl_xor_sync(0xffffffffu, pm0, 2));
        pm1 = fmaxf(pm1, __shfl_xor_sync(0xffffffffu, pm1, 1));
        pm1 = fmaxf(pm1, __shfl_xor_sync(0xffffffffu, pm1, 2));

        float mn0 = fmaxf(m0r, pm0), mn1 = fmaxf(m1r, pm1);
        float sf0 = ex2f(m0r - mn0), sf1 = ex2f(m1r - mn1);
        m0r = mn0; m1r = mn1;
        #pragma unroll
        for (int nt = 0; nt < 8; nt++) {
            oacc[nt][0] *= sf0; oacc[nt][1] *= sf0;
            oacc[nt][2] *= sf1; oacc[nt][3] *= sf1;
        }
        l0 *= sf0; l1 *= sf1;

        // ---- exp, rowsum, pack P to fp16 IN REGISTERS ----
        unsigned ph[8][2];
        float sum0 = 0.f, sum1 = 0.f;
        #pragma unroll
        for (int nt = 0; nt < 8; nt++) {
            float e0 = ex2f(pacc[nt][0] - mn0);
            float e1 = ex2f(pacc[nt][1] - mn0);
            float e2 = ex2f(pacc[nt][2] - mn1);
            float e3 = ex2f(pacc[nt][3] - mn1);
            sum0 += e0 + e1; sum1 += e2 + e3;
            __half2 p0 = __floats2half2_rn(e0, e1);
            __half2 p1 = __floats2half2_rn(e2, e3);
            ph[nt][0] = *(unsigned*)&p0;
            ph[nt][1] = *(unsigned*)&p1;
        }
        sum0 += __shfl_xor_sync(0xffffffffu, sum0, 1);
        sum0 += __shfl_xor_sync(0xffffffffu, sum0, 2);
        sum1 += __shfl_xor_sync(0xffffffffu, sum1, 1);
        sum1 += __shfl_xor_sync(0xffffffffu, sum1, 2);
        l0 += sum0; l1 += sum1;

        // ---- O += P · V (fp16; A-frag from registers) ----
        #pragma unroll
        for (int kc = 0; kc < 4; kc++) {
            unsigned af[4] = { ph[2*kc][0], ph[2*kc][1], ph[2*kc+1][0], ph[2*kc+1][1] };
            #pragma unroll
            for (int nt = 0; nt < 8; nt++) {
                int drow = nt * 8 + r;
                unsigned bf[2];
                bf[0] = Vb[drow * 36 + kc * 8 + cc];
                bf[1] = Vb[drow * 36 + kc * 8 + cc + 4];
                MMA16(oacc[nt], af, bf);
            }
        }
        __syncwarp();

        // commit BD(it+1) then KV(it+2)  (keeps group order stable)
        if (it < T_ / 64 - 1)
            PREFETCH_BD(s0 + 64);
        PREFETCH_KV((it + 2) % 3, (s0 + 128) & (T_ - 1));
    }
    asm volatile("cp.async.wait_group 0;" ::: "memory");

    // ---- epilogue: O /= l -> g_ctx (fp16) ----
    float il0 = 1.f / l0, il1 = 1.f / l1;
    #pragma unroll
    for (int nt = 0; nt < 8; nt++) {
        int d = h * 64 + nt * 8 + 2 * cc;
        __half2 o0 = __floats2half2_rn(oacc[nt][0] * il0, oacc[nt][1] * il0);
        *(__half2*)(g_ctx + ((size_t)trow0 * B_ + b) * E_ + d) = o0;
        __half2 o1 = __floats2half2_rn(oacc[nt][2] * il1, oacc[nt][3] * il1);
        *(__half2*)(g_ctx + ((size_t)trow1 * B_ + b) * E_ + d) = o1;
    }
#undef PREFETCH_KV
#undef PREFETCH_BD
}

// ============================================================
// out projection (fp16 GEMM, fp32 output)
// ============================================================
__global__ __launch_bounds__(256) void k_out(const float* __restrict__ bias,
                                             float* __restrict__ out) {
    extern __shared__ unsigned dsm[];
    float acc[4][4][4] = {};
    const int m0 = blockIdx.y * 128, n0 = blockIdx.x * 128;
    gemm_nt_hp<E_>(g_ctx, E_, g_cwout, E_, m0, n0, acc, dsm);
    const int lane = threadIdx.x & 31, warp = threadIdx.x >> 5;
    const int wm = (warp >> 2) * 64, wn = (warp & 3) * 32;
    #pragma unroll
    for (int mi = 0; mi < 4; mi++)
        #pragma unroll
        for (int ni = 0; ni < 4; ni++)
            #pragma unroll
            for (int rg = 0; rg < 4; rg++) {
                int row = EPI_ROW(m0, wm, mi, rg);
                int col = EPI_COL(n0, wn, ni, rg);
                out[(size_t)row * E_ + col] = acc[mi][ni][rg] + bias[col];
            }
}

// ============================================================
extern "C" void kernel_launch(void* const* d_in, const int* in_sizes, int n_in,
                              void* d_out, int out_size) {
    const float* input = (const float*)d_in[0];
    const float* pos   = (const float*)d_in[1];
    const float* w_in  = (const float*)d_in[2];
    const float* w_out = (const float*)d_in[3];
    const float* w_pos = (const float*)d_in[4];
    const float* b_in  = (const float*)d_in[5];
    const float* b_out = (const float*)d_in[6];
    const float* b_pos = (const float*)d_in[7];
    const float* rwb   = (const float*)d_in[8];
    const float* rrb   = (const float*)d_in[9];
    float* out = (float*)d_out;

    const int gemm_smem  = 2 * 2 * 128 * 20 * 4;                 // 40960
    const int flash_smem = (3 * (64*40 + 64*36) + 128*36) * 4;   // 76800
    cudaFuncSetAttribute(k_proj, cudaFuncAttributeMaxDynamicSharedMemorySize, gemm_smem);
    cudaFuncSetAttribute(k_bd,   cudaFuncAttributeMaxDynamicSharedMemorySize, gemm_smem);
    cudaFuncSetAttribute(k_out,  cudaFuncAttributeMaxDynamicSharedMemorySize, gemm_smem);
    cudaFuncSetAttribute(k_flash, cudaFuncAttributeMaxDynamicSharedMemorySize, flash_smem);

    k_cvt_all<<<(N4_TOT + 255)/256, 256>>>(input, pos, w_in, w_out, w_pos);
    k_proj <<<448, 256, gemm_smem>>>(b_in, b_pos);
    k_bd   <<<dim3(T_/128, T_/128, B_*H_), 256, gemm_smem>>>(rrb);
    k_flash<<<dim3(T_/128, B_*H_), 256, flash_smem>>>(rwb);
    k_out  <<<dim3(E_/128, (T_*B_)/128), 256, gemm_smem>>>(b_out, out);
}

// round 10
// speedup vs baseline: 1.2344x; 1.2344x over previous
#include <cuda_runtime.h>
#include <cuda_fp16.h>
#include <math.h>

#define T_  2048
#define B_  2
#define E_  512
#define H_  8
#define D_  64
#define E3_ 1536

// scale * log2(e): softmax in base-2 domain
#define SCL 0.1803368801111204f

// ---- scratch (__device__ globals: allocation-guard-legal) ----
__device__ __half g_q[B_*H_*T_*D_];           // [B,H,T,D] fp16
__device__ __half g_k[B_*H_*T_*D_];           // [B,H,T,D] fp16, d uint-pair-permuted
__device__ __half g_v[B_*H_*D_*T_];           // [B,H,D,T] fp16, t uint-pair-permuted
__device__ __half g_r[H_*T_*D_];              // [H,R,D]   fp16
__device__ float  g_br[H_*T_];                // rrb_h · r[h,c]
__device__ __half g_BDs[(size_t)B_*H_*T_*T_]; // BD, PRE-SHIFTED + scaled, fp16
__device__ __half g_ctx[T_*B_*E_];            // [T,B,E]   fp16
// fp16 copies of harness inputs (raw cp.async GEMM operands)
__device__ __half g_ci[T_*B_*E_];
__device__ __half g_cpos[T_*E_];
__device__ __half g_cwin[E3_*E_];
__device__ __half g_cwout[E_*E_];
__device__ __half g_cwpos[E_*E_];

__device__ __forceinline__ float ex2f(float x) {
    float y;
    asm("ex2.approx.ftz.f32 %0, %1;" : "=f"(y) : "f"(x));
    return y;
}
__device__ __forceinline__ void cpa16(void* d, const void* s) {
    unsigned a = (unsigned)__cvta_generic_to_shared(d);
    asm volatile("cp.async.cg.shared.global [%0], [%1], 16;" :: "r"(a), "l"(s));
}

// fp16 mma, fp32 accum
#define MMA16(d, a, b) \
  asm volatile("mma.sync.aligned.m16n8k16.row.col.f32.f16.f16.f32 " \
      "{%0,%1,%2,%3},{%4,%5,%6,%7},{%8,%9},{%0,%1,%2,%3};" \
      : "+f"((d)[0]), "+f"((d)[1]), "+f"((d)[2]), "+f"((d)[3]) \
      : "r"((a)[0]), "r"((a)[1]), "r"((a)[2]), "r"((a)[3]), \
        "r"((b)[0]), "r"((b)[1]))

// ============================================================
// One-shot fp32 -> fp16 conversion of all inputs (merged)
// ============================================================
#define N4_CI   (T_*B_*E_/4)
#define N4_CPOS (T_*E_/4)
#define N4_CWIN (E3_*E_/4)
#define N4_CW   (E_*E_/4)
#define N4_TOT  (N4_CI + N4_CPOS + N4_CWIN + 2*N4_CW)

__global__ __launch_bounds__(256) void k_cvt_all(const float* __restrict__ s0,
                                                 const float* __restrict__ s1,
                                                 const float* __restrict__ s2,
                                                 const float* __restrict__ s3,
                                                 const float* __restrict__ s4) {
    int i = blockIdx.x * 256 + threadIdx.x;
    if (i >= N4_TOT) return;
    const float* src; __half* dst; int off = i;
    if (i < N4_CI)                               { src = s0; dst = g_ci; }
    else if ((off -= N4_CI)   < N4_CPOS)         { src = s1; dst = g_cpos; }
    else if ((off -= N4_CPOS) < N4_CWIN)         { src = s2; dst = g_cwin; }
    else if ((off -= N4_CWIN) < N4_CW)           { src = s3; dst = g_cwout; }
    else { off -= N4_CW;                           src = s4; dst = g_cwpos; }
    float4 v = ((const float4*)src)[off];
    __half2 h0 = __floats2half2_rn(v.x, v.y);
    __half2 h1 = __floats2half2_rn(v.z, v.w);
    uint2 u = { *(unsigned*)&h0, *(unsigned*)&h1 };
    ((uint2*)dst)[off] = u;
}

// ============================================================
// fp16 double-buffered cp.async NT mainloop: C[128,128] = A·Bt^T.
// ============================================================
template<int KTOT>
__device__ __forceinline__ void gemm_nt_hp(const __half* __restrict__ A, int lda,
                                           const __half* __restrict__ Bt, int ldb,
                                           int m0, int n0, float acc[4][4][4],
                                           unsigned* sm) {
    const int tid = threadIdx.x;
    const int lane = tid & 31, warp = tid >> 5;
    const int wm = (warp >> 2) * 64, wn = (warp & 3) * 32;

#define HSTAGE(buf_, k0_) do {                                                \
    unsigned* As_ = sm + (buf_) * 5120;                                       \
    unsigned* Bs_ = As_ + 2560;                                               \
    _Pragma("unroll")                                                         \
    for (int i_ = 0; i_ < 2; i_++) {                                          \
        int idx_ = tid + i_ * 256;                                            \
        int row_ = idx_ >> 2, c8_ = (idx_ & 3) * 8;                           \
        cpa16(As_ + row_*20 + (idx_ & 3)*4, A  + (size_t)(m0 + row_) * lda + (k0_) + c8_); \
        cpa16(Bs_ + row_*20 + (idx_ & 3)*4, Bt + (size_t)(n0 + row_) * ldb + (k0_) + c8_); \
    }                                                                         \
    asm volatile("cp.async.commit_group;" ::: "memory");                      \
} while (0)

    HSTAGE(0, 0);
    #pragma unroll 1
    for (int k0 = 0; k0 < KTOT; k0 += 32) {
        const int buf = (k0 >> 5) & 1;
        const bool more = (k0 + 32 < KTOT);
        if (more) HSTAGE(buf ^ 1, k0 + 32);
        if (more) asm volatile("cp.async.wait_group 1;" ::: "memory");
        else      asm volatile("cp.async.wait_group 0;" ::: "memory");
        __syncthreads();

        const unsigned* As = sm + buf * 5120;
        const unsigned* Bs = As + 2560;
        #pragma unroll
        for (int ks = 0; ks < 2; ks++) {
            const int r = lane >> 2, c = ks * 8 + (lane & 3);
            unsigned af[4][4], bf[4][2];
            #pragma unroll
            for (int mi = 0; mi < 4; mi++) {
                int rr = wm + mi * 16 + r;
                af[mi][0] = As[rr*20 + c];     af[mi][1] = As[(rr+8)*20 + c];
                af[mi][2] = As[rr*20 + c + 4]; af[mi][3] = As[(rr+8)*20 + c + 4];
            }
            #pragma unroll
            for (int ni = 0; ni < 4; ni++) {
                int rb = wn + ni * 8 + r;
                bf[ni][0] = Bs[rb*20 + c]; bf[ni][1] = Bs[rb*20 + c + 4];
            }
            #pragma unroll
            for (int mi = 0; mi < 4; mi++)
                #pragma unroll
                for (int ni = 0; ni < 4; ni++)
                    MMA16(acc[mi][ni], af[mi], bf[ni]);
        }
        __syncthreads();
    }
#undef HSTAGE
}

#define EPI_ROW(m0, wm, mi, rg) ((m0) + (wm) + (mi)*16 + (lane >> 2) + (((rg) & 2) << 2))
#define EPI_COL(n0, wn, ni, rg) ((n0) + (wn) + (ni)*8 + ((lane & 3) << 1) + ((rg) & 1))

// ============================================================
// QKV projection -> q/k [B,H,T,D], v [B,H,D,T'] (all fp16)
// K: d uint-pair-permuted.  V: t uint-pair-permuted (PV LDS.64).
// ============================================================
__global__ __launch_bounds__(256) void k_qkv(const float* __restrict__ bias) {
    extern __shared__ unsigned dsm[];
    float acc[4][4][4] = {};
    const int m0 = blockIdx.y * 128, n0 = blockIdx.x * 128;
    gemm_nt_hp<E_>(g_ci, E_, g_cwin, E_, m0, n0, acc, dsm);
    const int lane = threadIdx.x & 31, warp = threadIdx.x >> 5;
    const int wm = (warp >> 2) * 64, wn = (warp & 3) * 32;
    #pragma unroll
    for (int mi = 0; mi < 4; mi++)
        #pragma unroll
        for (int ni = 0; ni < 4; ni++)
            #pragma unroll
            for (int rg = 0; rg < 4; rg++) {
                int row = EPI_ROW(m0, wm, mi, rg);
                int col = EPI_COL(n0, wn, ni, rg);
                float v = acc[mi][ni][rg] + bias[col];
                int t = row / B_, b = row % B_;
                int sec = col >> 9, h = (col >> 6) & 7, d = col & 63;
                if (sec == 0) {
                    g_q[(((size_t)(b * H_ + h) * T_) + t) * D_ + d] = __float2half_rn(v);
                } else if (sec == 1) {
                    // permute d so uint-pairs (u, u+4) within each k16 chunk are adjacent
                    int u = d >> 1;
                    int up = (u & 24) | ((u & 3) << 1) | ((u >> 2) & 1);
                    g_k[(((size_t)(b * H_ + h) * T_) + t) * D_ + (up << 1 | (d & 1))] =
                        __float2half_rn(v);
                } else {
                    // V transposed [B,H,D,T]; permute t words: o -> ((o&3)<<1)|(o>>2)
                    int w = t >> 1;
                    int o = w & 7;
                    int wp = (w & ~7) | (((o & 3) << 1) | (o >> 2));
                    int tp = (wp << 1) | (t & 1);
                    g_v[(((size_t)(b * H_ + h) * D_) + d) * T_ + tp] = __float2half_rn(v);
                }
            }
}

// ============================================================
// pos projection -> g_r[H,R,D] fp16
// ============================================================
__global__ __launch_bounds__(256) void k_pos(const float* __restrict__ bias) {
    extern __shared__ unsigned dsm[];
    float acc[4][4][4] = {};
    const int m0 = blockIdx.y * 128, n0 = blockIdx.x * 128;
    gemm_nt_hp<E_>(g_cpos, E_, g_cwpos, E_, m0, n0, acc, dsm);
    const int lane = threadIdx.x & 31, warp = threadIdx.x >> 5;
    const int wm = (warp >> 2) * 64, wn = (warp & 3) * 32;
    #pragma unroll
    for (int mi = 0; mi < 4; mi++)
        #pragma unroll
        for (int ni = 0; ni < 4; ni++)
            #pragma unroll
            for (int rg = 0; rg < 4; rg++) {
                int rr = EPI_ROW(m0, wm, mi, rg);
                int col = EPI_COL(n0, wn, ni, rg);
                int h = col >> 6, d = col & 63;
                g_r[((size_t)h * T_ + rr) * D_ + d] =
                    __float2half_rn(acc[mi][ni][rg] + bias[col]);
            }
}

// ============================================================
// br[h][c] = rrb_h · r[h,c]
// ============================================================
__global__ __launch_bounds__(128) void k_brdot(const float* __restrict__ rrb) {
    int idx = blockIdx.x * 128 + threadIdx.x;   // h*T + c
    int h = idx >> 11;
    const __half2* rr = (const __half2*)(g_r + (size_t)idx * D_);
    const float* bb = rrb + h * D_;
    float s = 0.f;
    #pragma unroll
    for (int i = 0; i < 32; i++) {
        float2 a = __half22float2(rr[i]);
        s += a.x * bb[2*i] + a.y * bb[2*i + 1];
    }
    g_br[idx] = s;
}

// ============================================================
// BD: raw[t,c] = q[t]·r[c] + br[c], written PRE-SHIFTED + scaled fp16.
// ============================================================
__global__ __launch_bounds__(256) void k_bd() {
    extern __shared__ unsigned dsm[];
    const int bh = blockIdx.z, h = bh & 7;
    float acc[4][4][4] = {};
    const int m0 = blockIdx.y * 128, n0 = blockIdx.x * 128;
    gemm_nt_hp<D_>(g_q + (size_t)bh * T_ * D_, D_,
                   g_r + (size_t)h  * T_ * D_, D_, m0, n0, acc, dsm);

    const int tid = threadIdx.x, lane = tid & 31, warp = tid >> 5;
    const int wm = (warp >> 2) * 64, wn = (warp & 3) * 32;
    __half* Hs = (__half*)dsm;                 // [128][136] halfs
    const float* br = g_br + h * T_;
    #pragma unroll
    for (int mi = 0; mi < 4; mi++)
        #pragma unroll
        for (int ni = 0; ni < 4; ni++)
            #pragma unroll
            for (int rg = 0; rg < 4; rg++) {
                int lt = wm + mi*16 + (lane >> 2) + (((rg) & 2) << 2);
                int lc = wn + ni*8 + ((lane & 3) << 1) + ((rg) & 1);
                float v = (acc[mi][ni][rg] + br[n0 + lc]) * SCL;
                Hs[lt * 136 + lc] = __float2half_rn(v);
            }
    __syncthreads();

    __half* out = g_BDs + (size_t)bh * T_ * T_;
    for (int i = 0; i < 16; i++) {
        int lt = warp * 16 + i;
        int t = m0 + lt;
        int cut = (T_ - 1) - t - n0;
        cut = min(max(cut, 0), 128);
        const __half* src = Hs + lt * 136;

        // segment A: cl in [cut,128) -> row t
        {
            int len = 128 - cut;
            if (len > 0) {
                size_t dst = (size_t)t * T_ + (n0 + cut + t - (T_ - 1));
                int so = cut;
                int k0 = (int)(dst & 1);
                if (k0 && lane == 0) out[dst] = src[so];
                for (int k = k0 + 2 * lane; k + 1 < len; k += 64) {
                    __half2 v = { src[so + k], src[so + k + 1] };
                    *(__half2*)(out + dst + k) = v;
                }
                if (((len - k0) & 1) && lane == 0) out[dst + len - 1] = src[so + len - 1];
            }
        }
        // segment B: cl in [0,cut) -> row t-1
        if (t >= 1 && cut > 0) {
            int len = cut;
            size_t dst = (size_t)(t - 1) * T_ + (n0 + t + 1);
            int k0 = (int)(dst & 1);
            if (k0 && lane == 0) out[dst] = src[0];
            for (int k = k0 + 2 * lane; k + 1 < len; k += 64) {
                __half2 v = { src[k], src[k + 1] };
                *(__half2*)(out + dst + k) = v;
            }
            if (((len - k0) & 1) && lane == 0) out[dst + len - 1] = src[len - 1];
        }
    }
}

// ============================================================
// Flash attention: t-tile 128, s-tile 64, 2 CTAs/SM, all-fp16 MMA.
// P in registers; K d-permuted and V t-permuted -> all LDS.64 frags.
// Diagonal-aware BD masking (uniform warp branch).
// ============================================================
__global__ __launch_bounds__(256, 2) void k_flash(const float* __restrict__ rwb) {
    extern __shared__ unsigned smem[];
    const int KW = 64 * 40;                 // K tile words (fp16, pitch 40)
    const int VW = 64 * 40;                 // V tile words (fp16 transposed, pitch 40)
    const int BUFW = KW + VW;               // 5120 words per stage
    unsigned* Ps = smem + 2 * BUFW;         // BD: [128][36] words

    const int bh = blockIdx.y, h = bh & 7, b = bh >> 3;
    const int t0 = blockIdx.x * 128;
    const __half* Q  = g_q + (size_t)bh * T_ * D_;
    const __half* K  = g_k + (size_t)bh * T_ * D_;
    const __half* V  = g_v + (size_t)bh * D_ * T_;   // [d][t'] (t-permuted)
    const __half* BD = g_BDs + (size_t)bh * T_ * T_;

    const int tid = threadIdx.x, lane = tid & 31, warp = tid >> 5;
    const int r = lane >> 2, cc = lane & 3;
    const int row0 = warp * 16;
    const int trow0 = t0 + row0 + r, trow1 = trow0 + 8;

#define PREFETCH_KV(buf, s0_) do {                                            \
    unsigned* Kb_ = smem + (buf) * BUFW;                                      \
    unsigned* Vb_ = Kb_ + KW;                                                 \
    _Pragma("unroll")                                                         \
    for (int i_ = 0; i_ < 2; i_++) {      /* K: 64 s-rows x 8 chunks */       \
        int idx_ = tid + i_ * 256;                                            \
        int row_ = idx_ >> 3, ch_ = idx_ & 7;                                 \
        cpa16(Kb_ + row_*40 + ch_*4, K + (size_t)((s0_) + row_) * D_ + ch_*8);\
    }                                                                         \
    _Pragma("unroll")                                                         \
    for (int i_ = 0; i_ < 2; i_++) {      /* V: 64 d-rows x 8 chunks */       \
        int idx_ = tid + i_ * 256;                                            \
        int row_ = idx_ >> 3, ch_ = idx_ & 7;                                 \
        cpa16(Vb_ + row_*40 + ch_*4, V + (size_t)row_ * T_ + (s0_) + ch_*8);  \
    }                                                                         \
    asm volatile("cp.async.commit_group;" ::: "memory");                      \
} while (0)

#define PREFETCH_BD(s0_) do {                                                 \
    _Pragma("unroll")                                                         \
    for (int i_ = 0; i_ < 4; i_++) {                                          \
        int idx_ = lane + i_ * 32;                                            \
        int row_ = idx_ >> 3, c16_ = idx_ & 7;                                \
        cpa16(Ps + (row0 + row_) * 36 + c16_ * 4,                             \
              BD + (size_t)(t0 + row0 + row_) * T_ + (s0_) + c16_ * 8);       \
    }                                                                         \
    asm volatile("cp.async.commit_group;" ::: "memory");                      \
} while (0)

    // q fragments (fp16 m16n8k16 A layout), prescaled + rwb
    unsigned aq[4][4];
    const float* rwbh = rwb + h * D_;
    #pragma unroll
    for (int kc = 0; kc < 4; kc++) {
        int c0 = kc * 16 + 2 * cc;
        #pragma unroll
        for (int half8 = 0; half8 < 2; half8++) {
            int c = c0 + half8 * 8;
            float2 q0 = __half22float2(*(const __half2*)(Q + (size_t)trow0 * D_ + c));
            float2 q1 = __half22float2(*(const __half2*)(Q + (size_t)trow1 * D_ + c));
            __half2 a0 = __floats2half2_rn((q0.x + rwbh[c]) * SCL, (q0.y + rwbh[c+1]) * SCL);
            __half2 a1 = __floats2half2_rn((q1.x + rwbh[c]) * SCL, (q1.y + rwbh[c+1]) * SCL);
            aq[kc][half8 * 2]     = *(unsigned*)&a0;
            aq[kc][half8 * 2 + 1] = *(unsigned*)&a1;
        }
    }

    PREFETCH_KV(0, 0);
    PREFETCH_BD(0);

    float oacc[8][4] = {};
    float m0r = -1e30f, m1r = -1e30f, l0 = 0.f, l1 = 0.f;

    #pragma unroll 1
    for (int it = 0; it < T_ / 64; it++) {
        const int s0 = it * 64;
        const int cur = it & 1;
        asm volatile("cp.async.wait_group 1;" ::: "memory");   // KV(it)
        __syncthreads();

        PREFETCH_KV(cur ^ 1, (s0 + 64) & (T_ - 1));

        const unsigned* Kb = smem + cur * BUFW;
        const unsigned* Vb = Kb + KW;

        // ---- AC = qw · K^T (fp16) ----
        float pacc[8][4];
        #pragma unroll
        for (int nt = 0; nt < 8; nt++)
            #pragma unroll
            for (int j = 0; j < 4; j++) pacc[nt][j] = 0.f;
        #pragma unroll
        for (int kc = 0; kc < 4; kc++) {
            #pragma unroll
            for (int nt = 0; nt < 8; nt++) {
                int srow = nt * 8 + r;
                uint2 kb2 = *(const uint2*)(Kb + srow * 40 + kc * 8 + 2 * cc);
                unsigned bf[2] = { kb2.x, kb2.y };
                MMA16(pacc[nt], aq[kc], bf);
            }
        }

        asm volatile("cp.async.wait_group 1;" ::: "memory");   // BD(it)
        __syncwarp();

        // ---- add BD (diagonal-aware masking), row max ----
        const __half2* bd0 = (const __half2*)(Ps + (row0 + r) * 36);
        const __half2* bd1 = (const __half2*)(Ps + (row0 + r + 8) * 36);
        float pm0 = -1e30f, pm1 = -1e30f;
        const bool diag = (t0 + row0 + 1 <= s0 + 63) && (t0 + row0 + 16 >= s0);
        if (diag) {
            #pragma unroll
            for (int nt = 0; nt < 8; nt++) {
                int sb = s0 + nt * 8 + 2 * cc;
                float2 f0 = __half22float2(bd0[4 * nt + cc]);
                float2 f1 = __half22float2(bd1[4 * nt + cc]);
                pacc[nt][0] += (sb     == trow0 + 1) ? 0.f : f0.x;
                pacc[nt][1] += (sb + 1 == trow0 + 1) ? 0.f : f0.y;
                pacc[nt][2] += (sb     == trow1 + 1) ? 0.f : f1.x;
                pacc[nt][3] += (sb + 1 == trow1 + 1) ? 0.f : f1.y;
                pm0 = fmaxf(pm0, fmaxf(pacc[nt][0], pacc[nt][1]));
                pm1 = fmaxf(pm1, fmaxf(pacc[nt][2], pacc[nt][3]));
            }
        } else {
            #pragma unroll
            for (int nt = 0; nt < 8; nt++) {
                float2 f0 = __half22float2(bd0[4 * nt + cc]);
                float2 f1 = __half22float2(bd1[4 * nt + cc]);
                pacc[nt][0] += f0.x;
                pacc[nt][1] += f0.y;
                pacc[nt][2] += f1.x;
                pacc[nt][3] += f1.y;
                pm0 = fmaxf(pm0, fmaxf(pacc[nt][0], pacc[nt][1]));
                pm1 = fmaxf(pm1, fmaxf(pacc[nt][2], pacc[nt][3]));
            }
        }
        pm0 = fmaxf(pm0, __shfl_xor_sync(0xffffffffu, pm0, 1));
        pm0 = fmaxf(pm0, __shfl_xor_sync(0xffffffffu, pm0, 2));
        pm1 = fmaxf(pm1, __shfl_xor_sync(0xffffffffu, pm1, 1));
        pm1 = fmaxf(pm1, __shfl_xor_sync(0xffffffffu, pm1, 2));

        float mn0 = fmaxf(m0r, pm0), mn1 = fmaxf(m1r, pm1);
        float sf0 = ex2f(m0r - mn0), sf1 = ex2f(m1r - mn1);
        m0r = mn0; m1r = mn1;
        #pragma unroll
        for (int nt = 0; nt < 8; nt++) {
            oacc[nt][0] *= sf0; oacc[nt][1] *= sf0;
            oacc[nt][2] *= sf1; oacc[nt][3] *= sf1;
        }
        l0 *= sf0; l1 *= sf1;

        // ---- exp, rowsum, pack P to fp16 IN REGISTERS ----
        unsigned ph[8][2];
        float sum0 = 0.f, sum1 = 0.f;
        #pragma unroll
        for (int nt = 0; nt < 8; nt++) {
            float e0 = ex2f(pacc[nt][0] - mn0);
            float e1 = ex2f(pacc[nt][1] - mn0);
            float e2 = ex2f(pacc[nt][2] - mn1);
            float e3 = ex2f(pacc[nt][3] - mn1);
            sum0 += e0 + e1; sum1 += e2 + e3;
            __half2 p0 = __floats2half2_rn(e0, e1);
            __half2 p1 = __floats2half2_rn(e2, e3);
            ph[nt][0] = *(unsigned*)&p0;
            ph[nt][1] = *(unsigned*)&p1;
        }
        sum0 += __shfl_xor_sync(0xffffffffu, sum0, 1);
        sum0 += __shfl_xor_sync(0xffffffffu, sum0, 2);
        sum1 += __shfl_xor_sync(0xffffffffu, sum1, 1);
        sum1 += __shfl_xor_sync(0xffffffffu, sum1, 2);
        l0 += sum0; l1 += sum1;

        // ---- O += P · V (fp16; A-frag from registers, B-frag LDS.64) ----
        #pragma unroll
        for (int kc = 0; kc < 4; kc++) {
            unsigned af[4] = { ph[2*kc][0], ph[2*kc][1], ph[2*kc+1][0], ph[2*kc+1][1] };
            #pragma unroll
            for (int nt = 0; nt < 8; nt++) {
                int drow = nt * 8 + r;
                uint2 vb2 = *(const uint2*)(Vb + drow * 40 + kc * 8 + 2 * cc);
                unsigned bf[2] = { vb2.x, vb2.y };
                MMA16(oacc[nt], af, bf);
            }
        }
        __syncwarp();

        if (it < T_ / 64 - 1)
            PREFETCH_BD(s0 + 64);
    }
    asm volatile("cp.async.wait_group 0;" ::: "memory");

    // ---- epilogue: O /= l -> g_ctx (fp16) ----
    float il0 = 1.f / l0, il1 = 1.f / l1;
    #pragma unroll
    for (int nt = 0; nt < 8; nt++) {
        int d = h * 64 + nt * 8 + 2 * cc;
        __half2 o0 = __floats2half2_rn(oacc[nt][0] * il0, oacc[nt][1] * il0);
        *(__half2*)(g_ctx + ((size_t)trow0 * B_ + b) * E_ + d) = o0;
        __half2 o1 = __floats2half2_rn(oacc[nt][2] * il1, oacc[nt][3] * il1);
        *(__half2*)(g_ctx + ((size_t)trow1 * B_ + b) * E_ + d) = o1;
    }
#undef PREFETCH_KV
#undef PREFETCH_BD
}

// ============================================================
// out projection (fp16 GEMM, fp32 output)
// ============================================================
__global__ __launch_bounds__(256) void k_out(const float* __restrict__ bias,
                                             float* __restrict__ out) {
    extern __shared__ unsigned dsm[];
    float acc[4][4][4] = {};
    const int m0 = blockIdx.y * 128, n0 = blockIdx.x * 128;
    gemm_nt_hp<E_>(g_ctx, E_, g_cwout, E_, m0, n0, acc, dsm);
    const int lane = threadIdx.x & 31, warp = threadIdx.x >> 5;
    const int wm = (warp >> 2) * 64, wn = (warp & 3) * 32;
    #pragma unroll
    for (int mi = 0; mi < 4; mi++)
        #pragma unroll
        for (int ni = 0; ni < 4; ni++)
            #pragma unroll
            for (int rg = 0; rg < 4; rg++) {
                int row = EPI_ROW(m0, wm, mi, rg);
                int col = EPI_COL(n0, wn, ni, rg);
                out[(size_t)row * E_ + col] = acc[mi][ni][rg] + bias[col];
            }
}

// ============================================================
extern "C" void kernel_launch(void* const* d_in, const int* in_sizes, int n_in,
                              void* d_out, int out_size) {
    const float* input = (const float*)d_in[0];
    const float* pos   = (const float*)d_in[1];
    const float* w_in  = (const float*)d_in[2];
    const float* w_out = (const float*)d_in[3];
    const float* w_pos = (const float*)d_in[4];
    const float* b_in  = (const float*)d_in[5];
    const float* b_out = (const float*)d_in[6];
    const float* b_pos = (const float*)d_in[7];
    const float* rwb   = (const float*)d_in[8];
    const float* rrb   = (const float*)d_in[9];
    float* out = (float*)d_out;

    const int gemm_smem  = 2 * 2 * 128 * 20 * 4;                 // 40960
    const int bd_smem    = 128 * 136 * 2;                        // 34816
    const int kbd_smem   = gemm_smem > bd_smem ? gemm_smem : bd_smem;
    const int flash_smem = (2 * (64*40 + 64*40) + 128*36) * 4;   // 59392
    cudaFuncSetAttribute(k_qkv,  cudaFuncAttributeMaxDynamicSharedMemorySize, gemm_smem);
    cudaFuncSetAttribute(k_pos,  cudaFuncAttributeMaxDynamicSharedMemorySize, gemm_smem);
    cudaFuncSetAttribute(k_bd,   cudaFuncAttributeMaxDynamicSharedMemorySize, kbd_smem);
    cudaFuncSetAttribute(k_out,  cudaFuncAttributeMaxDynamicSharedMemorySize, gemm_smem);
    cudaFuncSetAttribute(k_flash, cudaFuncAttributeMaxDynamicSharedMemorySize, flash_smem);

    k_cvt_all<<<(N4_TOT + 255)/256, 256>>>(input, pos, w_in, w_out, w_pos);

    k_qkv  <<<dim3(E3_/128, (T_*B_)/128), 256, gemm_smem>>>(b_in);
    k_pos  <<<dim3(E_/128,  T_/128),      256, gemm_smem>>>(b_pos);
    k_brdot<<<H_*T_/128, 128>>>(rrb);
    k_bd   <<<dim3(T_/128, T_/128, B_*H_), 256, kbd_smem>>>();
    k_flash<<<dim3(T_/128, B_*H_), 256, flash_smem>>>(rwb);
    k_out  <<<dim3(E_/128, (T_*B_)/128), 256, gemm_smem>>>(b_out, out);
}

// round 11
// speedup vs baseline: 1.2796x; 1.0366x over previous
#include <cuda_runtime.h>
#include <cuda_fp16.h>
#include <math.h>

#define T_  2048
#define B_  2
#define E_  512
#define H_  8
#define D_  64
#define E3_ 1536

// scale * log2(e): softmax in base-2 domain
#define SCL 0.1803368801111204f

// uint-pair permute within each 8-uint chunk: o -> ((o&3)<<1)|(o>>2)
// Applied to the K-contiguous dim of EVERY fp16 MMA operand so that the
// m16n8k16 fragment pairs (u, u+4) are physically adjacent (LDS.64).
__device__ __forceinline__ int permu(int u) {
    return (u & ~7) | (((u & 3) << 1) | ((u >> 2) & 1));
}

// ---- scratch (__device__ globals: allocation-guard-legal) ----
__device__ __half g_q[B_*H_*T_*D_];           // [B,H,T,D] fp16, d-permuted
__device__ __half g_k[B_*H_*T_*D_];           // [B,H,T,D] fp16, d-permuted
__device__ __half g_v[B_*H_*D_*T_];           // [B,H,D,T] fp16, t-permuted
__device__ __half g_r[H_*T_*D_];              // [H,R,D]   fp16, d-permuted
__device__ float  g_br[H_*T_];                // rrb_h · r[h,c]
__device__ __half g_BDs[(size_t)B_*H_*T_*T_]; // BD, PRE-SHIFTED + scaled, fp16
__device__ __half g_ctx[T_*B_*E_];            // [T,B,E]   fp16, E-permuted
// fp16 copies of harness inputs, K-permuted (raw cp.async GEMM operands)
__device__ __half g_ci[T_*B_*E_];
__device__ __half g_cpos[T_*E_];
__device__ __half g_cwin[E3_*E_];
__device__ __half g_cwout[E_*E_];
__device__ __half g_cwpos[E_*E_];

__device__ __forceinline__ float ex2f(float x) {
    float y;
    asm("ex2.approx.ftz.f32 %0, %1;" : "=f"(y) : "f"(x));
    return y;
}
__device__ __forceinline__ void cpa16(void* d, const void* s) {
    unsigned a = (unsigned)__cvta_generic_to_shared(d);
    asm volatile("cp.async.cg.shared.global [%0], [%1], 16;" :: "r"(a), "l"(s));
}

// fp16 mma, fp32 accum
#define MMA16(d, a, b) \
  asm volatile("mma.sync.aligned.m16n8k16.row.col.f32.f16.f16.f32 " \
      "{%0,%1,%2,%3},{%4,%5,%6,%7},{%8,%9},{%0,%1,%2,%3};" \
      : "+f"((d)[0]), "+f"((d)[1]), "+f"((d)[2]), "+f"((d)[3]) \
      : "r"((a)[0]), "r"((a)[1]), "r"((a)[2]), "r"((a)[3]), \
        "r"((b)[0]), "r"((b)[1]))

// ============================================================
// One-shot fp32 -> fp16 conversion of all inputs, K-PERMUTED
// ============================================================
#define N4_CI   (T_*B_*E_/4)
#define N4_CPOS (T_*E_/4)
#define N4_CWIN (E3_*E_/4)
#define N4_CW   (E_*E_/4)
#define N4_TOT  (N4_CI + N4_CPOS + N4_CWIN + 2*N4_CW)

__global__ __launch_bounds__(256) void k_cvt_all(const float* __restrict__ s0,
                                                 const float* __restrict__ s1,
                                                 const float* __restrict__ s2,
                                                 const float* __restrict__ s3,
                                                 const float* __restrict__ s4) {
    int i = blockIdx.x * 256 + threadIdx.x;
    if (i >= N4_TOT) return;
    const float* src; __half* dst; int off = i;
    if (i < N4_CI)                               { src = s0; dst = g_ci; }
    else if ((off -= N4_CI)   < N4_CPOS)         { src = s1; dst = g_cpos; }
    else if ((off -= N4_CPOS) < N4_CWIN)         { src = s2; dst = g_cwin; }
    else if ((off -= N4_CWIN) < N4_CW)           { src = s3; dst = g_cwout; }
    else { off -= N4_CW;                           src = s4; dst = g_cwpos; }
    float4 v = ((const float4*)src)[off];
    __half2 h0 = __floats2half2_rn(v.x, v.y);
    __half2 h1 = __floats2half2_rn(v.z, v.w);
    unsigned* du = (unsigned*)dst;
    du[permu(2 * off)]     = *(unsigned*)&h0;   // row-internal permute: all rows
    du[permu(2 * off + 1)] = *(unsigned*)&h1;   // are multiples of 8 uints wide
}

// ============================================================
// fp16 double-buffered cp.async NT mainloop: C[128,128] = A·Bt^T.
// Operands K-PERMUTED -> fragments are uint2 LDS.64 (pitch 24, conflict-free).
// smem: 2 stages x (As 128x24 + Bs 128x24) uints = 49152 B.
// ============================================================
template<int KTOT>
__device__ __forceinline__ void gemm_nt_hp(const __half* __restrict__ A, int lda,
                                           const __half* __restrict__ Bt, int ldb,
                                           int m0, int n0, float acc[4][4][4],
                                           unsigned* sm) {
    const int tid = threadIdx.x;
    const int lane = tid & 31, warp = tid >> 5;
    const int wm = (warp >> 2) * 64, wn = (warp & 3) * 32;

#define HSTAGE(buf_, k0_) do {                                                \
    unsigned* As_ = sm + (buf_) * 6144;                                       \
    unsigned* Bs_ = As_ + 3072;                                               \
    _Pragma("unroll")                                                         \
    for (int i_ = 0; i_ < 2; i_++) {                                          \
        int idx_ = tid + i_ * 256;                                            \
        int row_ = idx_ >> 2, c8_ = (idx_ & 3) * 8;                           \
        cpa16(As_ + row_*24 + (idx_ & 3)*4, A  + (size_t)(m0 + row_) * lda + (k0_) + c8_); \
        cpa16(Bs_ + row_*24 + (idx_ & 3)*4, Bt + (size_t)(n0 + row_) * ldb + (k0_) + c8_); \
    }                                                                         \
    asm volatile("cp.async.commit_group;" ::: "memory");                      \
} while (0)

    HSTAGE(0, 0);
    #pragma unroll 1
    for (int k0 = 0; k0 < KTOT; k0 += 32) {
        const int buf = (k0 >> 5) & 1;
        const bool more = (k0 + 32 < KTOT);
        if (more) HSTAGE(buf ^ 1, k0 + 32);
        if (more) asm volatile("cp.async.wait_group 1;" ::: "memory");
        else      asm volatile("cp.async.wait_group 0;" ::: "memory");
        __syncthreads();

        const unsigned* As = sm + buf * 6144;
        const unsigned* Bs = As + 3072;
        #pragma unroll
        for (int ks = 0; ks < 2; ks++) {
            const int r = lane >> 2, cb = ks * 8 + 2 * (lane & 3);
            unsigned af[4][4], bf[4][2];
            #pragma unroll
            for (int mi = 0; mi < 4; mi++) {
                int rr = wm + mi * 16 + r;
                uint2 lo = *(const uint2*)(As + rr * 24 + cb);
                uint2 hi = *(const uint2*)(As + (rr + 8) * 24 + cb);
                af[mi][0] = lo.x; af[mi][1] = hi.x;
                af[mi][2] = lo.y; af[mi][3] = hi.y;
            }
            #pragma unroll
            for (int ni = 0; ni < 4; ni++) {
                int rb = wn + ni * 8 + r;
                uint2 u = *(const uint2*)(Bs + rb * 24 + cb);
                bf[ni][0] = u.x; bf[ni][1] = u.y;
            }
            #pragma unroll
            for (int mi = 0; mi < 4; mi++)
                #pragma unroll
                for (int ni = 0; ni < 4; ni++)
                    MMA16(acc[mi][ni], af[mi], bf[ni]);
        }
        __syncthreads();
    }
#undef HSTAGE
}

#define EPI_ROW(m0, wm, mi, rg) ((m0) + (wm) + (mi)*16 + (lane >> 2) + (((rg) & 2) << 2))
#define EPI_COL(n0, wn, ni, rg) ((n0) + (wn) + (ni)*8 + ((lane & 3) << 1) + ((rg) & 1))

// ============================================================
// QKV projection -> q/k [B,H,T,D] d-permuted, v [B,H,D,T] t-permuted
// ============================================================
__global__ __launch_bounds__(256) void k_qkv(const float* __restrict__ bias) {
    extern __shared__ unsigned dsm[];
    float acc[4][4][4] = {};
    const int m0 = blockIdx.y * 128, n0 = blockIdx.x * 128;
    gemm_nt_hp<E_>(g_ci, E_, g_cwin, E_, m0, n0, acc, dsm);
    const int lane = threadIdx.x & 31, warp = threadIdx.x >> 5;
    const int wm = (warp >> 2) * 64, wn = (warp & 3) * 32;
    #pragma unroll
    for (int mi = 0; mi < 4; mi++)
        #pragma unroll
        for (int ni = 0; ni < 4; ni++)
            #pragma unroll
            for (int rg = 0; rg < 4; rg++) {
                int row = EPI_ROW(m0, wm, mi, rg);
                int col = EPI_COL(n0, wn, ni, rg);
                float v = acc[mi][ni][rg] + bias[col];
                int t = row / B_, b = row % B_;
                int sec = col >> 9, h = (col >> 6) & 7, d = col & 63;
                if (sec == 2) {
                    // V transposed [B,H,D,T]; permute t words
                    int w = t >> 1;
                    int tp = (permu(w) << 1) | (t & 1);
                    g_v[(((size_t)(b * H_ + h) * D_) + d) * T_ + tp] = __float2half_rn(v);
                } else {
                    int pd = (permu(d >> 1) << 1) | (d & 1);
                    __half* dst = (sec == 0) ? g_q : g_k;
                    dst[(((size_t)(b * H_ + h) * T_) + t) * D_ + pd] = __float2half_rn(v);
                }
            }
}

// ============================================================
// pos projection -> g_r[H,R,D] d-permuted + in-block br
// (each block covers 2 FULL heads x 128 r-rows -> 256 br dots)
// ============================================================
__global__ __launch_bounds__(256) void k_pos(const float* __restrict__ bias,
                                             const float* __restrict__ rrb) {
    extern __shared__ unsigned dsm[];
    float acc[4][4][4] = {};
    const int m0 = blockIdx.y * 128, n0 = blockIdx.x * 128;
    gemm_nt_hp<E_>(g_cpos, E_, g_cwpos, E_, m0, n0, acc, dsm);
    const int tid = threadIdx.x, lane = tid & 31, warp = tid >> 5;
    const int wm = (warp >> 2) * 64, wn = (warp & 3) * 32;
    __half* Hs = (__half*)dsm;                 // [128][136] logical tile
    #pragma unroll
    for (int mi = 0; mi < 4; mi++)
        #pragma unroll
        for (int ni = 0; ni < 4; ni++)
            #pragma unroll
            for (int rg = 0; rg < 4; rg++) {
                int rr = EPI_ROW(m0, wm, mi, rg);
                int col = EPI_COL(n0, wn, ni, rg);
                int h = col >> 6, d = col & 63;
                __half hv = __float2half_rn(acc[mi][ni][rg] + bias[col]);
                int pd = (permu(d >> 1) << 1) | (d & 1);
                g_r[((size_t)h * T_ + rr) * D_ + pd] = hv;
                Hs[(rr - m0) * 136 + (col - n0)] = hv;   // logical copy for br
            }
    __syncthreads();

    // br: one dot per thread (128 rows x 2 heads)
    int lr = tid & 127, hl = tid >> 7;
    int h = (n0 >> 6) + hl;
    const __half2* rowp = (const __half2*)(Hs + lr * 136 + hl * 64);
    const float* bb = rrb + h * D_;
    float s = 0.f;
    #pragma unroll
    for (int i = 0; i < 32; i++) {
        float2 a = __half22float2(rowp[i]);
        s += a.x * bb[2*i] + a.y * bb[2*i + 1];
    }
    g_br[h * T_ + m0 + lr] = s;
}

// ============================================================
// BD: raw[t,c] = q[t]·r[c] + br[c], written PRE-SHIFTED + scaled fp16.
// ============================================================
__global__ __launch_bounds__(256) void k_bd() {
    extern __shared__ unsigned dsm[];
    const int bh = blockIdx.z, h = bh & 7;
    float acc[4][4][4] = {};
    const int m0 = blockIdx.y * 128, n0 = blockIdx.x * 128;
    gemm_nt_hp<D_>(g_q + (size_t)bh * T_ * D_, D_,
                   g_r + (size_t)h  * T_ * D_, D_, m0, n0, acc, dsm);

    const int tid = threadIdx.x, lane = tid & 31, warp = tid >> 5;
    const int wm = (warp >> 2) * 64, wn = (warp & 3) * 32;
    __half* Hs = (__half*)dsm;                 // [128][136] halfs
    const float* br = g_br + h * T_;
    #pragma unroll
    for (int mi = 0; mi < 4; mi++)
        #pragma unroll
        for (int ni = 0; ni < 4; ni++)
            #pragma unroll
            for (int rg = 0; rg < 4; rg++) {
                int lt = wm + mi*16 + (lane >> 2) + (((rg) & 2) << 2);
                int lc = wn + ni*8 + ((lane & 3) << 1) + ((rg) & 1);
                float v = (acc[mi][ni][rg] + br[n0 + lc]) * SCL;
                Hs[lt * 136 + lc] = __float2half_rn(v);
            }
    __syncthreads();

    __half* out = g_BDs + (size_t)bh * T_ * T_;
    for (int i = 0; i < 16; i++) {
        int lt = warp * 16 + i;
        int t = m0 + lt;
        int cut = (T_ - 1) - t - n0;
        cut = min(max(cut, 0), 128);
        const __half* src = Hs + lt * 136;

        // segment A: cl in [cut,128) -> row t
        {
            int len = 128 - cut;
            if (len > 0) {
                size_t dst = (size_t)t * T_ + (n0 + cut + t - (T_ - 1));
                int so = cut;
                int k0 = (int)(dst & 1);
                if (k0 && lane == 0) out[dst] = src[so];
                for (int k = k0 + 2 * lane; k + 1 < len; k += 64) {
                    __half2 v = { src[so + k], src[so + k + 1] };
                    *(__half2*)(out + dst + k) = v;
                }
                if (((len - k0) & 1) && lane == 0) out[dst + len - 1] = src[so + len - 1];
            }
        }
        // segment B: cl in [0,cut) -> row t-1
        if (t >= 1 && cut > 0) {
            int len = cut;
            size_t dst = (size_t)(t - 1) * T_ + (n0 + t + 1);
            int k0 = (int)(dst & 1);
            if (k0 && lane == 0) out[dst] = src[0];
            for (int k = k0 + 2 * lane; k + 1 < len; k += 64) {
                __half2 v = { src[k], src[k + 1] };
                *(__half2*)(out + dst + k) = v;
            }
            if (((len - k0) & 1) && lane == 0) out[dst + len - 1] = src[len - 1];
        }
    }
}

// ============================================================
// Flash attention: as round 10 (t-tile 128, s-tile 64, 2 CTAs/SM,
// all-fp16 MMA, P in registers, LDS.64 K/V frags, diag-aware mask).
// aq now single uint2 gmem loads (q is d-permuted).
// ============================================================
__global__ __launch_bounds__(256, 2) void k_flash(const float* __restrict__ rwb) {
    extern __shared__ unsigned smem[];
    const int KW = 64 * 40;
    const int VW = 64 * 40;
    const int BUFW = KW + VW;
    unsigned* Ps = smem + 2 * BUFW;         // BD: [128][36] words

    const int bh = blockIdx.y, h = bh & 7, b = bh >> 3;
    const int t0 = blockIdx.x * 128;
    const __half* Q  = g_q + (size_t)bh * T_ * D_;
    const __half* K  = g_k + (size_t)bh * T_ * D_;
    const __half* V  = g_v + (size_t)bh * D_ * T_;
    const __half* BD = g_BDs + (size_t)bh * T_ * T_;

    const int tid = threadIdx.x, lane = tid & 31, warp = tid >> 5;
    const int r = lane >> 2, cc = lane & 3;
    const int row0 = warp * 16;
    const int trow0 = t0 + row0 + r, trow1 = trow0 + 8;

#define PREFETCH_KV(buf, s0_) do {                                            \
    unsigned* Kb_ = smem + (buf) * BUFW;                                      \
    unsigned* Vb_ = Kb_ + KW;                                                 \
    _Pragma("unroll")                                                         \
    for (int i_ = 0; i_ < 2; i_++) {                                          \
        int idx_ = tid + i_ * 256;                                            \
        int row_ = idx_ >> 3, ch_ = idx_ & 7;                                 \
        cpa16(Kb_ + row_*40 + ch_*4, K + (size_t)((s0_) + row_) * D_ + ch_*8);\
    }                                                                         \
    _Pragma("unroll")                                                         \
    for (int i_ = 0; i_ < 2; i_++) {                                          \
        int idx_ = tid + i_ * 256;                                            \
        int row_ = idx_ >> 3, ch_ = idx_ & 7;                                 \
        cpa16(Vb_ + row_*40 + ch_*4, V + (size_t)row_ * T_ + (s0_) + ch_*8);  \
    }                                                                         \
    asm volatile("cp.async.commit_group;" ::: "memory");                      \
} while (0)

#define PREFETCH_BD(s0_) do {                                                 \
    _Pragma("unroll")                                                         \
    for (int i_ = 0; i_ < 4; i_++) {                                          \
        int idx_ = lane + i_ * 32;                                            \
        int row_ = idx_ >> 3, c16_ = idx_ & 7;                                \
        cpa16(Ps + (row0 + row_) * 36 + c16_ * 4,                             \
              BD + (size_t)(t0 + row0 + row_) * T_ + (s0_) + c16_ * 8);       \
    }                                                                         \
    asm volatile("cp.async.commit_group;" ::: "memory");                      \
} while (0)

    // q fragments (fp16 m16n8k16 A layout), prescaled + rwb.
    // q d-permuted -> logical pairs (u, u+4) are adjacent: uint2 loads.
    unsigned aq[4][4];
    const float* rwbh = rwb + h * D_;
    const unsigned* Qu = (const unsigned*)Q;
    #pragma unroll
    for (int kc = 0; kc < 4; kc++) {
        int c0 = kc * 16 + 2 * cc;
        uint2 qw0 = *(const uint2*)(Qu + (size_t)trow0 * 32 + kc * 8 + 2 * cc);
        uint2 qw1 = *(const uint2*)(Qu + (size_t)trow1 * 32 + kc * 8 + 2 * cc);
        float2 f;
        __half2 a;
        f = __half22float2(*(__half2*)&qw0.x);
        a = __floats2half2_rn((f.x + rwbh[c0]) * SCL, (f.y + rwbh[c0+1]) * SCL);
        aq[kc][0] = *(unsigned*)&a;
        f = __half22float2(*(__half2*)&qw1.x);
        a = __floats2half2_rn((f.x + rwbh[c0]) * SCL, (f.y + rwbh[c0+1]) * SCL);
        aq[kc][1] = *(unsigned*)&a;
        f = __half22float2(*(__half2*)&qw0.y);
        a = __floats2half2_rn((f.x + rwbh[c0+8]) * SCL, (f.y + rwbh[c0+9]) * SCL);
        aq[kc][2] = *(unsigned*)&a;
        f = __half22float2(*(__half2*)&qw1.y);
        a = __floats2half2_rn((f.x + rwbh[c0+8]) * SCL, (f.y + rwbh[c0+9]) * SCL);
        aq[kc][3] = *(unsigned*)&a;
    }

    PREFETCH_KV(0, 0);
    PREFETCH_BD(0);

    float oacc[8][4] = {};
    float m0r = -1e30f, m1r = -1e30f, l0 = 0.f, l1 = 0.f;

    #pragma unroll 1
    for (int it = 0; it < T_ / 64; it++) {
        const int s0 = it * 64;
        const int cur = it & 1;
        asm volatile("cp.async.wait_group 1;" ::: "memory");   // KV(it)
        __syncthreads();

        PREFETCH_KV(cur ^ 1, (s0 + 64) & (T_ - 1));

        const unsigned* Kb = smem + cur * BUFW;
        const unsigned* Vb = Kb + KW;

        // ---- AC = qw · K^T ----
        float pacc[8][4];
        #pragma unroll
        for (int nt = 0; nt < 8; nt++)
            #pragma unroll
            for (int j = 0; j < 4; j++) pacc[nt][j] = 0.f;
        #pragma unroll
        for (int kc = 0; kc < 4; kc++) {
            #pragma unroll
            for (int nt = 0; nt < 8; nt++) {
                int srow = nt * 8 + r;
                uint2 kb2 = *(const uint2*)(Kb + srow * 40 + kc * 8 + 2 * cc);
                unsigned bf[2] = { kb2.x, kb2.y };
                MMA16(pacc[nt], aq[kc], bf);
            }
        }

        asm volatile("cp.async.wait_group 1;" ::: "memory");   // BD(it)
        __syncwarp();

        // ---- add BD (diagonal-aware masking), row max ----
        const __half2* bd0 = (const __half2*)(Ps + (row0 + r) * 36);
        const __half2* bd1 = (const __half2*)(Ps + (row0 + r + 8) * 36);
        float pm0 = -1e30f, pm1 = -1e30f;
        const bool diag = (t0 + row0 + 1 <= s0 + 63) && (t0 + row0 + 16 >= s0);
        if (diag) {
            #pragma unroll
            for (int nt = 0; nt < 8; nt++) {
                int sb = s0 + nt * 8 + 2 * cc;
                float2 f0 = __half22float2(bd0[4 * nt + cc]);
                float2 f1 = __half22float2(bd1[4 * nt + cc]);
                pacc[nt][0] += (sb     == trow0 + 1) ? 0.f : f0.x;
                pacc[nt][1] += (sb + 1 == trow0 + 1) ? 0.f : f0.y;
                pacc[nt][2] += (sb     == trow1 + 1) ? 0.f : f1.x;
                pacc[nt][3] += (sb + 1 == trow1 + 1) ? 0.f : f1.y;
                pm0 = fmaxf(pm0, fmaxf(pacc[nt][0], pacc[nt][1]));
                pm1 = fmaxf(pm1, fmaxf(pacc[nt][2], pacc[nt][3]));
            }
        } else {
            #pragma unroll
            for (int nt = 0; nt < 8; nt++) {
                float2 f0 = __half22float2(bd0[4 * nt + cc]);
                float2 f1 = __half22float2(bd1[4 * nt + cc]);
                pacc[nt][0] += f0.x;
                pacc[nt][1] += f0.y;
                pacc[nt][2] += f1.x;
                pacc[nt][3] += f1.y;
                pm0 = fmaxf(pm0, fmaxf(pacc[nt][0], pacc[nt][1]));
                pm1 = fmaxf(pm1, fmaxf(pacc[nt][2], pacc[nt][3]));
            }
        }
        pm0 = fmaxf(pm0, __shfl_xor_sync(0xffffffffu, pm0, 1));
        pm0 = fmaxf(pm0, __shfl_xor_sync(0xffffffffu, pm0, 2));
        pm1 = fmaxf(pm1, __shfl_xor_sync(0xffffffffu, pm1, 1));
        pm1 = fmaxf(pm1, __shfl_xor_sync(0xffffffffu, pm1, 2));

        float mn0 = fmaxf(m0r, pm0), mn1 = fmaxf(m1r, pm1);
        float sf0 = ex2f(m0r - mn0), sf1 = ex2f(m1r - mn1);
        m0r = mn0; m1r = mn1;
        #pragma unroll
        for (int nt = 0; nt < 8; nt++) {
            oacc[nt][0] *= sf0; oacc[nt][1] *= sf0;
            oacc[nt][2] *= sf1; oacc[nt][3] *= sf1;
        }
        l0 *= sf0; l1 *= sf1;

        // ---- exp, rowsum, pack P to fp16 IN REGISTERS ----
        unsigned ph[8][2];
        float sum0 = 0.f, sum1 = 0.f;
        #pragma unroll
        for (int nt = 0; nt < 8; nt++) {
            float e0 = ex2f(pacc[nt][0] - mn0);
            float e1 = ex2f(pacc[nt][1] - mn0);
            float e2 = ex2f(pacc[nt][2] - mn1);
            float e3 = ex2f(pacc[nt][3] - mn1);
            sum0 += e0 + e1; sum1 += e2 + e3;
            __half2 p0 = __floats2half2_rn(e0, e1);
            __half2 p1 = __floats2half2_rn(e2, e3);
            ph[nt][0] = *(unsigned*)&p0;
            ph[nt][1] = *(unsigned*)&p1;
        }
        sum0 += __shfl_xor_sync(0xffffffffu, sum0, 1);
        sum0 += __shfl_xor_sync(0xffffffffu, sum0, 2);
        sum1 += __shfl_xor_sync(0xffffffffu, sum1, 1);
        sum1 += __shfl_xor_sync(0xffffffffu, sum1, 2);
        l0 += sum0; l1 += sum1;

        // ---- O += P · V ----
        #pragma unroll
        for (int kc = 0; kc < 4; kc++) {
            unsigned af[4] = { ph[2*kc][0], ph[2*kc][1], ph[2*kc+1][0], ph[2*kc+1][1] };
            #pragma unroll
            for (int nt = 0; nt < 8; nt++) {
                int drow = nt * 8 + r;
                uint2 vb2 = *(const uint2*)(Vb + drow * 40 + kc * 8 + 2 * cc);
                unsigned bf[2] = { vb2.x, vb2.y };
                MMA16(oacc[nt], af, bf);
            }
        }
        __syncwarp();

        if (it < T_ / 64 - 1)
            PREFETCH_BD(s0 + 64);
    }
    asm volatile("cp.async.wait_group 0;" ::: "memory");

    // ---- epilogue: O /= l -> g_ctx (fp16, E-permuted for k_out) ----
    float il0 = 1.f / l0, il1 = 1.f / l1;
    unsigned* ctxu = (unsigned*)g_ctx;
    #pragma unroll
    for (int nt = 0; nt < 8; nt++) {
        int u_l = h * 32 + nt * 4 + cc;        // logical uint index of d pair
        int pu = permu(u_l);
        __half2 o0 = __floats2half2_rn(oacc[nt][0] * il0, oacc[nt][1] * il0);
        ctxu[((size_t)trow0 * B_ + b) * (E_/2) + pu] = *(unsigned*)&o0;
        __half2 o1 = __floats2half2_rn(oacc[nt][2] * il1, oacc[nt][3] * il1);
        ctxu[((size_t)trow1 * B_ + b) * (E_/2) + pu] = *(unsigned*)&o1;
    }
#undef PREFETCH_KV
#undef PREFETCH_BD
}

// ============================================================
// out projection (fp16 GEMM, fp32 output)
// ============================================================
__global__ __launch_bounds__(256) void k_out(const float* __restrict__ bias,
                                             float* __restrict__ out) {
    extern __shared__ unsigned dsm[];
    float acc[4][4][4] = {};
    const int m0 = blockIdx.y * 128, n0 = blockIdx.x * 128;
    gemm_nt_hp<E_>(g_ctx, E_, g_cwout, E_, m0, n0, acc, dsm);
    const int lane = threadIdx.x & 31, warp = threadIdx.x >> 5;
    const int wm = (warp >> 2) * 64, wn = (warp & 3) * 32;
    #pragma unroll
    for (int mi = 0; mi < 4; mi++)
        #pragma unroll
        for (int ni = 0; ni < 4; ni++)
            #pragma unroll
            for (int rg = 0; rg < 4; rg++) {
                int row = EPI_ROW(m0, wm, mi, rg);
                int col = EPI_COL(n0, wn, ni, rg);
                out[(size_t)row * E_ + col] = acc[mi][ni][rg] + bias[col];
            }
}

// ============================================================
extern "C" void kernel_launch(void* const* d_in, const int* in_sizes, int n_in,
                              void* d_out, int out_size) {
    const float* input = (const float*)d_in[0];
    const float* pos   = (const float*)d_in[1];
    const float* w_in  = (const float*)d_in[2];
    const float* w_out = (const float*)d_in[3];
    const float* w_pos = (const float*)d_in[4];
    const float* b_in  = (const float*)d_in[5];
    const float* b_out = (const float*)d_in[6];
    const float* b_pos = (const float*)d_in[7];
    const float* rwb   = (const float*)d_in[8];
    const float* rrb   = (const float*)d_in[9];
    float* out = (float*)d_out;

    const int gemm_smem  = 2 * 2 * 128 * 24 * 4;                 // 49152
    const int flash_smem = (2 * (64*40 + 64*40) + 128*36) * 4;   // 59392
    cudaFuncSetAttribute(k_qkv,  cudaFuncAttributeMaxDynamicSharedMemorySize, gemm_smem);
    cudaFuncSetAttribute(k_pos,  cudaFuncAttributeMaxDynamicSharedMemorySize, gemm_smem);
    cudaFuncSetAttribute(k_bd,   cudaFuncAttributeMaxDynamicSharedMemorySize, gemm_smem);
    cudaFuncSetAttribute(k_out,  cudaFuncAttributeMaxDynamicSharedMemorySize, gemm_smem);
    cudaFuncSetAttribute(k_flash, cudaFuncAttributeMaxDynamicSharedMemorySize, flash_smem);

    k_cvt_all<<<(N4_TOT + 255)/256, 256>>>(input, pos, w_in, w_out, w_pos);

    k_qkv  <<<dim3(E3_/128, (T_*B_)/128), 256, gemm_smem>>>(b_in);
    k_pos  <<<dim3(E_/128,  T_/128),      256, gemm_smem>>>(b_pos, rrb);
    k_bd   <<<dim3(T_/128, T_/128, B_*H_), 256, gemm_smem>>>();
    k_flash<<<dim3(T_/128, B_*H_), 256, flash_smem>>>(rwb);
    k_out  <<<dim3(E_/128, (T_*B_)/128), 256, gemm_smem>>>(b_out, out);
}

// round 12
// speedup vs baseline: 1.3658x; 1.0673x over previous
#include <cuda_runtime.h>
#include <cuda_fp16.h>
#include <math.h>

#define T_  2048
#define B_  2
#define E_  512
#define H_  8
#define D_  64
#define E3_ 1536

// scale * log2(e): softmax in base-2 domain
#define SCL 0.1803368801111204f

// uint-pair permute within each 8-uint chunk: o -> ((o&3)<<1)|(o>>2)
__device__ __forceinline__ int permu(int u) {
    return (u & ~7) | (((u & 3) << 1) | ((u >> 2) & 1));
}

// ---- scratch (__device__ globals: allocation-guard-legal) ----
__device__ __half g_q[B_*H_*T_*D_];           // [B,H,T,D] fp16, d-permuted
__device__ __half g_k[B_*H_*T_*D_];           // [B,H,T,D] fp16, d-permuted
__device__ __half g_v[B_*H_*D_*T_];           // [B,H,D,T] fp16, t-permuted
__device__ __half g_r[H_*T_*D_];              // [H,R,D]   fp16, d-permuted
__device__ float  g_br[H_*T_];                // rrb_h · r[h,c]
__device__ __half g_BDs[(size_t)B_*H_*T_*T_]; // BD, PRE-SHIFTED + scaled, fp16
__device__ __half g_ctx[T_*B_*E_];            // [T,B,E]   fp16, E-permuted
// fp16 copies of harness inputs, K-permuted (raw cp.async GEMM operands)
__device__ __half g_ci[T_*B_*E_];
__device__ __half g_cpos[T_*E_];
__device__ __half g_cwin[E3_*E_];
__device__ __half g_cwout[E_*E_];
__device__ __half g_cwpos[E_*E_];

__device__ __forceinline__ float ex2f(float x) {
    float y;
    asm("ex2.approx.ftz.f32 %0, %1;" : "=f"(y) : "f"(x));
    return y;
}
__device__ __forceinline__ void cpa16(void* d, const void* s) {
    unsigned a = (unsigned)__cvta_generic_to_shared(d);
    asm volatile("cp.async.cg.shared.global [%0], [%1], 16;" :: "r"(a), "l"(s));
}

// fp16 mma, fp32 accum
#define MMA16(d, a, b) \
  asm volatile("mma.sync.aligned.m16n8k16.row.col.f32.f16.f16.f32 " \
      "{%0,%1,%2,%3},{%4,%5,%6,%7},{%8,%9},{%0,%1,%2,%3};" \
      : "+f"((d)[0]), "+f"((d)[1]), "+f"((d)[2]), "+f"((d)[3]) \
      : "r"((a)[0]), "r"((a)[1]), "r"((a)[2]), "r"((a)[3]), \
        "r"((b)[0]), "r"((b)[1]))

// ============================================================
// One-shot fp32 -> fp16 conversion of all inputs, K-PERMUTED
// ============================================================
#define N4_CI   (T_*B_*E_/4)
#define N4_CPOS (T_*E_/4)
#define N4_CWIN (E3_*E_/4)
#define N4_CW   (E_*E_/4)
#define N4_TOT  (N4_CI + N4_CPOS + N4_CWIN + 2*N4_CW)

__global__ __launch_bounds__(256) void k_cvt_all(const float* __restrict__ s0,
                                                 const float* __restrict__ s1,
                                                 const float* __restrict__ s2,
                                                 const float* __restrict__ s3,
                                                 const float* __restrict__ s4) {
    int i = blockIdx.x * 256 + threadIdx.x;
    if (i >= N4_TOT) return;
    const float* src; __half* dst; int off = i;
    if (i < N4_CI)                               { src = s0; dst = g_ci; }
    else if ((off -= N4_CI)   < N4_CPOS)         { src = s1; dst = g_cpos; }
    else if ((off -= N4_CPOS) < N4_CWIN)         { src = s2; dst = g_cwin; }
    else if ((off -= N4_CWIN) < N4_CW)           { src = s3; dst = g_cwout; }
    else { off -= N4_CW;                           src = s4; dst = g_cwpos; }
    float4 v = ((const float4*)src)[off];
    __half2 h0 = __floats2half2_rn(v.x, v.y);
    __half2 h1 = __floats2half2_rn(v.z, v.w);
    unsigned* du = (unsigned*)dst;
    du[permu(2 * off)]     = *(unsigned*)&h0;
    du[permu(2 * off + 1)] = *(unsigned*)&h1;
}

// ============================================================
// fp16 double-buffered cp.async NT mainloop: C[128,128] = A·Bt^T.
// Operands K-PERMUTED -> fragments uint2 LDS.64 (pitch 24, conflict-free).
// ============================================================
template<int KTOT>
__device__ __forceinline__ void gemm_nt_hp(const __half* __restrict__ A, int lda,
                                           const __half* __restrict__ Bt, int ldb,
                                           int m0, int n0, float acc[4][4][4],
                                           unsigned* sm) {
    const int tid = threadIdx.x;
    const int lane = tid & 31, warp = tid >> 5;
    const int wm = (warp >> 2) * 64, wn = (warp & 3) * 32;

#define HSTAGE(buf_, k0_) do {                                                \
    unsigned* As_ = sm + (buf_) * 6144;                                       \
    unsigned* Bs_ = As_ + 3072;                                               \
    _Pragma("unroll")                                                         \
    for (int i_ = 0; i_ < 2; i_++) {                                          \
        int idx_ = tid + i_ * 256;                                            \
        int row_ = idx_ >> 2, c8_ = (idx_ & 3) * 8;                           \
        cpa16(As_ + row_*24 + (idx_ & 3)*4, A  + (size_t)(m0 + row_) * lda + (k0_) + c8_); \
        cpa16(Bs_ + row_*24 + (idx_ & 3)*4, Bt + (size_t)(n0 + row_) * ldb + (k0_) + c8_); \
    }                                                                         \
    asm volatile("cp.async.commit_group;" ::: "memory");                      \
} while (0)

    HSTAGE(0, 0);
    #pragma unroll 1
    for (int k0 = 0; k0 < KTOT; k0 += 32) {
        const int buf = (k0 >> 5) & 1;
        const bool more = (k0 + 32 < KTOT);
        if (more) HSTAGE(buf ^ 1, k0 + 32);
        if (more) asm volatile("cp.async.wait_group 1;" ::: "memory");
        else      asm volatile("cp.async.wait_group 0;" ::: "memory");
        __syncthreads();

        const unsigned* As = sm + buf * 6144;
        const unsigned* Bs = As + 3072;
        #pragma unroll
        for (int ks = 0; ks < 2; ks++) {
            const int r = lane >> 2, cb = ks * 8 + 2 * (lane & 3);
            unsigned af[4][4], bf[4][2];
            #pragma unroll
            for (int mi = 0; mi < 4; mi++) {
                int rr = wm + mi * 16 + r;
                uint2 lo = *(const uint2*)(As + rr * 24 + cb);
                uint2 hi = *(const uint2*)(As + (rr + 8) * 24 + cb);
                af[mi][0] = lo.x; af[mi][1] = hi.x;
                af[mi][2] = lo.y; af[mi][3] = hi.y;
            }
            #pragma unroll
            for (int ni = 0; ni < 4; ni++) {
                int rb = wn + ni * 8 + r;
                uint2 u = *(const uint2*)(Bs + rb * 24 + cb);
                bf[ni][0] = u.x; bf[ni][1] = u.y;
            }
            #pragma unroll
            for (int mi = 0; mi < 4; mi++)
                #pragma unroll
                for (int ni = 0; ni < 4; ni++)
                    MMA16(acc[mi][ni], af[mi], bf[ni]);
        }
        __syncthreads();
    }
#undef HSTAGE
}

#define EPI_ROW(m0, wm, mi, rg) ((m0) + (wm) + (mi)*16 + (lane >> 2) + (((rg) & 2) << 2))
#define EPI_COL(n0, wn, ni, rg) ((n0) + (wn) + (ni)*8 + ((lane & 3) << 1) + ((rg) & 1))

// ============================================================
// QKV projection -> q/k [B,H,T,D] d-permuted, v [B,H,D,T] t-permuted
// ============================================================
__global__ __launch_bounds__(256) void k_qkv(const float* __restrict__ bias) {
    extern __shared__ unsigned dsm[];
    float acc[4][4][4] = {};
    const int m0 = blockIdx.y * 128, n0 = blockIdx.x * 128;
    gemm_nt_hp<E_>(g_ci, E_, g_cwin, E_, m0, n0, acc, dsm);
    const int lane = threadIdx.x & 31, warp = threadIdx.x >> 5;
    const int wm = (warp >> 2) * 64, wn = (warp & 3) * 32;
    #pragma unroll
    for (int mi = 0; mi < 4; mi++)
        #pragma unroll
        for (int ni = 0; ni < 4; ni++)
            #pragma unroll
            for (int rg = 0; rg < 4; rg++) {
                int row = EPI_ROW(m0, wm, mi, rg);
                int col = EPI_COL(n0, wn, ni, rg);
                float v = acc[mi][ni][rg] + bias[col];
                int t = row / B_, b = row % B_;
                int sec = col >> 9, h = (col >> 6) & 7, d = col & 63;
                if (sec == 2) {
                    int w = t >> 1;
                    int tp = (permu(w) << 1) | (t & 1);
                    g_v[(((size_t)(b * H_ + h) * D_) + d) * T_ + tp] = __float2half_rn(v);
                } else {
                    int pd = (permu(d >> 1) << 1) | (d & 1);
                    __half* dst = (sec == 0) ? g_q : g_k;
                    dst[(((size_t)(b * H_ + h) * T_) + t) * D_ + pd] = __float2half_rn(v);
                }
            }
}

// ============================================================
// pos projection -> g_r[H,R,D] d-permuted + in-block br
// ============================================================
__global__ __launch_bounds__(256) void k_pos(const float* __restrict__ bias,
                                             const float* __restrict__ rrb) {
    extern __shared__ unsigned dsm[];
    float acc[4][4][4] = {};
    const int m0 = blockIdx.y * 128, n0 = blockIdx.x * 128;
    gemm_nt_hp<E_>(g_cpos, E_, g_cwpos, E_, m0, n0, acc, dsm);
    const int tid = threadIdx.x, lane = tid & 31, warp = tid >> 5;
    const int wm = (warp >> 2) * 64, wn = (warp & 3) * 32;
    __half* Hs = (__half*)dsm;                 // [128][136] logical tile
    #pragma unroll
    for (int mi = 0; mi < 4; mi++)
        #pragma unroll
        for (int ni = 0; ni < 4; ni++)
            #pragma unroll
            for (int rg = 0; rg < 4; rg++) {
                int rr = EPI_ROW(m0, wm, mi, rg);
                int col = EPI_COL(n0, wn, ni, rg);
                int h = col >> 6, d = col & 63;
                __half hv = __float2half_rn(acc[mi][ni][rg] + bias[col]);
                int pd = (permu(d >> 1) << 1) | (d & 1);
                g_r[((size_t)h * T_ + rr) * D_ + pd] = hv;
                Hs[(rr - m0) * 136 + (col - n0)] = hv;
            }
    __syncthreads();

    int lr = tid & 127, hl = tid >> 7;
    int h = (n0 >> 6) + hl;
    const __half2* rowp = (const __half2*)(Hs + lr * 136 + hl * 64);
    const float* bb = rrb + h * D_;
    float s = 0.f;
    #pragma unroll
    for (int i = 0; i < 32; i++) {
        float2 a = __half22float2(rowp[i]);
        s += a.x * bb[2*i] + a.y * bb[2*i + 1];
    }
    g_br[h * T_ + m0 + lr] = s;
}

// ============================================================
// BD: raw[t,c] = q[t]·r[c] + br[c], written PRE-SHIFTED + scaled fp16.
// BRANCHLESS parity-aligned scatter:
//   src[k] -> (k>=cut ? baseA : baseB) + k, where
//   baseA = t·T + n0 + t - (T-1), baseB = (t-1)·T + n0 + t + 1.
//   baseA, baseB, and the unclamped cut ALL have parity (t+1)&1, so
//   half2 pairs never straddle the cut and stores are always aligned.
// ============================================================
__global__ __launch_bounds__(256) void k_bd() {
    extern __shared__ unsigned dsm[];
    const int bh = blockIdx.z, h = bh & 7;
    float acc[4][4][4] = {};
    const int m0 = blockIdx.y * 128, n0 = blockIdx.x * 128;
    gemm_nt_hp<D_>(g_q + (size_t)bh * T_ * D_, D_,
                   g_r + (size_t)h  * T_ * D_, D_, m0, n0, acc, dsm);

    const int tid = threadIdx.x, lane = tid & 31, warp = tid >> 5;
    const int wm = (warp >> 2) * 64, wn = (warp & 3) * 32;
    __half* Hs = (__half*)dsm;                 // [128][136] halfs
    const float* br = g_br + h * T_;
    #pragma unroll
    for (int mi = 0; mi < 4; mi++)
        #pragma unroll
        for (int ni = 0; ni < 4; ni++)
            #pragma unroll
            for (int rg = 0; rg < 4; rg++) {
                int lt = wm + mi*16 + (lane >> 2) + (((rg) & 2) << 2);
                int lc = wn + ni*8 + ((lane & 3) << 1) + ((rg) & 1);
                float v = (acc[mi][ni][rg] + br[n0 + lc]) * SCL;
                Hs[lt * 136 + lc] = __float2half_rn(v);
            }
    __syncthreads();

    __half* out = g_BDs + (size_t)bh * T_ * T_;
    #pragma unroll 1
    for (int i = 0; i < 16; i++) {
        const int lt = warp * 16 + i;
        const int t = m0 + lt;
        int cut = (T_ - 1) - t - n0;
        cut = min(max(cut, 0), 128);
        const __half* src = Hs + lt * 136;
        const long baseA = (long)t * T_ + n0 + t - (T_ - 1);
        const long baseB = (long)(t - 1) * T_ + n0 + t + 1;
        const bool hasB = (t >= 1);

        if (t & 1) {
            // bases even, cut even: pure half2 lanes
            #pragma unroll
            for (int kk = 0; kk < 2; kk++) {
                int k = 2 * lane + kk * 64;
                bool isA = (k >= cut);
                if (isA | hasB) {
                    long base = isA ? baseA : baseB;
                    *(__half2*)(out + base + k) = *(const __half2*)(src + k);
                }
            }
        } else {
            // bases odd, cut odd (or clamped 0/128): scalar ends + odd-k half2
            if (lane == 0) {
                bool a0 = (0 >= cut);
                if (a0 | hasB) out[(a0 ? baseA : baseB)] = src[0];
                bool a127 = (127 >= cut);
                if (a127 | hasB) out[(a127 ? baseA : baseB) + 127] = src[127];
            }
            #pragma unroll
            for (int kk = 0; kk < 2; kk++) {
                int k = 1 + 2 * lane + kk * 64;
                if (k < 127) {
                    bool isA = (k >= cut);
                    if (isA | hasB) {
                        long base = isA ? baseA : baseB;
                        __half2 v = { src[k], src[k + 1] };
                        *(__half2*)(out + base + k) = v;
                    }
                }
            }
        }
    }
}

// ============================================================
// Flash attention (unchanged from round 11)
// ============================================================
__global__ __launch_bounds__(256, 2) void k_flash(const float* __restrict__ rwb) {
    extern __shared__ unsigned smem[];
    const int KW = 64 * 40;
    const int VW = 64 * 40;
    const int BUFW = KW + VW;
    unsigned* Ps = smem + 2 * BUFW;         // BD: [128][36] words

    const int bh = blockIdx.y, h = bh & 7, b = bh >> 3;
    const int t0 = blockIdx.x * 128;
    const __half* Q  = g_q + (size_t)bh * T_ * D_;
    const __half* K  = g_k + (size_t)bh * T_ * D_;
    const __half* V  = g_v + (size_t)bh * D_ * T_;
    const __half* BD = g_BDs + (size_t)bh * T_ * T_;

    const int tid = threadIdx.x, lane = tid & 31, warp = tid >> 5;
    const int r = lane >> 2, cc = lane & 3;
    const int row0 = warp * 16;
    const int trow0 = t0 + row0 + r, trow1 = trow0 + 8;

#define PREFETCH_KV(buf, s0_) do {                                            \
    unsigned* Kb_ = smem + (buf) * BUFW;                                      \
    unsigned* Vb_ = Kb_ + KW;                                                 \
    _Pragma("unroll")                                                         \
    for (int i_ = 0; i_ < 2; i_++) {                                          \
        int idx_ = tid + i_ * 256;                                            \
        int row_ = idx_ >> 3, ch_ = idx_ & 7;                                 \
        cpa16(Kb_ + row_*40 + ch_*4, K + (size_t)((s0_) + row_) * D_ + ch_*8);\
    }                                                                         \
    _Pragma("unroll")                                                         \
    for (int i_ = 0; i_ < 2; i_++) {                                          \
        int idx_ = tid + i_ * 256;                                            \
        int row_ = idx_ >> 3, ch_ = idx_ & 7;                                 \
        cpa16(Vb_ + row_*40 + ch_*4, V + (size_t)row_ * T_ + (s0_) + ch_*8);  \
    }                                                                         \
    asm volatile("cp.async.commit_group;" ::: "memory");                      \
} while (0)

#define PREFETCH_BD(s0_) do {                                                 \
    _Pragma("unroll")                                                         \
    for (int i_ = 0; i_ < 4; i_++) {                                          \
        int idx_ = lane + i_ * 32;                                            \
        int row_ = idx_ >> 3, c16_ = idx_ & 7;                                \
        cpa16(Ps + (row0 + row_) * 36 + c16_ * 4,                             \
              BD + (size_t)(t0 + row0 + row_) * T_ + (s0_) + c16_ * 8);       \
    }                                                                         \
    asm volatile("cp.async.commit_group;" ::: "memory");                      \
} while (0)

    unsigned aq[4][4];
    const float* rwbh = rwb + h * D_;
    const unsigned* Qu = (const unsigned*)Q;
    #pragma unroll
    for (int kc = 0; kc < 4; kc++) {
        int c0 = kc * 16 + 2 * cc;
        uint2 qw0 = *(const uint2*)(Qu + (size_t)trow0 * 32 + kc * 8 + 2 * cc);
        uint2 qw1 = *(const uint2*)(Qu + (size_t)trow1 * 32 + kc * 8 + 2 * cc);
        float2 f;
        __half2 a;
        f = __half22float2(*(__half2*)&qw0.x);
        a = __floats2half2_rn((f.x + rwbh[c0]) * SCL, (f.y + rwbh[c0+1]) * SCL);
        aq[kc][0] = *(unsigned*)&a;
        f = __half22float2(*(__half2*)&qw1.x);
        a = __floats2half2_rn((f.x + rwbh[c0]) * SCL, (f.y + rwbh[c0+1]) * SCL);
        aq[kc][1] = *(unsigned*)&a;
        f = __half22float2(*(__half2*)&qw0.y);
        a = __floats2half2_rn((f.x + rwbh[c0+8]) * SCL, (f.y + rwbh[c0+9]) * SCL);
        aq[kc][2] = *(unsigned*)&a;
        f = __half22float2(*(__half2*)&qw1.y);
        a = __floats2half2_rn((f.x + rwbh[c0+8]) * SCL, (f.y + rwbh[c0+9]) * SCL);
        aq[kc][3] = *(unsigned*)&a;
    }

    PREFETCH_KV(0, 0);
    PREFETCH_BD(0);

    float oacc[8][4] = {};
    float m0r = -1e30f, m1r = -1e30f, l0 = 0.f, l1 = 0.f;

    #pragma unroll 1
    for (int it = 0; it < T_ / 64; it++) {
        const int s0 = it * 64;
        const int cur = it & 1;
        asm volatile("cp.async.wait_group 1;" ::: "memory");   // KV(it)
        __syncthreads();

        PREFETCH_KV(cur ^ 1, (s0 + 64) & (T_ - 1));

        const unsigned* Kb = smem + cur * BUFW;
        const unsigned* Vb = Kb + KW;

        float pacc[8][4];
        #pragma unroll
        for (int nt = 0; nt < 8; nt++)
            #pragma unroll
            for (int j = 0; j < 4; j++) pacc[nt][j] = 0.f;
        #pragma unroll
        for (int kc = 0; kc < 4; kc++) {
            #pragma unroll
            for (int nt = 0; nt < 8; nt++) {
                int srow = nt * 8 + r;
                uint2 kb2 = *(const uint2*)(Kb + srow * 40 + kc * 8 + 2 * cc);
                unsigned bf[2] = { kb2.x, kb2.y };
                MMA16(pacc[nt], aq[kc], bf);
            }
        }

        asm volatile("cp.async.wait_group 1;" ::: "memory");   // BD(it)
        __syncwarp();

        const __half2* bd0 = (const __half2*)(Ps + (row0 + r) * 36);
        const __half2* bd1 = (const __half2*)(Ps + (row0 + r + 8) * 36);
        float pm0 = -1e30f, pm1 = -1e30f;
        const bool diag = (t0 + row0 + 1 <= s0 + 63) && (t0 + row0 + 16 >= s0);
        if (diag) {
            #pragma unroll
            for (int nt = 0; nt < 8; nt++) {
                int sb = s0 + nt * 8 + 2 * cc;
                float2 f0 = __half22float2(bd0[4 * nt + cc]);
                float2 f1 = __half22float2(bd1[4 * nt + cc]);
                pacc[nt][0] += (sb     == trow0 + 1) ? 0.f : f0.x;
                pacc[nt][1] += (sb + 1 == trow0 + 1) ? 0.f : f0.y;
                pacc[nt][2] += (sb     == trow1 + 1) ? 0.f : f1.x;
                pacc[nt][3] += (sb + 1 == trow1 + 1) ? 0.f : f1.y;
                pm0 = fmaxf(pm0, fmaxf(pacc[nt][0], pacc[nt][1]));
                pm1 = fmaxf(pm1, fmaxf(pacc[nt][2], pacc[nt][3]));
            }
        } else {
            #pragma unroll
            for (int nt = 0; nt < 8; nt++) {
                float2 f0 = __half22float2(bd0[4 * nt + cc]);
                float2 f1 = __half22float2(bd1[4 * nt + cc]);
                pacc[nt][0] += f0.x;
                pacc[nt][1] += f0.y;
                pacc[nt][2] += f1.x;
                pacc[nt][3] += f1.y;
                pm0 = fmaxf(pm0, fmaxf(pacc[nt][0], pacc[nt][1]));
                pm1 = fmaxf(pm1, fmaxf(pacc[nt][2], pacc[nt][3]));
            }
        }
        pm0 = fmaxf(pm0, __shfl_xor_sync(0xffffffffu, pm0, 1));
        pm0 = fmaxf(pm0, __shfl_xor_sync(0xffffffffu, pm0, 2));
        pm1 = fmaxf(pm1, __shfl_xor_sync(0xffffffffu, pm1, 1));
        pm1 = fmaxf(pm1, __shfl_xor_sync(0xffffffffu, pm1, 2));

        float mn0 = fmaxf(m0r, pm0), mn1 = fmaxf(m1r, pm1);
        float sf0 = ex2f(m0r - mn0), sf1 = ex2f(m1r - mn1);
        m0r = mn0; m1r = mn1;
        #pragma unroll
        for (int nt = 0; nt < 8; nt++) {
            oacc[nt][0] *= sf0; oacc[nt][1] *= sf0;
            oacc[nt][2] *= sf1; oacc[nt][3] *= sf1;
        }
        l0 *= sf0; l1 *= sf1;

        unsigned ph[8][2];
        float sum0 = 0.f, sum1 = 0.f;
        #pragma unroll
        for (int nt = 0; nt < 8; nt++) {
            float e0 = ex2f(pacc[nt][0] - mn0);
            float e1 = ex2f(pacc[nt][1] - mn0);
            float e2 = ex2f(pacc[nt][2] - mn1);
            float e3 = ex2f(pacc[nt][3] - mn1);
            sum0 += e0 + e1; sum1 += e2 + e3;
            __half2 p0 = __floats2half2_rn(e0, e1);
            __half2 p1 = __floats2half2_rn(e2, e3);
            ph[nt][0] = *(unsigned*)&p0;
            ph[nt][1] = *(unsigned*)&p1;
        }
        sum0 += __shfl_xor_sync(0xffffffffu, sum0, 1);
        sum0 += __shfl_xor_sync(0xffffffffu, sum0, 2);
        sum1 += __shfl_xor_sync(0xffffffffu, sum1, 1);
        sum1 += __shfl_xor_sync(0xffffffffu, sum1, 2);
        l0 += sum0; l1 += sum1;

        #pragma unroll
        for (int kc = 0; kc < 4; kc++) {
            unsigned af[4] = { ph[2*kc][0], ph[2*kc][1], ph[2*kc+1][0], ph[2*kc+1][1] };
            #pragma unroll
            for (int nt = 0; nt < 8; nt++) {
                int drow = nt * 8 + r;
                uint2 vb2 = *(const uint2*)(Vb + drow * 40 + kc * 8 + 2 * cc);
                unsigned bf[2] = { vb2.x, vb2.y };
                MMA16(oacc[nt], af, bf);
            }
        }
        __syncwarp();

        if (it < T_ / 64 - 1)
            PREFETCH_BD(s0 + 64);
    }
    asm volatile("cp.async.wait_group 0;" ::: "memory");

    float il0 = 1.f / l0, il1 = 1.f / l1;
    unsigned* ctxu = (unsigned*)g_ctx;
    #pragma unroll
    for (int nt = 0; nt < 8; nt++) {
        int u_l = h * 32 + nt * 4 + cc;
        int pu = permu(u_l);
        __half2 o0 = __floats2half2_rn(oacc[nt][0] * il0, oacc[nt][1] * il0);
        ctxu[((size_t)trow0 * B_ + b) * (E_/2) + pu] = *(unsigned*)&o0;
        __half2 o1 = __floats2half2_rn(oacc[nt][2] * il1, oacc[nt][3] * il1);
        ctxu[((size_t)trow1 * B_ + b) * (E_/2) + pu] = *(unsigned*)&o1;
    }
#undef PREFETCH_KV
#undef PREFETCH_BD
}

// ============================================================
// out projection (fp16 GEMM, fp32 output)
// ============================================================
__global__ __launch_bounds__(256) void k_out(const float* __restrict__ bias,
                                             float* __restrict__ out) {
    extern __shared__ unsigned dsm[];
    float acc[4][4][4] = {};
    const int m0 = blockIdx.y * 128, n0 = blockIdx.x * 128;
    gemm_nt_hp<E_>(g_ctx, E_, g_cwout, E_, m0, n0, acc, dsm);
    const int lane = threadIdx.x & 31, warp = threadIdx.x >> 5;
    const int wm = (warp >> 2) * 64, wn = (warp & 3) * 32;
    #pragma unroll
    for (int mi = 0; mi < 4; mi++)
        #pragma unroll
        for (int ni = 0; ni < 4; ni++)
            #pragma unroll
            for (int rg = 0; rg < 4; rg++) {
                int row = EPI_ROW(m0, wm, mi, rg);
                int col = EPI_COL(n0, wn, ni, rg);
                out[(size_t)row * E_ + col] = acc[mi][ni][rg] + bias[col];
            }
}

// ============================================================
extern "C" void kernel_launch(void* const* d_in, const int* in_sizes, int n_in,
                              void* d_out, int out_size) {
    const float* input = (const float*)d_in[0];
    const float* pos   = (const float*)d_in[1];
    const float* w_in  = (const float*)d_in[2];
    const float* w_out = (const float*)d_in[3];
    const float* w_pos = (const float*)d_in[4];
    const float* b_in  = (const float*)d_in[5];
    const float* b_out = (const float*)d_in[6];
    const float* b_pos = (const float*)d_in[7];
    const float* rwb   = (const float*)d_in[8];
    const float* rrb   = (const float*)d_in[9];
    float* out = (float*)d_out;

    const int gemm_smem  = 2 * 2 * 128 * 24 * 4;                 // 49152
    const int flash_smem = (2 * (64*40 + 64*40) + 128*36) * 4;   // 59392
    cudaFuncSetAttribute(k_qkv,  cudaFuncAttributeMaxDynamicSharedMemorySize, gemm_smem);
    cudaFuncSetAttribute(k_pos,  cudaFuncAttributeMaxDynamicSharedMemorySize, gemm_smem);
    cudaFuncSetAttribute(k_bd,   cudaFuncAttributeMaxDynamicSharedMemorySize, gemm_smem);
    cudaFuncSetAttribute(k_out,  cudaFuncAttributeMaxDynamicSharedMemorySize, gemm_smem);
    cudaFuncSetAttribute(k_flash, cudaFuncAttributeMaxDynamicSharedMemorySize, flash_smem);

    k_cvt_all<<<(N4_TOT + 255)/256, 256>>>(input, pos, w_in, w_out, w_pos);

    k_qkv  <<<dim3(E3_/128, (T_*B_)/128), 256, gemm_smem>>>(b_in);
    k_pos  <<<dim3(E_/128,  T_/128),      256, gemm_smem>>>(b_pos, rrb);
    k_bd   <<<dim3(T_/128, T_/128, B_*H_), 256, gemm_smem>>>();
    k_flash<<<dim3(T_/128, B_*H_), 256, flash_smem>>>(rwb);
    k_out  <<<dim3(E_/128, (T_*B_)/128), 256, gemm_smem>>>(b_out, out);
}

// round 13
// speedup vs baseline: 1.4909x; 1.0917x over previous
#include <cuda_runtime.h>
#include <cuda_fp16.h>
#include <math.h>

#define T_  2048
#define B_  2
#define E_  512
#define H_  8
#define D_  64
#define E3_ 1536

// scale * log2(e): softmax in base-2 domain
#define SCL 0.1803368801111204f

// uint-pair permute within each 8-uint chunk: o -> ((o&3)<<1)|(o>>2)
__device__ __forceinline__ int permu(int u) {
    return (u & ~7) | (((u & 3) << 1) | ((u >> 2) & 1));
}

// ---- scratch (__device__ globals: allocation-guard-legal) ----
__device__ __half g_q[B_*H_*T_*D_];           // [B,H,T,D] fp16, d-permuted
__device__ __half g_k[B_*H_*T_*D_];           // [B,H,T,D] fp16, d-permuted
__device__ __half g_v[B_*H_*D_*T_];           // [B,H,D,T] fp16, t-permuted
__device__ __half g_r[H_*T_*D_];              // [H,R,D]   fp16, d-permuted
__device__ float  g_br[H_*T_];                // rrb_h · r[h,c]
__device__ __half g_BDs[(size_t)B_*H_*T_*T_]; // BD, PRE-SHIFTED + scaled, fp16
__device__ __half g_ctx[T_*B_*E_];            // [T,B,E]   fp16, E-permuted
// fp16 copies of harness inputs, K-permuted (raw cp.async GEMM operands)
__device__ __half g_ci[T_*B_*E_];
__device__ __half g_cpos[T_*E_];
__device__ __half g_cwin[E3_*E_];
__device__ __half g_cwout[E_*E_];
__device__ __half g_cwpos[E_*E_];

__device__ __forceinline__ float ex2f(float x) {
    float y;
    asm("ex2.approx.ftz.f32 %0, %1;" : "=f"(y) : "f"(x));
    return y;
}
__device__ __forceinline__ void cpa16(void* d, const void* s) {
    unsigned a = (unsigned)__cvta_generic_to_shared(d);
    asm volatile("cp.async.cg.shared.global [%0], [%1], 16;" :: "r"(a), "l"(s));
}

// fp16 mma, fp32 accum
#define MMA16(d, a, b) \
  asm volatile("mma.sync.aligned.m16n8k16.row.col.f32.f16.f16.f32 " \
      "{%0,%1,%2,%3},{%4,%5,%6,%7},{%8,%9},{%0,%1,%2,%3};" \
      : "+f"((d)[0]), "+f"((d)[1]), "+f"((d)[2]), "+f"((d)[3]) \
      : "r"((a)[0]), "r"((a)[1]), "r"((a)[2]), "r"((a)[3]), \
        "r"((b)[0]), "r"((b)[1]))

// ============================================================
// One-shot fp32 -> fp16 conversion of all inputs, K-PERMUTED
// ============================================================
#define N4_CI   (T_*B_*E_/4)
#define N4_CPOS (T_*E_/4)
#define N4_CWIN (E3_*E_/4)
#define N4_CW   (E_*E_/4)
#define N4_TOT  (N4_CI + N4_CPOS + N4_CWIN + 2*N4_CW)

__global__ __launch_bounds__(256) void k_cvt_all(const float* __restrict__ s0,
                                                 const float* __restrict__ s1,
                                                 const float* __restrict__ s2,
                                                 const float* __restrict__ s3,
                                                 const float* __restrict__ s4) {
    int i = blockIdx.x * 256 + threadIdx.x;
    if (i >= N4_TOT) return;
    const float* src; __half* dst; int off = i;
    if (i < N4_CI)                               { src = s0; dst = g_ci; }
    else if ((off -= N4_CI)   < N4_CPOS)         { src = s1; dst = g_cpos; }
    else if ((off -= N4_CPOS) < N4_CWIN)         { src = s2; dst = g_cwin; }
    else if ((off -= N4_CWIN) < N4_CW)           { src = s3; dst = g_cwout; }
    else { off -= N4_CW;                           src = s4; dst = g_cwpos; }
    float4 v = ((const float4*)src)[off];
    __half2 h0 = __floats2half2_rn(v.x, v.y);
    __half2 h1 = __floats2half2_rn(v.z, v.w);
    unsigned* du = (unsigned*)dst;
    du[permu(2 * off)]     = *(unsigned*)&h0;
    du[permu(2 * off + 1)] = *(unsigned*)&h1;
}

// ============================================================
// fp16 double-buffered cp.async NT mainloop: C[128,128] = A·Bt^T.
// Operands K-PERMUTED -> fragments uint2 LDS.64 (pitch 24, conflict-free).
// ============================================================
template<int KTOT>
__device__ __forceinline__ void gemm_nt_hp(const __half* __restrict__ A, int lda,
                                           const __half* __restrict__ Bt, int ldb,
                                           int m0, int n0, float acc[4][4][4],
                                           unsigned* sm) {
    const int tid = threadIdx.x;
    const int lane = tid & 31, warp = tid >> 5;
    const int wm = (warp >> 2) * 64, wn = (warp & 3) * 32;

#define HSTAGE(buf_, k0_) do {                                                \
    unsigned* As_ = sm + (buf_) * 6144;                                       \
    unsigned* Bs_ = As_ + 3072;                                               \
    _Pragma("unroll")                                                         \
    for (int i_ = 0; i_ < 2; i_++) {                                          \
        int idx_ = tid + i_ * 256;                                            \
        int row_ = idx_ >> 2, c8_ = (idx_ & 3) * 8;                           \
        cpa16(As_ + row_*24 + (idx_ & 3)*4, A  + (size_t)(m0 + row_) * lda + (k0_) + c8_); \
        cpa16(Bs_ + row_*24 + (idx_ & 3)*4, Bt + (size_t)(n0 + row_) * ldb + (k0_) + c8_); \
    }                                                                         \
    asm volatile("cp.async.commit_group;" ::: "memory");                      \
} while (0)

    HSTAGE(0, 0);
    #pragma unroll 1
    for (int k0 = 0; k0 < KTOT; k0 += 32) {
        const int buf = (k0 >> 5) & 1;
        const bool more = (k0 + 32 < KTOT);
        if (more) HSTAGE(buf ^ 1, k0 + 32);
        if (more) asm volatile("cp.async.wait_group 1;" ::: "memory");
        else      asm volatile("cp.async.wait_group 0;" ::: "memory");
        __syncthreads();

        const unsigned* As = sm + buf * 6144;
        const unsigned* Bs = As + 3072;
        #pragma unroll
        for (int ks = 0; ks < 2; ks++) {
            const int r = lane >> 2, cb = ks * 8 + 2 * (lane & 3);
            unsigned af[4][4], bf[4][2];
            #pragma unroll
            for (int mi = 0; mi < 4; mi++) {
                int rr = wm + mi * 16 + r;
                uint2 lo = *(const uint2*)(As + rr * 24 + cb);
                uint2 hi = *(const uint2*)(As + (rr + 8) * 24 + cb);
                af[mi][0] = lo.x; af[mi][1] = hi.x;
                af[mi][2] = lo.y; af[mi][3] = hi.y;
            }
            #pragma unroll
            for (int ni = 0; ni < 4; ni++) {
                int rb = wn + ni * 8 + r;
                uint2 u = *(const uint2*)(Bs + rb * 24 + cb);
                bf[ni][0] = u.x; bf[ni][1] = u.y;
            }
            #pragma unroll
            for (int mi = 0; mi < 4; mi++)
                #pragma unroll
                for (int ni = 0; ni < 4; ni++)
                    MMA16(acc[mi][ni], af[mi], bf[ni]);
        }
        __syncthreads();
    }
#undef HSTAGE
}

#define EPI_ROW(m0, wm, mi, rg) ((m0) + (wm) + (mi)*16 + (lane >> 2) + (((rg) & 2) << 2))
#define EPI_COL(n0, wn, ni, rg) ((n0) + (wn) + (ni)*8 + ((lane & 3) << 1) + ((rg) & 1))

// ============================================================
// QKV projection -> q/k [B,H,T,D] d-permuted, v [B,H,D,T] t-permuted
// ============================================================
__global__ __launch_bounds__(256) void k_qkv(const float* __restrict__ bias) {
    extern __shared__ unsigned dsm[];
    float acc[4][4][4] = {};
    const int m0 = blockIdx.y * 128, n0 = blockIdx.x * 128;
    gemm_nt_hp<E_>(g_ci, E_, g_cwin, E_, m0, n0, acc, dsm);
    const int lane = threadIdx.x & 31, warp = threadIdx.x >> 5;
    const int wm = (warp >> 2) * 64, wn = (warp & 3) * 32;
    #pragma unroll
    for (int mi = 0; mi < 4; mi++)
        #pragma unroll
        for (int ni = 0; ni < 4; ni++)
            #pragma unroll
            for (int rg = 0; rg < 4; rg++) {
                int row = EPI_ROW(m0, wm, mi, rg);
                int col = EPI_COL(n0, wn, ni, rg);
                float v = acc[mi][ni][rg] + bias[col];
                int t = row / B_, b = row % B_;
                int sec = col >> 9, h = (col >> 6) & 7, d = col & 63;
                if (sec == 2) {
                    int w = t >> 1;
                    int tp = (permu(w) << 1) | (t & 1);
                    g_v[(((size_t)(b * H_ + h) * D_) + d) * T_ + tp] = __float2half_rn(v);
                } else {
                    int pd = (permu(d >> 1) << 1) | (d & 1);
                    __half* dst = (sec == 0) ? g_q : g_k;
                    dst[(((size_t)(b * H_ + h) * T_) + t) * D_ + pd] = __float2half_rn(v);
                }
            }
}

// ============================================================
// pos projection -> g_r[H,R,D] d-permuted + in-block br
// ============================================================
__global__ __launch_bounds__(256) void k_pos(const float* __restrict__ bias,
                                             const float* __restrict__ rrb) {
    extern __shared__ unsigned dsm[];
    float acc[4][4][4] = {};
    const int m0 = blockIdx.y * 128, n0 = blockIdx.x * 128;
    gemm_nt_hp<E_>(g_cpos, E_, g_cwpos, E_, m0, n0, acc, dsm);
    const int tid = threadIdx.x, lane = tid & 31, warp = tid >> 5;
    const int wm = (warp >> 2) * 64, wn = (warp & 3) * 32;
    __half* Hs = (__half*)dsm;                 // [128][136] logical tile
    #pragma unroll
    for (int mi = 0; mi < 4; mi++)
        #pragma unroll
        for (int ni = 0; ni < 4; ni++)
            #pragma unroll
            for (int rg = 0; rg < 4; rg++) {
                int rr = EPI_ROW(m0, wm, mi, rg);
                int col = EPI_COL(n0, wn, ni, rg);
                int h = col >> 6, d = col & 63;
                __half hv = __float2half_rn(acc[mi][ni][rg] + bias[col]);
                int pd = (permu(d >> 1) << 1) | (d & 1);
                g_r[((size_t)h * T_ + rr) * D_ + pd] = hv;
                Hs[(rr - m0) * 136 + (col - n0)] = hv;
            }
    __syncthreads();

    int lr = tid & 127, hl = tid >> 7;
    int h = (n0 >> 6) + hl;
    const __half2* rowp = (const __half2*)(Hs + lr * 136 + hl * 64);
    const float* bb = rrb + h * D_;
    float s = 0.f;
    #pragma unroll
    for (int i = 0; i < 32; i++) {
        float2 a = __half22float2(rowp[i]);
        s += a.x * bb[2*i] + a.y * bb[2*i + 1];
    }
    g_br[h * T_ + m0 + lr] = s;
}

// ============================================================
// BD: raw[t,c] = q[t]·r[c] + br[c] -> PRE-SHIFTED fp16.
// KEY IDENTITY: both shift segments map to the SAME contiguous range:
//   out[t*(T+1) + n0 - (T-1) + k] = src[k],  k in [0,128)
// (the diagonal slot t*T+t+1 is exactly the one index never covered).
// Only exception: t==0 drops k < T-1-n0 (would be negative addresses).
// Single-stage K=64 GEMM (one cp.async group, pitch 40, 3 syncs total).
// ============================================================
__global__ __launch_bounds__(256) void k_bd() {
    extern __shared__ unsigned dsm[];
    const int bh = blockIdx.z, h = bh & 7;
    const int m0 = blockIdx.y * 128, n0 = blockIdx.x * 128;
    const __half* A  = g_q + (size_t)bh * T_ * D_;
    const __half* Bt = g_r + (size_t)h  * T_ * D_;

    const int tid = threadIdx.x, lane = tid & 31, warp = tid >> 5;
    const int wm = (warp >> 2) * 64, wn = (warp & 3) * 32;

    // ---- single-stage load: full K=64 (128 bytes/row = 8 chunks) ----
    unsigned* As = dsm;            // [128][40] uints (32 data + pad)
    unsigned* Bs = dsm + 5120;
    #pragma unroll
    for (int i = 0; i < 4; i++) {
        int idx = tid + i * 256;
        int row = idx >> 3, ch = idx & 7;
        cpa16(As + row*40 + ch*4, A  + (size_t)(m0 + row) * D_ + ch*8);
        cpa16(Bs + row*40 + ch*4, Bt + (size_t)(n0 + row) * D_ + ch*8);
    }
    asm volatile("cp.async.commit_group;" ::: "memory");
    asm volatile("cp.async.wait_group 0;" ::: "memory");
    __syncthreads();

    float acc[4][4][4] = {};
    #pragma unroll
    for (int ks = 0; ks < 4; ks++) {
        const int r = lane >> 2, cb = ks * 8 + 2 * (lane & 3);
        unsigned af[4][4], bf[4][2];
        #pragma unroll
        for (int mi = 0; mi < 4; mi++) {
            int rr = wm + mi * 16 + r;
            uint2 lo = *(const uint2*)(As + rr * 40 + cb);
            uint2 hi = *(const uint2*)(As + (rr + 8) * 40 + cb);
            af[mi][0] = lo.x; af[mi][1] = hi.x;
            af[mi][2] = lo.y; af[mi][3] = hi.y;
        }
        #pragma unroll
        for (int ni = 0; ni < 4; ni++) {
            int rb = wn + ni * 8 + r;
            uint2 u = *(const uint2*)(Bs + rb * 40 + cb);
            bf[ni][0] = u.x; bf[ni][1] = u.y;
        }
        #pragma unroll
        for (int mi = 0; mi < 4; mi++)
            #pragma unroll
            for (int ni = 0; ni < 4; ni++)
                MMA16(acc[mi][ni], af[mi], bf[ni]);
    }
    __syncthreads();

    // ---- stage tile to smem as half2 (br added, scaled) ----
    __half* Hs = (__half*)dsm;                 // [128][136] halfs
    const float2* brv = (const float2*)(g_br + h * T_ + n0);
    #pragma unroll
    for (int mi = 0; mi < 4; mi++)
        #pragma unroll
        for (int ni = 0; ni < 4; ni++) {
            int lc = wn + ni * 8 + 2 * (lane & 3);
            float2 brx = brv[lc >> 1];
            #pragma unroll
            for (int rgp = 0; rgp < 2; rgp++) {
                int lt = wm + mi * 16 + (lane >> 2) + rgp * 8;
                __half2 v = __floats2half2_rn(
                    (acc[mi][ni][2*rgp]     + brx.x) * SCL,
                    (acc[mi][ni][2*rgp + 1] + brx.y) * SCL);
                *(__half2*)(Hs + lt * 136 + lc) = v;
            }
        }
    __syncthreads();

    // ---- contiguous shifted row copies ----
    __half* out = g_BDs + (size_t)bh * T_ * T_;
    const int tb = m0 + warp * 16;
    #pragma unroll 1
    for (int i = 0; i < 16; i++) {
        const int t = tb + i;
        const long base = (long)t * (T_ + 1) + n0 - (T_ - 1);
        const __half* src = Hs + (warp * 16 + i) * 136;
        if (t == 0) {
            int cut = T_ - 1 - n0;                    // >= 127
            if (cut < 128 && lane < 128 - cut)
                out[base + cut + lane] = src[cut + lane];
        } else if (t & 1) {                           // base even
            *(__half2*)(out + base + 2*lane)      = *(const __half2*)(src + 2*lane);
            *(__half2*)(out + base + 2*lane + 64) = *(const __half2*)(src + 2*lane + 64);
        } else {                                      // base odd
            if (lane == 0) { out[base] = src[0]; out[base + 127] = src[127]; }
            int k = 1 + 2 * lane;
            __half2 v0; v0.x = src[k]; v0.y = src[k + 1];
            *(__half2*)(out + base + k) = v0;
            if (lane < 31) {
                int k2 = k + 64;
                __half2 v1; v1.x = src[k2]; v1.y = src[k2 + 1];
                *(__half2*)(out + base + k2) = v1;
            }
        }
    }
}

// ============================================================
// Flash attention (unchanged from round 12)
// ============================================================
__global__ __launch_bounds__(256, 2) void k_flash(const float* __restrict__ rwb) {
    extern __shared__ unsigned smem[];
    const int KW = 64 * 40;
    const int VW = 64 * 40;
    const int BUFW = KW + VW;
    unsigned* Ps = smem + 2 * BUFW;         // BD: [128][36] words

    const int bh = blockIdx.y, h = bh & 7, b = bh >> 3;
    const int t0 = blockIdx.x * 128;
    const __half* Q  = g_q + (size_t)bh * T_ * D_;
    const __half* K  = g_k + (size_t)bh * T_ * D_;
    const __half* V  = g_v + (size_t)bh * D_ * T_;
    const __half* BD = g_BDs + (size_t)bh * T_ * T_;

    const int tid = threadIdx.x, lane = tid & 31, warp = tid >> 5;
    const int r = lane >> 2, cc = lane & 3;
    const int row0 = warp * 16;
    const int trow0 = t0 + row0 + r, trow1 = trow0 + 8;

#define PREFETCH_KV(buf, s0_) do {                                            \
    unsigned* Kb_ = smem + (buf) * BUFW;                                      \
    unsigned* Vb_ = Kb_ + KW;                                                 \
    _Pragma("unroll")                                                         \
    for (int i_ = 0; i_ < 2; i_++) {                                          \
        int idx_ = tid + i_ * 256;                                            \
        int row_ = idx_ >> 3, ch_ = idx_ & 7;                                 \
        cpa16(Kb_ + row_*40 + ch_*4, K + (size_t)((s0_) + row_) * D_ + ch_*8);\
    }                                                                         \
    _Pragma("unroll")                                                         \
    for (int i_ = 0; i_ < 2; i_++) {                                          \
        int idx_ = tid + i_ * 256;                                            \
        int row_ = idx_ >> 3, ch_ = idx_ & 7;                                 \
        cpa16(Vb_ + row_*40 + ch_*4, V + (size_t)row_ * T_ + (s0_) + ch_*8);  \
    }                                                                         \
    asm volatile("cp.async.commit_group;" ::: "memory");                      \
} while (0)

#define PREFETCH_BD(s0_) do {                                                 \
    _Pragma("unroll")                                                         \
    for (int i_ = 0; i_ < 4; i_++) {                                          \
        int idx_ = lane + i_ * 32;                                            \
        int row_ = idx_ >> 3, c16_ = idx_ & 7;                                \
        cpa16(Ps + (row0 + row_) * 36 + c16_ * 4,                             \
              BD + (size_t)(t0 + row0 + row_) * T_ + (s0_) + c16_ * 8);       \
    }                                                                         \
    asm volatile("cp.async.commit_group;" ::: "memory");                      \
} while (0)

    unsigned aq[4][4];
    const float* rwbh = rwb + h * D_;
    const unsigned* Qu = (const unsigned*)Q;
    #pragma unroll
    for (int kc = 0; kc < 4; kc++) {
        int c0 = kc * 16 + 2 * cc;
        uint2 qw0 = *(const uint2*)(Qu + (size_t)trow0 * 32 + kc * 8 + 2 * cc);
        uint2 qw1 = *(const uint2*)(Qu + (size_t)trow1 * 32 + kc * 8 + 2 * cc);
        float2 f;
        __half2 a;
        f = __half22float2(*(__half2*)&qw0.x);
        a = __floats2half2_rn((f.x + rwbh[c0]) * SCL, (f.y + rwbh[c0+1]) * SCL);
        aq[kc][0] = *(unsigned*)&a;
        f = __half22float2(*(__half2*)&qw1.x);
        a = __floats2half2_rn((f.x + rwbh[c0]) * SCL, (f.y + rwbh[c0+1]) * SCL);
        aq[kc][1] = *(unsigned*)&a;
        f = __half22float2(*(__half2*)&qw0.y);
        a = __floats2half2_rn((f.x + rwbh[c0+8]) * SCL, (f.y + rwbh[c0+9]) * SCL);
        aq[kc][2] = *(unsigned*)&a;
        f = __half22float2(*(__half2*)&qw1.y);
        a = __floats2half2_rn((f.x + rwbh[c0+8]) * SCL, (f.y + rwbh[c0+9]) * SCL);
        aq[kc][3] = *(unsigned*)&a;
    }

    PREFETCH_KV(0, 0);
    PREFETCH_BD(0);

    float oacc[8][4] = {};
    float m0r = -1e30f, m1r = -1e30f, l0 = 0.f, l1 = 0.f;

    #pragma unroll 1
    for (int it = 0; it < T_ / 64; it++) {
        const int s0 = it * 64;
        const int cur = it & 1;
        asm volatile("cp.async.wait_group 1;" ::: "memory");   // KV(it)
        __syncthreads();

        PREFETCH_KV(cur ^ 1, (s0 + 64) & (T_ - 1));

        const unsigned* Kb = smem + cur * BUFW;
        const unsigned* Vb = Kb + KW;

        float pacc[8][4];
        #pragma unroll
        for (int nt = 0; nt < 8; nt++)
            #pragma unroll
            for (int j = 0; j < 4; j++) pacc[nt][j] = 0.f;
        #pragma unroll
        for (int kc = 0; kc < 4; kc++) {
            #pragma unroll
            for (int nt = 0; nt < 8; nt++) {
                int srow = nt * 8 + r;
                uint2 kb2 = *(const uint2*)(Kb + srow * 40 + kc * 8 + 2 * cc);
                unsigned bf[2] = { kb2.x, kb2.y };
                MMA16(pacc[nt], aq[kc], bf);
            }
        }

        asm volatile("cp.async.wait_group 1;" ::: "memory");   // BD(it)
        __syncwarp();

        const __half2* bd0 = (const __half2*)(Ps + (row0 + r) * 36);
        const __half2* bd1 = (const __half2*)(Ps + (row0 + r + 8) * 36);
        float pm0 = -1e30f, pm1 = -1e30f;
        const bool diag = (t0 + row0 + 1 <= s0 + 63) && (t0 + row0 + 16 >= s0);
        if (diag) {
            #pragma unroll
            for (int nt = 0; nt < 8; nt++) {
                int sb = s0 + nt * 8 + 2 * cc;
                float2 f0 = __half22float2(bd0[4 * nt + cc]);
                float2 f1 = __half22float2(bd1[4 * nt + cc]);
                pacc[nt][0] += (sb     == trow0 + 1) ? 0.f : f0.x;
                pacc[nt][1] += (sb + 1 == trow0 + 1) ? 0.f : f0.y;
                pacc[nt][2] += (sb     == trow1 + 1) ? 0.f : f1.x;
                pacc[nt][3] += (sb + 1 == trow1 + 1) ? 0.f : f1.y;
                pm0 = fmaxf(pm0, fmaxf(pacc[nt][0], pacc[nt][1]));
                pm1 = fmaxf(pm1, fmaxf(pacc[nt][2], pacc[nt][3]));
            }
        } else {
            #pragma unroll
            for (int nt = 0; nt < 8; nt++) {
                float2 f0 = __half22float2(bd0[4 * nt + cc]);
                float2 f1 = __half22float2(bd1[4 * nt + cc]);
                pacc[nt][0] += f0.x;
                pacc[nt][1] += f0.y;
                pacc[nt][2] += f1.x;
                pacc[nt][3] += f1.y;
                pm0 = fmaxf(pm0, fmaxf(pacc[nt][0], pacc[nt][1]));
                pm1 = fmaxf(pm1, fmaxf(pacc[nt][2], pacc[nt][3]));
            }
        }
        pm0 = fmaxf(pm0, __shfl_xor_sync(0xffffffffu, pm0, 1));
        pm0 = fmaxf(pm0, __shfl_xor_sync(0xffffffffu, pm0, 2));
        pm1 = fmaxf(pm1, __shfl_xor_sync(0xffffffffu, pm1, 1));
        pm1 = fmaxf(pm1, __shfl_xor_sync(0xffffffffu, pm1, 2));

        float mn0 = fmaxf(m0r, pm0), mn1 = fmaxf(m1r, pm1);
        float sf0 = ex2f(m0r - mn0), sf1 = ex2f(m1r - mn1);
        m0r = mn0; m1r = mn1;
        #pragma unroll
        for (int nt = 0; nt < 8; nt++) {
            oacc[nt][0] *= sf0; oacc[nt][1] *= sf0;
            oacc[nt][2] *= sf1; oacc[nt][3] *= sf1;
        }
        l0 *= sf0; l1 *= sf1;

        unsigned ph[8][2];
        float sum0 = 0.f, sum1 = 0.f;
        #pragma unroll
        for (int nt = 0; nt < 8; nt++) {
            float e0 = ex2f(pacc[nt][0] - mn0);
            float e1 = ex2f(pacc[nt][1] - mn0);
            float e2 = ex2f(pacc[nt][2] - mn1);
            float e3 = ex2f(pacc[nt][3] - mn1);
            sum0 += e0 + e1; sum1 += e2 + e3;
            __half2 p0 = __floats2half2_rn(e0, e1);
            __half2 p1 = __floats2half2_rn(e2, e3);
            ph[nt][0] = *(unsigned*)&p0;
            ph[nt][1] = *(unsigned*)&p1;
        }
        sum0 += __shfl_xor_sync(0xffffffffu, sum0, 1);
        sum0 += __shfl_xor_sync(0xffffffffu, sum0, 2);
        sum1 += __shfl_xor_sync(0xffffffffu, sum1, 1);
        sum1 += __shfl_xor_sync(0xffffffffu, sum1, 2);
        l0 += sum0; l1 += sum1;

        #pragma unroll
        for (int kc = 0; kc < 4; kc++) {
            unsigned af[4] = { ph[2*kc][0], ph[2*kc][1], ph[2*kc+1][0], ph[2*kc+1][1] };
            #pragma unroll
            for (int nt = 0; nt < 8; nt++) {
                int drow = nt * 8 + r;
                uint2 vb2 = *(const uint2*)(Vb + drow * 40 + kc * 8 + 2 * cc);
                unsigned bf[2] = { vb2.x, vb2.y };
                MMA16(oacc[nt], af, bf);
            }
        }
        __syncwarp();

        if (it < T_ / 64 - 1)
            PREFETCH_BD(s0 + 64);
    }
    asm volatile("cp.async.wait_group 0;" ::: "memory");

    float il0 = 1.f / l0, il1 = 1.f / l1;
    unsigned* ctxu = (unsigned*)g_ctx;
    #pragma unroll
    for (int nt = 0; nt < 8; nt++) {
        int u_l = h * 32 + nt * 4 + cc;
        int pu = permu(u_l);
        __half2 o0 = __floats2half2_rn(oacc[nt][0] * il0, oacc[nt][1] * il0);
        ctxu[((size_t)trow0 * B_ + b) * (E_/2) + pu] = *(unsigned*)&o0;
        __half2 o1 = __floats2half2_rn(oacc[nt][2] * il1, oacc[nt][3] * il1);
        ctxu[((size_t)trow1 * B_ + b) * (E_/2) + pu] = *(unsigned*)&o1;
    }
#undef PREFETCH_KV
#undef PREFETCH_BD
}

// ============================================================
// out projection (fp16 GEMM, fp32 output)
// ============================================================
__global__ __launch_bounds__(256) void k_out(const float* __restrict__ bias,
                                             float* __restrict__ out) {
    extern __shared__ unsigned dsm[];
    float acc[4][4][4] = {};
    const int m0 = blockIdx.y * 128, n0 = blockIdx.x * 128;
    gemm_nt_hp<E_>(g_ctx, E_, g_cwout, E_, m0, n0, acc, dsm);
    const int lane = threadIdx.x & 31, warp = threadIdx.x >> 5;
    const int wm = (warp >> 2) * 64, wn = (warp & 3) * 32;
    #pragma unroll
    for (int mi = 0; mi < 4; mi++)
        #pragma unroll
        for (int ni = 0; ni < 4; ni++)
            #pragma unroll
            for (int rg = 0; rg < 4; rg++) {
                int row = EPI_ROW(m0, wm, mi, rg);
                int col = EPI_COL(n0, wn, ni, rg);
                out[(size_t)row * E_ + col] = acc[mi][ni][rg] + bias[col];
            }
}

// ============================================================
extern "C" void kernel_launch(void* const* d_in, const int* in_sizes, int n_in,
                              void* d_out, int out_size) {
    const float* input = (const float*)d_in[0];
    const float* pos   = (const float*)d_in[1];
    const float* w_in  = (const float*)d_in[2];
    const float* w_out = (const float*)d_in[3];
    const float* w_pos = (const float*)d_in[4];
    const float* b_in  = (const float*)d_in[5];
    const float* b_out = (const float*)d_in[6];
    const float* b_pos = (const float*)d_in[7];
    const float* rwb   = (const float*)d_in[8];
    const float* rrb   = (const float*)d_in[9];
    float* out = (float*)d_out;

    const int gemm_smem  = 2 * 2 * 128 * 24 * 4;                 // 49152
    const int bd_smem    = 2 * 128 * 40 * 4;                     // 40960
    const int flash_smem = (2 * (64*40 + 64*40) + 128*36) * 4;   // 59392
    cudaFuncSetAttribute(k_qkv,  cudaFuncAttributeMaxDynamicSharedMemorySize, gemm_smem);
    cudaFuncSetAttribute(k_pos,  cudaFuncAttributeMaxDynamicSharedMemorySize, gemm_smem);
    cudaFuncSetAttribute(k_bd,   cudaFuncAttributeMaxDynamicSharedMemorySize, bd_smem);
    cudaFuncSetAttribute(k_out,  cudaFuncAttributeMaxDynamicSharedMemorySize, gemm_smem);
    cudaFuncSetAttribute(k_flash, cudaFuncAttributeMaxDynamicSharedMemorySize, flash_smem);

    k_cvt_all<<<(N4_TOT + 255)/256, 256>>>(input, pos, w_in, w_out, w_pos);

    k_qkv  <<<dim3(E3_/128, (T_*B_)/128), 256, gemm_smem>>>(b_in);
    k_pos  <<<dim3(E_/128,  T_/128),      256, gemm_smem>>>(b_pos, rrb);
    k_bd   <<<dim3(T_/128, T_/128, B_*H_), 256, bd_smem>>>();
    k_flash<<<dim3(T_/128, B_*H_), 256, flash_smem>>>(rwb);
    k_out  <<<dim3(E_/128, (T_*B_)/128), 256, gemm_smem>>>(b_out, out);
}

// round 14
// speedup vs baseline: 1.5403x; 1.0331x over previous
#include <cuda_runtime.h>
#include <cuda_fp16.h>
#include <math.h>

#define T_  2048
#define B_  2
#define E_  512
#define H_  8
#define D_  64
#define E3_ 1536

// scale * log2(e): softmax in base-2 domain
#define SCL 0.1803368801111204f

// uint-pair permute within each 8-uint chunk: o -> ((o&3)<<1)|(o>>2)
__device__ __forceinline__ int permu(int u) {
    return (u & ~7) | (((u & 3) << 1) | ((u >> 2) & 1));
}

// ---- scratch (__device__ globals: allocation-guard-legal) ----
__device__ __half g_q[B_*H_*T_*D_];           // [B,H,T,D] fp16, d-permuted
__device__ __half g_k[B_*H_*T_*D_];           // [B,H,T,D] fp16, d-permuted
__device__ __half g_v[B_*H_*D_*T_];           // [B,H,D,T] fp16, t-permuted
__device__ __half g_r[H_*T_*D_];              // [H,R,D]   fp16, d-permuted
__device__ float  g_br[H_*T_];                // rrb_h · r[h,c]
__device__ __half g_BDs[(size_t)B_*H_*T_*T_]; // BD, PRE-SHIFTED + scaled, fp16
__device__ __half g_ctx[T_*B_*E_];            // [T,B,E]   fp16, E-permuted
// fp16 copies of harness inputs, K-permuted (raw cp.async GEMM operands)
__device__ __half g_ci[T_*B_*E_];
__device__ __half g_cpos[T_*E_];
__device__ __half g_cwin[E3_*E_];
__device__ __half g_cwout[E_*E_];
__device__ __half g_cwpos[E_*E_];

__device__ __forceinline__ float ex2f(float x) {
    float y;
    asm("ex2.approx.ftz.f32 %0, %1;" : "=f"(y) : "f"(x));
    return y;
}
__device__ __forceinline__ void cpa16(void* d, const void* s) {
    unsigned a = (unsigned)__cvta_generic_to_shared(d);
    asm volatile("cp.async.cg.shared.global [%0], [%1], 16;" :: "r"(a), "l"(s));
}

// fp16 mma, fp32 accum
#define MMA16(d, a, b) \
  asm volatile("mma.sync.aligned.m16n8k16.row.col.f32.f16.f16.f32 " \
      "{%0,%1,%2,%3},{%4,%5,%6,%7},{%8,%9},{%0,%1,%2,%3};" \
      : "+f"((d)[0]), "+f"((d)[1]), "+f"((d)[2]), "+f"((d)[3]) \
      : "r"((a)[0]), "r"((a)[1]), "r"((a)[2]), "r"((a)[3]), \
        "r"((b)[0]), "r"((b)[1]))

// ============================================================
// One-shot fp32 -> fp16 conversion of all inputs, K-PERMUTED
// ============================================================
#define N4_CI   (T_*B_*E_/4)
#define N4_CPOS (T_*E_/4)
#define N4_CWIN (E3_*E_/4)
#define N4_CW   (E_*E_/4)
#define N4_TOT  (N4_CI + N4_CPOS + N4_CWIN + 2*N4_CW)

__global__ __launch_bounds__(256) void k_cvt_all(const float* __restrict__ s0,
                                                 const float* __restrict__ s1,
                                                 const float* __restrict__ s2,
                                                 const float* __restrict__ s3,
                                                 const float* __restrict__ s4) {
    int i = blockIdx.x * 256 + threadIdx.x;
    if (i >= N4_TOT) return;
    const float* src; __half* dst; int off = i;
    if (i < N4_CI)                               { src = s0; dst = g_ci; }
    else if ((off -= N4_CI)   < N4_CPOS)         { src = s1; dst = g_cpos; }
    else if ((off -= N4_CPOS) < N4_CWIN)         { src = s2; dst = g_cwin; }
    else if ((off -= N4_CWIN) < N4_CW)           { src = s3; dst = g_cwout; }
    else { off -= N4_CW;                           src = s4; dst = g_cwpos; }
    float4 v = ((const float4*)src)[off];
    __half2 h0 = __floats2half2_rn(v.x, v.y);
    __half2 h1 = __floats2half2_rn(v.z, v.w);
    unsigned* du = (unsigned*)dst;
    du[permu(2 * off)]     = *(unsigned*)&h0;
    du[permu(2 * off + 1)] = *(unsigned*)&h1;
}

// ============================================================
// fp16 double-buffered cp.async NT mainloop: C[128,128] = A·Bt^T.
// Operands K-PERMUTED -> fragments uint2 LDS.64 (pitch 24, conflict-free).
// ============================================================
template<int KTOT>
__device__ __forceinline__ void gemm_nt_hp(const __half* __restrict__ A, int lda,
                                           const __half* __restrict__ Bt, int ldb,
                                           int m0, int n0, float acc[4][4][4],
                                           unsigned* sm) {
    const int tid = threadIdx.x;
    const int lane = tid & 31, warp = tid >> 5;
    const int wm = (warp >> 2) * 64, wn = (warp & 3) * 32;

#define HSTAGE(buf_, k0_) do {                                                \
    unsigned* As_ = sm + (buf_) * 6144;                                       \
    unsigned* Bs_ = As_ + 3072;                                               \
    _Pragma("unroll")                                                         \
    for (int i_ = 0; i_ < 2; i_++) {                                          \
        int idx_ = tid + i_ * 256;                                            \
        int row_ = idx_ >> 2, c8_ = (idx_ & 3) * 8;                           \
        cpa16(As_ + row_*24 + (idx_ & 3)*4, A  + (size_t)(m0 + row_) * lda + (k0_) + c8_); \
        cpa16(Bs_ + row_*24 + (idx_ & 3)*4, Bt + (size_t)(n0 + row_) * ldb + (k0_) + c8_); \
    }                                                                         \
    asm volatile("cp.async.commit_group;" ::: "memory");                      \
} while (0)

    HSTAGE(0, 0);
    #pragma unroll 1
    for (int k0 = 0; k0 < KTOT; k0 += 32) {
        const int buf = (k0 >> 5) & 1;
        const bool more = (k0 + 32 < KTOT);
        if (more) HSTAGE(buf ^ 1, k0 + 32);
        if (more) asm volatile("cp.async.wait_group 1;" ::: "memory");
        else      asm volatile("cp.async.wait_group 0;" ::: "memory");
        __syncthreads();

        const unsigned* As = sm + buf * 6144;
        const unsigned* Bs = As + 3072;
        #pragma unroll
        for (int ks = 0; ks < 2; ks++) {
            const int r = lane >> 2, cb = ks * 8 + 2 * (lane & 3);
            unsigned af[4][4], bf[4][2];
            #pragma unroll
            for (int mi = 0; mi < 4; mi++) {
                int rr = wm + mi * 16 + r;
                uint2 lo = *(const uint2*)(As + rr * 24 + cb);
                uint2 hi = *(const uint2*)(As + (rr + 8) * 24 + cb);
                af[mi][0] = lo.x; af[mi][1] = hi.x;
                af[mi][2] = lo.y; af[mi][3] = hi.y;
            }
            #pragma unroll
            for (int ni = 0; ni < 4; ni++) {
                int rb = wn + ni * 8 + r;
                uint2 u = *(const uint2*)(Bs + rb * 24 + cb);
                bf[ni][0] = u.x; bf[ni][1] = u.y;
            }
            #pragma unroll
            for (int mi = 0; mi < 4; mi++)
                #pragma unroll
                for (int ni = 0; ni < 4; ni++)
                    MMA16(acc[mi][ni], af[mi], bf[ni]);
        }
        __syncthreads();
    }
#undef HSTAGE
}

#define EPI_ROW(m0, wm, mi, rg) ((m0) + (wm) + (mi)*16 + (lane >> 2) + (((rg) & 2) << 2))
#define EPI_COL(n0, wn, ni, rg) ((n0) + (wn) + (ni)*8 + ((lane & 3) << 1) + ((rg) & 1))

// ============================================================
// QKV projection -> q/k [B,H,T,D] d-permuted, v [B,H,D,T] t-permuted
// ============================================================
__global__ __launch_bounds__(256) void k_qkv(const float* __restrict__ bias) {
    extern __shared__ unsigned dsm[];
    float acc[4][4][4] = {};
    const int m0 = blockIdx.y * 128, n0 = blockIdx.x * 128;
    gemm_nt_hp<E_>(g_ci, E_, g_cwin, E_, m0, n0, acc, dsm);
    const int lane = threadIdx.x & 31, warp = threadIdx.x >> 5;
    const int wm = (warp >> 2) * 64, wn = (warp & 3) * 32;
    #pragma unroll
    for (int mi = 0; mi < 4; mi++)
        #pragma unroll
        for (int ni = 0; ni < 4; ni++)
            #pragma unroll
            for (int rg = 0; rg < 4; rg++) {
                int row = EPI_ROW(m0, wm, mi, rg);
                int col = EPI_COL(n0, wn, ni, rg);
                float v = acc[mi][ni][rg] + bias[col];
                int t = row / B_, b = row % B_;
                int sec = col >> 9, h = (col >> 6) & 7, d = col & 63;
                if (sec == 2) {
                    int w = t >> 1;
                    int tp = (permu(w) << 1) | (t & 1);
                    g_v[(((size_t)(b * H_ + h) * D_) + d) * T_ + tp] = __float2half_rn(v);
                } else {
                    int pd = (permu(d >> 1) << 1) | (d & 1);
                    __half* dst = (sec == 0) ? g_q : g_k;
                    dst[(((size_t)(b * H_ + h) * T_) + t) * D_ + pd] = __float2half_rn(v);
                }
            }
}

// ============================================================
// pos projection -> g_r[H,R,D] d-permuted + in-block br
// ============================================================
__global__ __launch_bounds__(256) void k_pos(const float* __restrict__ bias,
                                             const float* __restrict__ rrb) {
    extern __shared__ unsigned dsm[];
    float acc[4][4][4] = {};
    const int m0 = blockIdx.y * 128, n0 = blockIdx.x * 128;
    gemm_nt_hp<E_>(g_cpos, E_, g_cwpos, E_, m0, n0, acc, dsm);
    const int tid = threadIdx.x, lane = tid & 31, warp = tid >> 5;
    const int wm = (warp >> 2) * 64, wn = (warp & 3) * 32;
    __half* Hs = (__half*)dsm;                 // [128][136] logical tile
    #pragma unroll
    for (int mi = 0; mi < 4; mi++)
        #pragma unroll
        for (int ni = 0; ni < 4; ni++)
            #pragma unroll
            for (int rg = 0; rg < 4; rg++) {
                int rr = EPI_ROW(m0, wm, mi, rg);
                int col = EPI_COL(n0, wn, ni, rg);
                int h = col >> 6, d = col & 63;
                __half hv = __float2half_rn(acc[mi][ni][rg] + bias[col]);
                int pd = (permu(d >> 1) << 1) | (d & 1);
                g_r[((size_t)h * T_ + rr) * D_ + pd] = hv;
                Hs[(rr - m0) * 136 + (col - n0)] = hv;
            }
    __syncthreads();

    int lr = tid & 127, hl = tid >> 7;
    int h = (n0 >> 6) + hl;
    const __half2* rowp = (const __half2*)(Hs + lr * 136 + hl * 64);
    const float* bb = rrb + h * D_;
    float s = 0.f;
    #pragma unroll
    for (int i = 0; i < 32; i++) {
        float2 a = __half22float2(rowp[i]);
        s += a.x * bb[2*i] + a.y * bb[2*i + 1];
    }
    g_br[h * T_ + m0 + lr] = s;
}

// ============================================================
// BD: raw[t,c] = q[t]·r[c] + br[c] -> PRE-SHIFTED fp16.
// Contiguous-copy identity: out[t*(T+1)+n0-(T-1)+k] = src[k].
// Hs staging lives in a DISJOINT smem region -> no post-MMA barrier.
// ============================================================
__global__ __launch_bounds__(256) void k_bd() {
    extern __shared__ unsigned dsm[];
    const int bh = blockIdx.z, h = bh & 7;
    const int m0 = blockIdx.y * 128, n0 = blockIdx.x * 128;
    const __half* A  = g_q + (size_t)bh * T_ * D_;
    const __half* Bt = g_r + (size_t)h  * T_ * D_;

    const int tid = threadIdx.x, lane = tid & 31, warp = tid >> 5;
    const int wm = (warp >> 2) * 64, wn = (warp & 3) * 32;

    unsigned* As = dsm;                       // [128][40]
    unsigned* Bs = dsm + 5120;                // [128][40]
    __half*   Hs = (__half*)(dsm + 10240);    // [128][136] halfs, DISJOINT

    // ---- single-stage load: full K=64 ----
    #pragma unroll
    for (int i = 0; i < 4; i++) {
        int idx = tid + i * 256;
        int row = idx >> 3, ch = idx & 7;
        cpa16(As + row*40 + ch*4, A  + (size_t)(m0 + row) * D_ + ch*8);
        cpa16(Bs + row*40 + ch*4, Bt + (size_t)(n0 + row) * D_ + ch*8);
    }
    asm volatile("cp.async.commit_group;" ::: "memory");
    asm volatile("cp.async.wait_group 0;" ::: "memory");
    __syncthreads();

    float acc[4][4][4] = {};
    #pragma unroll
    for (int ks = 0; ks < 4; ks++) {
        const int r = lane >> 2, cb = ks * 8 + 2 * (lane & 3);
        unsigned af[4][4], bf[4][2];
        #pragma unroll
        for (int mi = 0; mi < 4; mi++) {
            int rr = wm + mi * 16 + r;
            uint2 lo = *(const uint2*)(As + rr * 40 + cb);
            uint2 hi = *(const uint2*)(As + (rr + 8) * 40 + cb);
            af[mi][0] = lo.x; af[mi][1] = hi.x;
            af[mi][2] = lo.y; af[mi][3] = hi.y;
        }
        #pragma unroll
        for (int ni = 0; ni < 4; ni++) {
            int rb = wn + ni * 8 + r;
            uint2 u = *(const uint2*)(Bs + rb * 40 + cb);
            bf[ni][0] = u.x; bf[ni][1] = u.y;
        }
        #pragma unroll
        for (int mi = 0; mi < 4; mi++)
            #pragma unroll
            for (int ni = 0; ni < 4; ni++)
                MMA16(acc[mi][ni], af[mi], bf[ni]);
    }
    // NO barrier: Hs is disjoint from As/Bs

    // ---- stage tile to Hs as half2 (br added, scaled) ----
    const float2* brv = (const float2*)(g_br + h * T_ + n0);
    #pragma unroll
    for (int mi = 0; mi < 4; mi++)
        #pragma unroll
        for (int ni = 0; ni < 4; ni++) {
            int lc = wn + ni * 8 + 2 * (lane & 3);
            float2 brx = brv[lc >> 1];
            #pragma unroll
            for (int rgp = 0; rgp < 2; rgp++) {
                int lt = wm + mi * 16 + (lane >> 2) + rgp * 8;
                __half2 v = __floats2half2_rn(
                    (acc[mi][ni][2*rgp]     + brx.x) * SCL,
                    (acc[mi][ni][2*rgp + 1] + brx.y) * SCL);
                *(__half2*)(Hs + lt * 136 + lc) = v;
            }
        }
    __syncthreads();

    // ---- contiguous shifted row copies ----
    __half* out = g_BDs + (size_t)bh * T_ * T_;
    const int tb = m0 + warp * 16;
    #pragma unroll 2
    for (int i = 0; i < 16; i++) {
        const int t = tb + i;
        const long base = (long)t * (T_ + 1) + n0 - (T_ - 1);
        const __half* src = Hs + (warp * 16 + i) * 136;
        if (t == 0) {
            int cut = T_ - 1 - n0;                    // >= 127
            if (cut < 128 && lane < 128 - cut)
                out[base + cut + lane] = src[cut + lane];
        } else if (t & 1) {                           // base even
            *(__half2*)(out + base + 2*lane)      = *(const __half2*)(src + 2*lane);
            *(__half2*)(out + base + 2*lane + 64) = *(const __half2*)(src + 2*lane + 64);
        } else {                                      // base odd
            if (lane == 0) { out[base] = src[0]; out[base + 127] = src[127]; }
            int k = 1 + 2 * lane;
            __half2 v0; v0.x = src[k]; v0.y = src[k + 1];
            *(__half2*)(out + base + k) = v0;
            if (lane < 31) {
                int k2 = k + 64;
                __half2 v1; v1.x = src[k2]; v1.y = src[k2 + 1];
                *(__half2*)(out + base + k2) = v1;
            }
        }
    }
}

// ============================================================
// Flash attention (round 13 + warp-ballot rescale skip)
// ============================================================
__global__ __launch_bounds__(256, 2) void k_flash(const float* __restrict__ rwb) {
    extern __shared__ unsigned smem[];
    const int KW = 64 * 40;
    const int VW = 64 * 40;
    const int BUFW = KW + VW;
    unsigned* Ps = smem + 2 * BUFW;         // BD: [128][36] words

    const int bh = blockIdx.y, h = bh & 7, b = bh >> 3;
    const int t0 = blockIdx.x * 128;
    const __half* Q  = g_q + (size_t)bh * T_ * D_;
    const __half* K  = g_k + (size_t)bh * T_ * D_;
    const __half* V  = g_v + (size_t)bh * D_ * T_;
    const __half* BD = g_BDs + (size_t)bh * T_ * T_;

    const int tid = threadIdx.x, lane = tid & 31, warp = tid >> 5;
    const int r = lane >> 2, cc = lane & 3;
    const int row0 = warp * 16;
    const int trow0 = t0 + row0 + r, trow1 = trow0 + 8;

#define PREFETCH_KV(buf, s0_) do {                                            \
    unsigned* Kb_ = smem + (buf) * BUFW;                                      \
    unsigned* Vb_ = Kb_ + KW;                                                 \
    _Pragma("unroll")                                                         \
    for (int i_ = 0; i_ < 2; i_++) {                                          \
        int idx_ = tid + i_ * 256;                                            \
        int row_ = idx_ >> 3, ch_ = idx_ & 7;                                 \
        cpa16(Kb_ + row_*40 + ch_*4, K + (size_t)((s0_) + row_) * D_ + ch_*8);\
    }                                                                         \
    _Pragma("unroll")                                                         \
    for (int i_ = 0; i_ < 2; i_++) {                                          \
        int idx_ = tid + i_ * 256;                                            \
        int row_ = idx_ >> 3, ch_ = idx_ & 7;                                 \
        cpa16(Vb_ + row_*40 + ch_*4, V + (size_t)row_ * T_ + (s0_) + ch_*8);  \
    }                                                                         \
    asm volatile("cp.async.commit_group;" ::: "memory");                      \
} while (0)

#define PREFETCH_BD(s0_) do {                                                 \
    _Pragma("unroll")                                                         \
    for (int i_ = 0; i_ < 4; i_++) {                                          \
        int idx_ = lane + i_ * 32;                                            \
        int row_ = idx_ >> 3, c16_ = idx_ & 7;                                \
        cpa16(Ps + (row0 + row_) * 36 + c16_ * 4,                             \
              BD + (size_t)(t0 + row0 + row_) * T_ + (s0_) + c16_ * 8);       \
    }                                                                         \
    asm volatile("cp.async.commit_group;" ::: "memory");                      \
} while (0)

    unsigned aq[4][4];
    const float* rwbh = rwb + h * D_;
    const unsigned* Qu = (const unsigned*)Q;
    #pragma unroll
    for (int kc = 0; kc < 4; kc++) {
        int c0 = kc * 16 + 2 * cc;
        uint2 qw0 = *(const uint2*)(Qu + (size_t)trow0 * 32 + kc * 8 + 2 * cc);
        uint2 qw1 = *(const uint2*)(Qu + (size_t)trow1 * 32 + kc * 8 + 2 * cc);
        float2 f;
        __half2 a;
        f = __half22float2(*(__half2*)&qw0.x);
        a = __floats2half2_rn((f.x + rwbh[c0]) * SCL, (f.y + rwbh[c0+1]) * SCL);
        aq[kc][0] = *(unsigned*)&a;
        f = __half22float2(*(__half2*)&qw1.x);
        a = __floats2half2_rn((f.x + rwbh[c0]) * SCL, (f.y + rwbh[c0+1]) * SCL);
        aq[kc][1] = *(unsigned*)&a;
        f = __half22float2(*(__half2*)&qw0.y);
        a = __floats2half2_rn((f.x + rwbh[c0+8]) * SCL, (f.y + rwbh[c0+9]) * SCL);
        aq[kc][2] = *(unsigned*)&a;
        f = __half22float2(*(__half2*)&qw1.y);
        a = __floats2half2_rn((f.x + rwbh[c0+8]) * SCL, (f.y + rwbh[c0+9]) * SCL);
        aq[kc][3] = *(unsigned*)&a;
    }

    PREFETCH_KV(0, 0);
    PREFETCH_BD(0);

    float oacc[8][4] = {};
    float m0r = -1e30f, m1r = -1e30f, l0 = 0.f, l1 = 0.f;

    #pragma unroll 1
    for (int it = 0; it < T_ / 64; it++) {
        const int s0 = it * 64;
        const int cur = it & 1;
        asm volatile("cp.async.wait_group 1;" ::: "memory");   // KV(it)
        __syncthreads();

        PREFETCH_KV(cur ^ 1, (s0 + 64) & (T_ - 1));

        const unsigned* Kb = smem + cur * BUFW;
        const unsigned* Vb = Kb + KW;

        float pacc[8][4];
        #pragma unroll
        for (int nt = 0; nt < 8; nt++)
            #pragma unroll
            for (int j = 0; j < 4; j++) pacc[nt][j] = 0.f;
        #pragma unroll
        for (int kc = 0; kc < 4; kc++) {
            #pragma unroll
            for (int nt = 0; nt < 8; nt++) {
                int srow = nt * 8 + r;
                uint2 kb2 = *(const uint2*)(Kb + srow * 40 + kc * 8 + 2 * cc);
                unsigned bf[2] = { kb2.x, kb2.y };
                MMA16(pacc[nt], aq[kc], bf);
            }
        }

        asm volatile("cp.async.wait_group 1;" ::: "memory");   // BD(it)
        __syncwarp();

        const __half2* bd0 = (const __half2*)(Ps + (row0 + r) * 36);
        const __half2* bd1 = (const __half2*)(Ps + (row0 + r + 8) * 36);
        float pm0 = -1e30f, pm1 = -1e30f;
        const bool diag = (t0 + row0 + 1 <= s0 + 63) && (t0 + row0 + 16 >= s0);
        if (diag) {
            #pragma unroll
            for (int nt = 0; nt < 8; nt++) {
                int sb = s0 + nt * 8 + 2 * cc;
                float2 f0 = __half22float2(bd0[4 * nt + cc]);
                float2 f1 = __half22float2(bd1[4 * nt + cc]);
                pacc[nt][0] += (sb     == trow0 + 1) ? 0.f : f0.x;
                pacc[nt][1] += (sb + 1 == trow0 + 1) ? 0.f : f0.y;
                pacc[nt][2] += (sb     == trow1 + 1) ? 0.f : f1.x;
                pacc[nt][3] += (sb + 1 == trow1 + 1) ? 0.f : f1.y;
                pm0 = fmaxf(pm0, fmaxf(pacc[nt][0], pacc[nt][1]));
                pm1 = fmaxf(pm1, fmaxf(pacc[nt][2], pacc[nt][3]));
            }
        } else {
            #pragma unroll
            for (int nt = 0; nt < 8; nt++) {
                float2 f0 = __half22float2(bd0[4 * nt + cc]);
                float2 f1 = __half22float2(bd1[4 * nt + cc]);
                pacc[nt][0] += f0.x;
                pacc[nt][1] += f0.y;
                pacc[nt][2] += f1.x;
                pacc[nt][3] += f1.y;
                pm0 = fmaxf(pm0, fmaxf(pacc[nt][0], pacc[nt][1]));
                pm1 = fmaxf(pm1, fmaxf(pacc[nt][2], pacc[nt][3]));
            }
        }
        pm0 = fmaxf(pm0, __shfl_xor_sync(0xffffffffu, pm0, 1));
        pm0 = fmaxf(pm0, __shfl_xor_sync(0xffffffffu, pm0, 2));
        pm1 = fmaxf(pm1, __shfl_xor_sync(0xffffffffu, pm1, 1));
        pm1 = fmaxf(pm1, __shfl_xor_sync(0xffffffffu, pm1, 2));

        float mn0 = fmaxf(m0r, pm0), mn1 = fmaxf(m1r, pm1);
        // rescale only when some lane's running max actually changed;
        // skipping is BIT-IDENTICAL (sf would be ex2(0) = 1.0 exactly)
        if (__ballot_sync(0xffffffffu, (pm0 > m0r) | (pm1 > m1r))) {
            float sf0 = ex2f(m0r - mn0), sf1 = ex2f(m1r - mn1);
            #pragma unroll
            for (int nt = 0; nt < 8; nt++) {
                oacc[nt][0] *= sf0; oacc[nt][1] *= sf0;
                oacc[nt][2] *= sf1; oacc[nt][3] *= sf1;
            }
            l0 *= sf0; l1 *= sf1;
        }
        m0r = mn0; m1r = mn1;

        unsigned ph[8][2];
        float sum0 = 0.f, sum1 = 0.f;
        #pragma unroll
        for (int nt = 0; nt < 8; nt++) {
            float e0 = ex2f(pacc[nt][0] - mn0);
            float e1 = ex2f(pacc[nt][1] - mn0);
            float e2 = ex2f(pacc[nt][2] - mn1);
            float e3 = ex2f(pacc[nt][3] - mn1);
            sum0 += e0 + e1; sum1 += e2 + e3;
            __half2 p0 = __floats2half2_rn(e0, e1);
            __half2 p1 = __floats2half2_rn(e2, e3);
            ph[nt][0] = *(unsigned*)&p0;
            ph[nt][1] = *(unsigned*)&p1;
        }
        sum0 += __shfl_xor_sync(0xffffffffu, sum0, 1);
        sum0 += __shfl_xor_sync(0xffffffffu, sum0, 2);
        sum1 += __shfl_xor_sync(0xffffffffu, sum1, 1);
        sum1 += __shfl_xor_sync(0xffffffffu, sum1, 2);
        l0 += sum0; l1 += sum1;

        #pragma unroll
        for (int kc = 0; kc < 4; kc++) {
            unsigned af[4] = { ph[2*kc][0], ph[2*kc][1], ph[2*kc+1][0], ph[2*kc+1][1] };
            #pragma unroll
            for (int nt = 0; nt < 8; nt++) {
                int drow = nt * 8 + r;
                uint2 vb2 = *(const uint2*)(Vb + drow * 40 + kc * 8 + 2 * cc);
                unsigned bf[2] = { vb2.x, vb2.y };
                MMA16(oacc[nt], af, bf);
            }
        }
        __syncwarp();

        if (it < T_ / 64 - 1)
            PREFETCH_BD(s0 + 64);
    }
    asm volatile("cp.async.wait_group 0;" ::: "memory");

    float il0 = 1.f / l0, il1 = 1.f / l1;
    unsigned* ctxu = (unsigned*)g_ctx;
    #pragma unroll
    for (int nt = 0; nt < 8; nt++) {
        int u_l = h * 32 + nt * 4 + cc;
        int pu = permu(u_l);
        __half2 o0 = __floats2half2_rn(oacc[nt][0] * il0, oacc[nt][1] * il0);
        ctxu[((size_t)trow0 * B_ + b) * (E_/2) + pu] = *(unsigned*)&o0;
        __half2 o1 = __floats2half2_rn(oacc[nt][2] * il1, oacc[nt][3] * il1);
        ctxu[((size_t)trow1 * B_ + b) * (E_/2) + pu] = *(unsigned*)&o1;
    }
#undef PREFETCH_KV
#undef PREFETCH_BD
}

// ============================================================
// out projection (fp16 GEMM, fp32 output)
// ============================================================
__global__ __launch_bounds__(256) void k_out(const float* __restrict__ bias,
                                             float* __restrict__ out) {
    extern __shared__ unsigned dsm[];
    float acc[4][4][4] = {};
    const int m0 = blockIdx.y * 128, n0 = blockIdx.x * 128;
    gemm_nt_hp<E_>(g_ctx, E_, g_cwout, E_, m0, n0, acc, dsm);
    const int lane = threadIdx.x & 31, warp = threadIdx.x >> 5;
    const int wm = (warp >> 2) * 64, wn = (warp & 3) * 32;
    #pragma unroll
    for (int mi = 0; mi < 4; mi++)
        #pragma unroll
        for (int ni = 0; ni < 4; ni++)
            #pragma unroll
            for (int rg = 0; rg < 4; rg++) {
                int row = EPI_ROW(m0, wm, mi, rg);
                int col = EPI_COL(n0, wn, ni, rg);
                out[(size_t)row * E_ + col] = acc[mi][ni][rg] + bias[col];
            }
}

// ============================================================
extern "C" void kernel_launch(void* const* d_in, const int* in_sizes, int n_in,
                              void* d_out, int out_size) {
    const float* input = (const float*)d_in[0];
    const float* pos   = (const float*)d_in[1];
    const float* w_in  = (const float*)d_in[2];
    const float* w_out = (const float*)d_in[3];
    const float* w_pos = (const float*)d_in[4];
    const float* b_in  = (const float*)d_in[5];
    const float* b_out = (const float*)d_in[6];
    const float* b_pos = (const float*)d_in[7];
    const float* rwb   = (const float*)d_in[8];
    const float* rrb   = (const float*)d_in[9];
    float* out = (float*)d_out;

    const int gemm_smem  = 2 * 2 * 128 * 24 * 4;                 // 49152
    const int bd_smem    = 2 * 128 * 40 * 4 + 128 * 136 * 2;     // 75776
    const int flash_smem = (2 * (64*40 + 64*40) + 128*36) * 4;   // 59392
    cudaFuncSetAttribute(k_qkv,  cudaFuncAttributeMaxDynamicSharedMemorySize, gemm_smem);
    cudaFuncSetAttribute(k_pos,  cudaFuncAttributeMaxDynamicSharedMemorySize, gemm_smem);
    cudaFuncSetAttribute(k_bd,   cudaFuncAttributeMaxDynamicSharedMemorySize, bd_smem);
    cudaFuncSetAttribute(k_out,  cudaFuncAttributeMaxDynamicSharedMemorySize, gemm_smem);
    cudaFuncSetAttribute(k_flash, cudaFuncAttributeMaxDynamicSharedMemorySize, flash_smem);

    k_cvt_all<<<(N4_TOT + 255)/256, 256>>>(input, pos, w_in, w_out, w_pos);

    k_qkv  <<<dim3(E3_/128, (T_*B_)/128), 256, gemm_smem>>>(b_in);
    k_pos  <<<dim3(E_/128,  T_/128),      256, gemm_smem>>>(b_pos, rrb);
    k_bd   <<<dim3(T_/128, T_/128, B_*H_), 256, bd_smem>>>();
    k_flash<<<dim3(T_/128, B_*H_), 256, flash_smem>>>(rwb);
    k_out  <<<dim3(E_/128, (T_*B_)/128), 256, gemm_smem>>>(b_out, out);
}

// round 15
// speedup vs baseline: 1.6045x; 1.0417x over previous
#include <cuda_runtime.h>
#include <cuda_fp16.h>
#include <math.h>

#define T_  2048
#define B_  2
#define E_  512
#define H_  8
#define D_  64
#define E3_ 1536

// scale * log2(e): softmax in base-2 domain
#define SCL 0.1803368801111204f

// uint-pair permute within each 8-uint chunk: o -> ((o&3)<<1)|(o>>2)
__device__ __forceinline__ int permu(int u) {
    return (u & ~7) | (((u & 3) << 1) | ((u >> 2) & 1));
}

// ---- scratch (__device__ globals: allocation-guard-legal) ----
__device__ __half g_q[B_*H_*T_*D_];           // [B,H,T,D] fp16, d-permuted
__device__ __half g_k[B_*H_*T_*D_];           // [B,H,T,D] fp16, d-permuted
__device__ __half g_v[B_*H_*D_*T_];           // [B,H,D,T] fp16, t-permuted
__device__ __half g_r[H_*T_*D_];              // [H,R,D]   fp16, d-permuted
__device__ float  g_br[H_*T_];                // rrb_h · r[h,c]
__device__ __half g_BDs[(size_t)B_*H_*T_*T_]; // BD, PRE-SHIFTED + scaled, fp16
__device__ __half g_ctx[T_*B_*E_];            // [T,B,E]   fp16, E-permuted
// fp16 copies of harness inputs, K-permuted (raw cp.async GEMM operands)
__device__ __half g_ci[T_*B_*E_];
__device__ __half g_cpos[T_*E_];
__device__ __half g_cwin[E3_*E_];
__device__ __half g_cwout[E_*E_];
__device__ __half g_cwpos[E_*E_];

__device__ __forceinline__ float ex2f(float x) {
    float y;
    asm("ex2.approx.ftz.f32 %0, %1;" : "=f"(y) : "f"(x));
    return y;
}
__device__ __forceinline__ void cpa16(void* d, const void* s) {
    unsigned a = (unsigned)__cvta_generic_to_shared(d);
    asm volatile("cp.async.cg.shared.global [%0], [%1], 16;" :: "r"(a), "l"(s));
}

// fp16 mma, fp32 accum
#define MMA16(d, a, b) \
  asm volatile("mma.sync.aligned.m16n8k16.row.col.f32.f16.f16.f32 " \
      "{%0,%1,%2,%3},{%4,%5,%6,%7},{%8,%9},{%0,%1,%2,%3};" \
      : "+f"((d)[0]), "+f"((d)[1]), "+f"((d)[2]), "+f"((d)[3]) \
      : "r"((a)[0]), "r"((a)[1]), "r"((a)[2]), "r"((a)[3]), \
        "r"((b)[0]), "r"((b)[1]))

// ============================================================
// One-shot fp32 -> fp16 conversion of all inputs, K-PERMUTED
// ============================================================
#define N4_CI   (T_*B_*E_/4)
#define N4_CPOS (T_*E_/4)
#define N4_CWIN (E3_*E_/4)
#define N4_CW   (E_*E_/4)
#define N4_TOT  (N4_CI + N4_CPOS + N4_CWIN + 2*N4_CW)

__global__ __launch_bounds__(256) void k_cvt_all(const float* __restrict__ s0,
                                                 const float* __restrict__ s1,
                                                 const float* __restrict__ s2,
                                                 const float* __restrict__ s3,
                                                 const float* __restrict__ s4) {
    int i = blockIdx.x * 256 + threadIdx.x;
    if (i >= N4_TOT) return;
    const float* src; __half* dst; int off = i;
    if (i < N4_CI)                               { src = s0; dst = g_ci; }
    else if ((off -= N4_CI)   < N4_CPOS)         { src = s1; dst = g_cpos; }
    else if ((off -= N4_CPOS) < N4_CWIN)         { src = s2; dst = g_cwin; }
    else if ((off -= N4_CWIN) < N4_CW)           { src = s3; dst = g_cwout; }
    else { off -= N4_CW;                           src = s4; dst = g_cwpos; }
    float4 v = ((const float4*)src)[off];
    __half2 h0 = __floats2half2_rn(v.x, v.y);
    __half2 h1 = __floats2half2_rn(v.z, v.w);
    unsigned* du = (unsigned*)dst;
    du[permu(2 * off)]     = *(unsigned*)&h0;
    du[permu(2 * off + 1)] = *(unsigned*)&h1;
}

// ============================================================
// fp16 double-buffered cp.async NT mainloop: C[128,128] = A·Bt^T.
// Operands K-PERMUTED -> fragments uint2 LDS.64 (pitch 24, conflict-free).
// ============================================================
template<int KTOT>
__device__ __forceinline__ void gemm_nt_hp(const __half* __restrict__ A, int lda,
                                           const __half* __restrict__ Bt, int ldb,
                                           int m0, int n0, float acc[4][4][4],
                                           unsigned* sm) {
    const int tid = threadIdx.x;
    const int lane = tid & 31, warp = tid >> 5;
    const int wm = (warp >> 2) * 64, wn = (warp & 3) * 32;

#define HSTAGE(buf_, k0_) do {                                                \
    unsigned* As_ = sm + (buf_) * 6144;                                       \
    unsigned* Bs_ = As_ + 3072;                                               \
    _Pragma("unroll")                                                         \
    for (int i_ = 0; i_ < 2; i_++) {                                          \
        int idx_ = tid + i_ * 256;                                            \
        int row_ = idx_ >> 2, c8_ = (idx_ & 3) * 8;                           \
        cpa16(As_ + row_*24 + (idx_ & 3)*4, A  + (size_t)(m0 + row_) * lda + (k0_) + c8_); \
        cpa16(Bs_ + row_*24 + (idx_ & 3)*4, Bt + (size_t)(n0 + row_) * ldb + (k0_) + c8_); \
    }                                                                         \
    asm volatile("cp.async.commit_group;" ::: "memory");                      \
} while (0)

    HSTAGE(0, 0);
    #pragma unroll 1
    for (int k0 = 0; k0 < KTOT; k0 += 32) {
        const int buf = (k0 >> 5) & 1;
        const bool more = (k0 + 32 < KTOT);
        if (more) HSTAGE(buf ^ 1, k0 + 32);
        if (more) asm volatile("cp.async.wait_group 1;" ::: "memory");
        else      asm volatile("cp.async.wait_group 0;" ::: "memory");
        __syncthreads();

        const unsigned* As = sm + buf * 6144;
        const unsigned* Bs = As + 3072;
        #pragma unroll
        for (int ks = 0; ks < 2; ks++) {
            const int r = lane >> 2, cb = ks * 8 + 2 * (lane & 3);
            unsigned af[4][4], bf[4][2];
            #pragma unroll
            for (int mi = 0; mi < 4; mi++) {
                int rr = wm + mi * 16 + r;
                uint2 lo = *(const uint2*)(As + rr * 24 + cb);
                uint2 hi = *(const uint2*)(As + (rr + 8) * 24 + cb);
                af[mi][0] = lo.x; af[mi][1] = hi.x;
                af[mi][2] = lo.y; af[mi][3] = hi.y;
            }
            #pragma unroll
            for (int ni = 0; ni < 4; ni++) {
                int rb = wn + ni * 8 + r;
                uint2 u = *(const uint2*)(Bs + rb * 24 + cb);
                bf[ni][0] = u.x; bf[ni][1] = u.y;
            }
            #pragma unroll
            for (int mi = 0; mi < 4; mi++)
                #pragma unroll
                for (int ni = 0; ni < 4; ni++)
                    MMA16(acc[mi][ni], af[mi], bf[ni]);
        }
        __syncthreads();
    }
#undef HSTAGE
}

#define EPI_ROW(m0, wm, mi, rg) ((m0) + (wm) + (mi)*16 + (lane >> 2) + (((rg) & 2) << 2))
#define EPI_COL(n0, wn, ni, rg) ((n0) + (wn) + (ni)*8 + ((lane & 3) << 1) + ((rg) & 1))

// ============================================================
// QKV projection -> q/k [B,H,T,D] d-permuted (half2 stores),
// v [B,H,D,T] t-permuted
// ============================================================
__global__ __launch_bounds__(256) void k_qkv(const float* __restrict__ bias) {
    extern __shared__ unsigned dsm[];
    float acc[4][4][4] = {};
    const int m0 = blockIdx.y * 128, n0 = blockIdx.x * 128;
    gemm_nt_hp<E_>(g_ci, E_, g_cwin, E_, m0, n0, acc, dsm);
    const int lane = threadIdx.x & 31, warp = threadIdx.x >> 5;
    const int wm = (warp >> 2) * 64, wn = (warp & 3) * 32;
    #pragma unroll
    for (int mi = 0; mi < 4; mi++)
        #pragma unroll
        for (int ni = 0; ni < 4; ni++)
            #pragma unroll
            for (int rp = 0; rp < 2; rp++) {       // rg pairs (0,1),(2,3)
                int row = EPI_ROW(m0, wm, mi, 2*rp);
                int col = EPI_COL(n0, wn, ni, 0);  // even col of the pair
                float v0 = acc[mi][ni][2*rp]     + bias[col];
                float v1 = acc[mi][ni][2*rp + 1] + bias[col + 1];
                int t = row / B_, b = row % B_;
                int sec = col >> 9, h = (col >> 6) & 7, d = col & 63;
                if (sec == 2) {
                    // V transposed [B,H,D,T]; adjacent d -> different rows: scalar
                    int w = t >> 1;
                    int tp = (permu(w) << 1) | (t & 1);
                    size_t vb = ((size_t)(b * H_ + h) * D_) * T_ + tp;
                    g_v[vb + (size_t)d * T_]       = __float2half_rn(v0);
                    g_v[vb + (size_t)(d + 1) * T_] = __float2half_rn(v1);
                } else {
                    // d-permute keeps the (2u, 2u+1) pair adjacent: half2 store
                    int pu = permu(d >> 1);
                    __half* dst = (sec == 0) ? g_q : g_k;
                    __half2 hv = __floats2half2_rn(v0, v1);
                    *(__half2*)(dst + (((size_t)(b * H_ + h) * T_) + t) * D_ + 2*pu) = hv;
                }
            }
}

// ============================================================
// pos projection -> g_r[H,R,D] d-permuted + in-block br
// ============================================================
__global__ __launch_bounds__(256) void k_pos(const float* __restrict__ bias,
                                             const float* __restrict__ rrb) {
    extern __shared__ unsigned dsm[];
    float acc[4][4][4] = {};
    const int m0 = blockIdx.y * 128, n0 = blockIdx.x * 128;
    gemm_nt_hp<E_>(g_cpos, E_, g_cwpos, E_, m0, n0, acc, dsm);
    const int tid = threadIdx.x, lane = tid & 31, warp = tid >> 5;
    const int wm = (warp >> 2) * 64, wn = (warp & 3) * 32;
    __half* Hs = (__half*)dsm;                 // [128][136] logical tile
    #pragma unroll
    for (int mi = 0; mi < 4; mi++)
        #pragma unroll
        for (int ni = 0; ni < 4; ni++)
            #pragma unroll
            for (int rp = 0; rp < 2; rp++) {
                int rr = EPI_ROW(m0, wm, mi, 2*rp);
                int col = EPI_COL(n0, wn, ni, 0);
                float v0 = acc[mi][ni][2*rp]     + bias[col];
                float v1 = acc[mi][ni][2*rp + 1] + bias[col + 1];
                int h = col >> 6, d = col & 63;
                __half2 hv = __floats2half2_rn(v0, v1);
                int pu = permu(d >> 1);
                *(__half2*)(g_r + ((size_t)h * T_ + rr) * D_ + 2*pu) = hv;
                *(__half2*)(Hs + (rr - m0) * 136 + (col - n0)) = hv;
            }
    __syncthreads();

    int lr = tid & 127, hl = tid >> 7;
    int h = (n0 >> 6) + hl;
    const __half2* rowp = (const __half2*)(Hs + lr * 136 + hl * 64);
    const float* bb = rrb + h * D_;
    float s = 0.f;
    #pragma unroll
    for (int i = 0; i < 32; i++) {
        float2 a = __half22float2(rowp[i]);
        s += a.x * bb[2*i] + a.y * bb[2*i + 1];
    }
    g_br[h * T_ + m0 + lr] = s;
}

// ============================================================
// BD: raw[t,c] = q[t]·r[c] + br[c] -> PRE-SHIFTED fp16.
// Contiguous-copy identity: out[t*(T+1)+n0-(T-1)+k] = src[k].
// Hs staging DISJOINT -> no post-MMA barrier.
// ============================================================
__global__ __launch_bounds__(256) void k_bd() {
    extern __shared__ unsigned dsm[];
    const int bh = blockIdx.z, h = bh & 7;
    const int m0 = blockIdx.y * 128, n0 = blockIdx.x * 128;
    const __half* A  = g_q + (size_t)bh * T_ * D_;
    const __half* Bt = g_r + (size_t)h  * T_ * D_;

    const int tid = threadIdx.x, lane = tid & 31, warp = tid >> 5;
    const int wm = (warp >> 2) * 64, wn = (warp & 3) * 32;

    unsigned* As = dsm;                       // [128][40]
    unsigned* Bs = dsm + 5120;                // [128][40]
    __half*   Hs = (__half*)(dsm + 10240);    // [128][136] halfs, DISJOINT

    #pragma unroll
    for (int i = 0; i < 4; i++) {
        int idx = tid + i * 256;
        int row = idx >> 3, ch = idx & 7;
        cpa16(As + row*40 + ch*4, A  + (size_t)(m0 + row) * D_ + ch*8);
        cpa16(Bs + row*40 + ch*4, Bt + (size_t)(n0 + row) * D_ + ch*8);
    }
    asm volatile("cp.async.commit_group;" ::: "memory");
    asm volatile("cp.async.wait_group 0;" ::: "memory");
    __syncthreads();

    float acc[4][4][4] = {};
    #pragma unroll
    for (int ks = 0; ks < 4; ks++) {
        const int r = lane >> 2, cb = ks * 8 + 2 * (lane & 3);
        unsigned af[4][4], bf[4][2];
        #pragma unroll
        for (int mi = 0; mi < 4; mi++) {
            int rr = wm + mi * 16 + r;
            uint2 lo = *(const uint2*)(As + rr * 40 + cb);
            uint2 hi = *(const uint2*)(As + (rr + 8) * 40 + cb);
            af[mi][0] = lo.x; af[mi][1] = hi.x;
            af[mi][2] = lo.y; af[mi][3] = hi.y;
        }
        #pragma unroll
        for (int ni = 0; ni < 4; ni++) {
            int rb = wn + ni * 8 + r;
            uint2 u = *(const uint2*)(Bs + rb * 40 + cb);
            bf[ni][0] = u.x; bf[ni][1] = u.y;
        }
        #pragma unroll
        for (int mi = 0; mi < 4; mi++)
            #pragma unroll
            for (int ni = 0; ni < 4; ni++)
                MMA16(acc[mi][ni], af[mi], bf[ni]);
    }
    // NO barrier: Hs disjoint

    const float2* brv = (const float2*)(g_br + h * T_ + n0);
    #pragma unroll
    for (int mi = 0; mi < 4; mi++)
        #pragma unroll
        for (int ni = 0; ni < 4; ni++) {
            int lc = wn + ni * 8 + 2 * (lane & 3);
            float2 brx = brv[lc >> 1];
            #pragma unroll
            for (int rgp = 0; rgp < 2; rgp++) {
                int lt = wm + mi * 16 + (lane >> 2) + rgp * 8;
                __half2 v = __floats2half2_rn(
                    (acc[mi][ni][2*rgp]     + brx.x) * SCL,
                    (acc[mi][ni][2*rgp + 1] + brx.y) * SCL);
                *(__half2*)(Hs + lt * 136 + lc) = v;
            }
        }
    __syncthreads();

    __half* out = g_BDs + (size_t)bh * T_ * T_;
    const int tb = m0 + warp * 16;
    #pragma unroll 4
    for (int i = 0; i < 16; i++) {
        const int t = tb + i;
        const long base = (long)t * (T_ + 1) + n0 - (T_ - 1);
        const __half* src = Hs + (warp * 16 + i) * 136;
        if (t == 0) {
            int cut = T_ - 1 - n0;                    // >= 127
            if (cut < 128 && lane < 128 - cut)
                out[base + cut + lane] = src[cut + lane];
        } else if (t & 1) {                           // base even
            *(__half2*)(out + base + 2*lane)      = *(const __half2*)(src + 2*lane);
            *(__half2*)(out + base + 2*lane + 64) = *(const __half2*)(src + 2*lane + 64);
        } else {                                      // base odd
            if (lane == 0) { out[base] = src[0]; out[base + 127] = src[127]; }
            int k = 1 + 2 * lane;
            __half2 v0; v0.x = src[k]; v0.y = src[k + 1];
            *(__half2*)(out + base + k) = v0;
            if (lane < 31) {
                int k2 = k + 64;
                __half2 v1; v1.x = src[k2]; v1.y = src[k2 + 1];
                *(__half2*)(out + base + k2) = v1;
            }
        }
    }
}

// ============================================================
// Flash attention (round 14 + early BD prefetch)
// ============================================================
__global__ __launch_bounds__(256, 2) void k_flash(const float* __restrict__ rwb) {
    extern __shared__ unsigned smem[];
    const int KW = 64 * 40;
    const int VW = 64 * 40;
    const int BUFW = KW + VW;
    unsigned* Ps = smem + 2 * BUFW;         // BD: [128][36] words

    const int bh = blockIdx.y, h = bh & 7, b = bh >> 3;
    const int t0 = blockIdx.x * 128;
    const __half* Q  = g_q + (size_t)bh * T_ * D_;
    const __half* K  = g_k + (size_t)bh * T_ * D_;
    const __half* V  = g_v + (size_t)bh * D_ * T_;
    const __half* BD = g_BDs + (size_t)bh * T_ * T_;

    const int tid = threadIdx.x, lane = tid & 31, warp = tid >> 5;
    const int r = lane >> 2, cc = lane & 3;
    const int row0 = warp * 16;
    const int trow0 = t0 + row0 + r, trow1 = trow0 + 8;

#define PREFETCH_KV(buf, s0_) do {                                            \
    unsigned* Kb_ = smem + (buf) * BUFW;                                      \
    unsigned* Vb_ = Kb_ + KW;                                                 \
    _Pragma("unroll")                                                         \
    for (int i_ = 0; i_ < 2; i_++) {                                          \
        int idx_ = tid + i_ * 256;                                            \
        int row_ = idx_ >> 3, ch_ = idx_ & 7;                                 \
        cpa16(Kb_ + row_*40 + ch_*4, K + (size_t)((s0_) + row_) * D_ + ch_*8);\
    }                                                                         \
    _Pragma("unroll")                                                         \
    for (int i_ = 0; i_ < 2; i_++) {                                          \
        int idx_ = tid + i_ * 256;                                            \
        int row_ = idx_ >> 3, ch_ = idx_ & 7;                                 \
        cpa16(Vb_ + row_*40 + ch_*4, V + (size_t)row_ * T_ + (s0_) + ch_*8);  \
    }                                                                         \
    asm volatile("cp.async.commit_group;" ::: "memory");                      \
} while (0)

#define PREFETCH_BD(s0_) do {                                                 \
    _Pragma("unroll")                                                         \
    for (int i_ = 0; i_ < 4; i_++) {                                          \
        int idx_ = lane + i_ * 32;                                            \
        int row_ = idx_ >> 3, c16_ = idx_ & 7;                                \
        cpa16(Ps + (row0 + row_) * 36 + c16_ * 4,                             \
              BD + (size_t)(t0 + row0 + row_) * T_ + (s0_) + c16_ * 8);       \
    }                                                                         \
    asm volatile("cp.async.commit_group;" ::: "memory");                      \
} while (0)

    unsigned aq[4][4];
    const float* rwbh = rwb + h * D_;
    const unsigned* Qu = (const unsigned*)Q;
    #pragma unroll
    for (int kc = 0; kc < 4; kc++) {
        int c0 = kc * 16 + 2 * cc;
        uint2 qw0 = *(const uint2*)(Qu + (size_t)trow0 * 32 + kc * 8 + 2 * cc);
        uint2 qw1 = *(const uint2*)(Qu + (size_t)trow1 * 32 + kc * 8 + 2 * cc);
        float2 f;
        __half2 a;
        f = __half22float2(*(__half2*)&qw0.x);
        a = __floats2half2_rn((f.x + rwbh[c0]) * SCL, (f.y + rwbh[c0+1]) * SCL);
        aq[kc][0] = *(unsigned*)&a;
        f = __half22float2(*(__half2*)&qw1.x);
        a = __floats2half2_rn((f.x + rwbh[c0]) * SCL, (f.y + rwbh[c0+1]) * SCL);
        aq[kc][1] = *(unsigned*)&a;
        f = __half22float2(*(__half2*)&qw0.y);
        a = __floats2half2_rn((f.x + rwbh[c0+8]) * SCL, (f.y + rwbh[c0+9]) * SCL);
        aq[kc][2] = *(unsigned*)&a;
        f = __half22float2(*(__half2*)&qw1.y);
        a = __floats2half2_rn((f.x + rwbh[c0+8]) * SCL, (f.y + rwbh[c0+9]) * SCL);
        aq[kc][3] = *(unsigned*)&a;
    }

    PREFETCH_KV(0, 0);
    PREFETCH_BD(0);

    float oacc[8][4] = {};
    float m0r = -1e30f, m1r = -1e30f, l0 = 0.f, l1 = 0.f;

    #pragma unroll 1
    for (int it = 0; it < T_ / 64; it++) {
        const int s0 = it * 64;
        const int cur = it & 1;
        asm volatile("cp.async.wait_group 1;" ::: "memory");   // KV(it)
        __syncthreads();

        PREFETCH_KV(cur ^ 1, (s0 + 64) & (T_ - 1));

        const unsigned* Kb = smem + cur * BUFW;
        const unsigned* Vb = Kb + KW;

        float pacc[8][4];
        #pragma unroll
        for (int nt = 0; nt < 8; nt++)
            #pragma unroll
            for (int j = 0; j < 4; j++) pacc[nt][j] = 0.f;
        #pragma unroll
        for (int kc = 0; kc < 4; kc++) {
            #pragma unroll
            for (int nt = 0; nt < 8; nt++) {
                int srow = nt * 8 + r;
                uint2 kb2 = *(const uint2*)(Kb + srow * 40 + kc * 8 + 2 * cc);
                unsigned bf[2] = { kb2.x, kb2.y };
                MMA16(pacc[nt], aq[kc], bf);
            }
        }

        asm volatile("cp.async.wait_group 1;" ::: "memory");   // BD(it)
        __syncwarp();

        const __half2* bd0 = (const __half2*)(Ps + (row0 + r) * 36);
        const __half2* bd1 = (const __half2*)(Ps + (row0 + r + 8) * 36);
        float pm0 = -1e30f, pm1 = -1e30f;
        const bool diag = (t0 + row0 + 1 <= s0 + 63) && (t0 + row0 + 16 >= s0);
        if (diag) {
            #pragma unroll
            for (int nt = 0; nt < 8; nt++) {
                int sb = s0 + nt * 8 + 2 * cc;
                float2 f0 = __half22float2(bd0[4 * nt + cc]);
                float2 f1 = __half22float2(bd1[4 * nt + cc]);
                pacc[nt][0] += (sb     == trow0 + 1) ? 0.f : f0.x;
                pacc[nt][1] += (sb + 1 == trow0 + 1) ? 0.f : f0.y;
                pacc[nt][2] += (sb     == trow1 + 1) ? 0.f : f1.x;
                pacc[nt][3] += (sb + 1 == trow1 + 1) ? 0.f : f1.y;
                pm0 = fmaxf(pm0, fmaxf(pacc[nt][0], pacc[nt][1]));
                pm1 = fmaxf(pm1, fmaxf(pacc[nt][2], pacc[nt][3]));
            }
        } else {
            #pragma unroll
            for (int nt = 0; nt < 8; nt++) {
                float2 f0 = __half22float2(bd0[4 * nt + cc]);
                float2 f1 = __half22float2(bd1[4 * nt + cc]);
                pacc[nt][0] += f0.x;
                pacc[nt][1] += f0.y;
                pacc[nt][2] += f1.x;
                pacc[nt][3] += f1.y;
                pm0 = fmaxf(pm0, fmaxf(pacc[nt][0], pacc[nt][1]));
                pm1 = fmaxf(pm1, fmaxf(pacc[nt][2], pacc[nt][3]));
            }
        }
        pm0 = fmaxf(pm0, __shfl_xor_sync(0xffffffffu, pm0, 1));
        pm0 = fmaxf(pm0, __shfl_xor_sync(0xffffffffu, pm0, 2));
        pm1 = fmaxf(pm1, __shfl_xor_sync(0xffffffffu, pm1, 1));
        pm1 = fmaxf(pm1, __shfl_xor_sync(0xffffffffu, pm1, 2));

        // Ps(it) fully consumed (shuffles converged the warp):
        // commit BD(it+1) NOW so it overlaps exp + PV + next AC.
        if (it < T_ / 64 - 1)
            PREFETCH_BD(s0 + 64);

        float mn0 = fmaxf(m0r, pm0), mn1 = fmaxf(m1r, pm1);
        // rescale only when a lane's running max changed (bit-identical skip)
        if (__ballot_sync(0xffffffffu, (pm0 > m0r) | (pm1 > m1r))) {
            float sf0 = ex2f(m0r - mn0), sf1 = ex2f(m1r - mn1);
            #pragma unroll
            for (int nt = 0; nt < 8; nt++) {
                oacc[nt][0] *= sf0; oacc[nt][1] *= sf0;
                oacc[nt][2] *= sf1; oacc[nt][3] *= sf1;
            }
            l0 *= sf0; l1 *= sf1;
        }
        m0r = mn0; m1r = mn1;

        unsigned ph[8][2];
        float sum0 = 0.f, sum1 = 0.f;
        #pragma unroll
        for (int nt = 0; nt < 8; nt++) {
            float e0 = ex2f(pacc[nt][0] - mn0);
            float e1 = ex2f(pacc[nt][1] - mn0);
            float e2 = ex2f(pacc[nt][2] - mn1);
            float e3 = ex2f(pacc[nt][3] - mn1);
            sum0 += e0 + e1; sum1 += e2 + e3;
            __half2 p0 = __floats2half2_rn(e0, e1);
            __half2 p1 = __floats2half2_rn(e2, e3);
            ph[nt][0] = *(unsigned*)&p0;
            ph[nt][1] = *(unsigned*)&p1;
        }
        sum0 += __shfl_xor_sync(0xffffffffu, sum0, 1);
        sum0 += __shfl_xor_sync(0xffffffffu, sum0, 2);
        sum1 += __shfl_xor_sync(0xffffffffu, sum1, 1);
        sum1 += __shfl_xor_sync(0xffffffffu, sum1, 2);
        l0 += sum0; l1 += sum1;

        #pragma unroll
        for (int kc = 0; kc < 4; kc++) {
            unsigned af[4] = { ph[2*kc][0], ph[2*kc][1], ph[2*kc+1][0], ph[2*kc+1][1] };
            #pragma unroll
            for (int nt = 0; nt < 8; nt++) {
                int drow = nt * 8 + r;
                uint2 vb2 = *(const uint2*)(Vb + drow * 40 + kc * 8 + 2 * cc);
                unsigned bf[2] = { vb2.x, vb2.y };
                MMA16(oacc[nt], af, bf);
            }
        }
        __syncwarp();
    }
    asm volatile("cp.async.wait_group 0;" ::: "memory");

    float il0 = 1.f / l0, il1 = 1.f / l1;
    unsigned* ctxu = (unsigned*)g_ctx;
    #pragma unroll
    for (int nt = 0; nt < 8; nt++) {
        int u_l = h * 32 + nt * 4 + cc;
        int pu = permu(u_l);
        __half2 o0 = __floats2half2_rn(oacc[nt][0] * il0, oacc[nt][1] * il0);
        ctxu[((size_t)trow0 * B_ + b) * (E_/2) + pu] = *(unsigned*)&o0;
        __half2 o1 = __floats2half2_rn(oacc[nt][2] * il1, oacc[nt][3] * il1);
        ctxu[((size_t)trow1 * B_ + b) * (E_/2) + pu] = *(unsigned*)&o1;
    }
#undef PREFETCH_KV
#undef PREFETCH_BD
}

// ============================================================
// out projection (fp16 GEMM, fp32 output, float2 stores)
// ============================================================
__global__ __launch_bounds__(256) void k_out(const float* __restrict__ bias,
                                             float* __restrict__ out) {
    extern __shared__ unsigned dsm[];
    float acc[4][4][4] = {};
    const int m0 = blockIdx.y * 128, n0 = blockIdx.x * 128;
    gemm_nt_hp<E_>(g_ctx, E_, g_cwout, E_, m0, n0, acc, dsm);
    const int lane = threadIdx.x & 31, warp = threadIdx.x >> 5;
    const int wm = (warp >> 2) * 64, wn = (warp & 3) * 32;
    #pragma unroll
    for (int mi = 0; mi < 4; mi++)
        #pragma unroll
        for (int ni = 0; ni < 4; ni++)
            #pragma unroll
            for (int rp = 0; rp < 2; rp++) {
                int row = EPI_ROW(m0, wm, mi, 2*rp);
                int col = EPI_COL(n0, wn, ni, 0);
                float2 v = { acc[mi][ni][2*rp]     + bias[col],
                             acc[mi][ni][2*rp + 1] + bias[col + 1] };
                *(float2*)(out + (size_t)row * E_ + col) = v;
            }
}

// ============================================================
extern "C" void kernel_launch(void* const* d_in, const int* in_sizes, int n_in,
                              void* d_out, int out_size) {
    const float* input = (const float*)d_in[0];
    const float* pos   = (const float*)d_in[1];
    const float* w_in  = (const float*)d_in[2];
    const float* w_out = (const float*)d_in[3];
    const float* w_pos = (const float*)d_in[4];
    const float* b_in  = (const float*)d_in[5];
    const float* b_out = (const float*)d_in[6];
    const float* b_pos = (const float*)d_in[7];
    const float* rwb   = (const float*)d_in[8];
    const float* rrb   = (const float*)d_in[9];
    float* out = (float*)d_out;

    const int gemm_smem  = 2 * 2 * 128 * 24 * 4;                 // 49152
    const int bd_smem    = 2 * 128 * 40 * 4 + 128 * 136 * 2;     // 75776
    const int flash_smem = (2 * (64*40 + 64*40) + 128*36) * 4;   // 59392
    cudaFuncSetAttribute(k_qkv,  cudaFuncAttributeMaxDynamicSharedMemorySize, gemm_smem);
    cudaFuncSetAttribute(k_pos,  cudaFuncAttributeMaxDynamicSharedMemorySize, gemm_smem);
    cudaFuncSetAttribute(k_bd,   cudaFuncAttributeMaxDynamicSharedMemorySize, bd_smem);
    cudaFuncSetAttribute(k_out,  cudaFuncAttributeMaxDynamicSharedMemorySize, gemm_smem);
    cudaFuncSetAttribute(k_flash, cudaFuncAttributeMaxDynamicSharedMemorySize, flash_smem);

    k_cvt_all<<<(N4_TOT + 255)/256, 256>>>(input, pos, w_in, w_out, w_pos);

    k_qkv  <<<dim3(E3_/128, (T_*B_)/128), 256, gemm_smem>>>(b_in);
    k_pos  <<<dim3(E_/128,  T_/128),      256, gemm_smem>>>(b_pos, rrb);
    k_bd   <<<dim3(T_/128, T_/128, B_*H_), 256, bd_smem>>>();
    k_flash<<<dim3(T_/128, B_*H_), 256, flash_smem>>>(rwb);
    k_out  <<<dim3(E_/128, (T_*B_)/128), 256, gemm_smem>>>(b_out, out);
}